// round 9
// baseline (speedup 1.0000x reference)
#include <cuda_runtime.h>
#include <math.h>
#include <stdint.h>

#define NB   4
#define TT   1024
#define HH   8
#define DD   64
#define DMOD 512
#define DFFV 1024
#define NLAY 6
#define ROWS (NB * TT)   // 4096
#define NH   (NB * HH)   // 32

#define QSCALE (0.125f * 1.4426950408889634f)

// ---------------- scratch (static device globals; no allocation) -------------
__device__ float g_h   [ROWS * DMOD];
__device__ float g_htf [ROWS * DMOD];           // tf32-rounded copy of g_h
__device__ float g_qkv [ROWS * 3 * DMOD];
__device__ float g_att [ROWS * DMOD];
__device__ float g_ff1 [ROWS * DFFV];           // tf32-rounded relu output
__device__ float g_ff2 [ROWS * DMOD];
__device__ float g_q   [NH * TT * DD];
__device__ float g_k   [NH * TT * DD];
__device__ float g_v   [NH * TT * DD];
// tf32-pre-rounded weights
__device__ float g_wqkv[NLAY * DMOD * 3 * DMOD];
__device__ float g_wff [NLAY * DMOD * DFFV];
__device__ float g_wo  [NLAY * DFFV * DMOD];

// ---------------- common PTX helpers -------------------------------------------
__device__ __forceinline__ uint32_t f2tf(float f)
{
    uint32_t r;
    asm("cvt.rna.tf32.f32 %0, %1;" : "=r"(r) : "f"(f));
    return r;
}
__device__ __forceinline__ float f2tff(float f) { return __uint_as_float(f2tf(f)); }
__device__ __forceinline__ void tfsplit(float x, uint32_t& big, uint32_t& small)
{
    big   = f2tf(x);
    small = f2tf(x - __uint_as_float(big));
}
__device__ __forceinline__ void mma_tf32(float* c, const uint32_t* a, uint32_t b0, uint32_t b1)
{
    asm volatile(
        "mma.sync.aligned.m16n8k8.row.col.f32.tf32.tf32.f32 "
        "{%0,%1,%2,%3}, {%4,%5,%6,%7}, {%8,%9}, {%0,%1,%2,%3};"
        : "+f"(c[0]), "+f"(c[1]), "+f"(c[2]), "+f"(c[3])
        : "r"(a[0]), "r"(a[1]), "r"(a[2]), "r"(a[3]), "r"(b0), "r"(b1));
}
__device__ __forceinline__ void cp_async16(uint32_t saddr, const void* gaddr)
{
    asm volatile("cp.async.cg.shared.global [%0], [%1], 16;" :: "r"(saddr), "l"(gaddr));
}
__device__ __forceinline__ void cp_commit() { asm volatile("cp.async.commit_group;"); }
template<int N> __device__ __forceinline__ void cp_wait() {
    asm volatile("cp.async.wait_group %0;" :: "n"(N));
}
__device__ __forceinline__ float ex2(float x)
{
    float r;
    asm("ex2.approx.ftz.f32 %0, %1;" : "=f"(r) : "f"(x));
    return r;
}

// ---------------- weight pre-rounding prepass ----------------------------------
__global__ __launch_bounds__(256)
void round_copy_kernel(const float* __restrict__ src, float* __restrict__ dst, int n4)
{
    int i = blockIdx.x * blockDim.x + threadIdx.x;
    for (; i < n4; i += gridDim.x * blockDim.x) {
        float4 v = ((const float4*)src)[i];
        v.x = f2tff(v.x); v.y = f2tff(v.y); v.z = f2tff(v.z); v.w = f2tff(v.w);
        ((float4*)dst)[i] = v;
    }
}

// ---------------- embedding + positional encoding (all-fp32, MUFU) -------------
__global__ void embed_kernel(const int* __restrict__ x, const float* __restrict__ emb)
{
    int row = blockIdx.x;
    int t   = row & (TT - 1);
    int tok = x[row];
    const float* e = emb + (size_t)tok * DMOD;
    float tf = (float)t;
    for (int i = threadIdx.x; i < DMOD; i += blockDim.x) {
        // angle_rate = 10000^(-2*floor(i/2)/512), fp32 (matches reference's f32 math)
        float expo = -2.0f * (float)(i >> 1) * (1.0f / (float)DMOD);
        float rate = powf(10000.0f, expo);
        float ang  = tf * rate;
        float s, c;
        sincosf(ang, &s, &c);
        float p   = (i & 1) ? c : s;
        float val = e[i] * 22.62741699796952f + p;  // sqrt(512)
        g_h  [(size_t)row * DMOD + i] = val;
        g_htf[(size_t)row * DMOD + i] = f2tff(val);
    }
}

// ---------------- TF32 GEMM — cvt-free, 3-stage cp.async pipeline --------------
#define LDA 20u
#define LDB 136u
#define STG 3

template<int MODE>
__global__ __launch_bounds__(256)
void gemm_tf32(const float* __restrict__ A, const float* __restrict__ B,
               const float* __restrict__ bias, float* __restrict__ C,
               int M, int N, int K)
{
    __shared__ float As[STG][128 * LDA];
    __shared__ float Bs[STG][16 * LDB];

    const int tid  = threadIdx.x;
    const int bm   = blockIdx.y * 128;
    const int bn   = blockIdx.x * 128;

    const int am = tid >> 1, ak = (tid & 1) * 8;
    const int bk = tid >> 4, bcol = (tid & 15) * 8;

    const uint32_t sA = (uint32_t)__cvta_generic_to_shared(&As[0][0]);
    const uint32_t sB = (uint32_t)__cvta_generic_to_shared(&Bs[0][0]);

    const int warp = tid >> 5, lane = tid & 31;
    const int gid  = lane >> 2, tig = lane & 3;
    const int wm   = (warp & 3) * 32;
    const int wn   = (warp >> 2) * 64;

    float c[2][8][4];
#pragma unroll
    for (int mt = 0; mt < 2; ++mt)
#pragma unroll
        for (int nt = 0; nt < 8; ++nt)
#pragma unroll
            for (int j = 0; j < 4; ++j) c[mt][nt][j] = 0.f;

    const int nIter = K >> 4;

    auto issue = [&](int t) {
        const int buf = t % STG;
        const float* Ap = A + (size_t)(bm + am) * K + t * 16 + ak;
        const float* Bp = B + (size_t)(t * 16 + bk) * N + bn + bcol;
        uint32_t sa = sA + (buf * 128 * LDA + am * LDA + ak) * 4;
        uint32_t sb = sB + (buf * 16 * LDB + bk * LDB + bcol) * 4;
        cp_async16(sa,      Ap);
        cp_async16(sa + 16, Ap + 4);
        cp_async16(sb,      Bp);
        cp_async16(sb + 16, Bp + 4);
        cp_commit();
    };

    issue(0);
    if (nIter > 1) issue(1);

    for (int it = 0; it < nIter; ++it) {
        if (it + 1 < nIter) cp_wait<1>(); else cp_wait<0>();
        __syncthreads();
        if (it + 2 < nIter) issue(it + 2);

        const float* Ac = As[it % STG];
        const float* Bc = Bs[it % STG];
#pragma unroll
        for (int ks = 0; ks < 2; ++ks) {
            const int kb = ks * 8;
            uint32_t a[2][4], b[8][2];
#pragma unroll
            for (int mt = 0; mt < 2; ++mt) {
                const int r = wm + mt * 16 + gid;
                a[mt][0] = __float_as_uint(Ac[(uint32_t)r * LDA + kb + tig]);
                a[mt][1] = __float_as_uint(Ac[(uint32_t)(r + 8) * LDA + kb + tig]);
                a[mt][2] = __float_as_uint(Ac[(uint32_t)r * LDA + kb + tig + 4]);
                a[mt][3] = __float_as_uint(Ac[(uint32_t)(r + 8) * LDA + kb + tig + 4]);
            }
#pragma unroll
            for (int nt = 0; nt < 8; ++nt) {
                const int col = wn + nt * 8 + gid;
                b[nt][0] = __float_as_uint(Bc[(uint32_t)(kb + tig) * LDB + col]);
                b[nt][1] = __float_as_uint(Bc[(uint32_t)(kb + tig + 4) * LDB + col]);
            }
#pragma unroll
            for (int mt = 0; mt < 2; ++mt)
#pragma unroll
                for (int nt = 0; nt < 8; ++nt)
                    mma_tf32(c[mt][nt], a[mt], b[nt][0], b[nt][1]);
        }
    }

#pragma unroll
    for (int mt = 0; mt < 2; ++mt) {
        const int row0 = bm + wm + mt * 16 + gid;
#pragma unroll
        for (int nt = 0; nt < 8; ++nt) {
            const int coln = bn + wn + nt * 8 + 2 * tig;
            const float2 bv = *(const float2*)(bias + coln);
            float2 v0, v1;
            v0.x = c[mt][nt][0] + bv.x; v0.y = c[mt][nt][1] + bv.y;
            v1.x = c[mt][nt][2] + bv.x; v1.y = c[mt][nt][3] + bv.y;
            if (MODE == 1) {
                v0.x = f2tff(fmaxf(v0.x, 0.f)); v0.y = f2tff(fmaxf(v0.y, 0.f));
                v1.x = f2tff(fmaxf(v1.x, 0.f)); v1.y = f2tff(fmaxf(v1.y, 0.f));
            }
            *(float2*)(C + (size_t)row0 * N + coln)       = v0;
            *(float2*)(C + (size_t)(row0 + 8) * N + coln) = v1;
        }
    }
}

// ---------------- split qkv into contiguous [nh][t][d] (fp32) ------------------
__global__ __launch_bounds__(384)
void split_qkv_kernel()
{
    int row = blockIdx.x;
    int n   = row >> 10;
    int t   = row & (TT - 1);
    int c0  = threadIdx.x * 4;
    float4 v = *(const float4*)(g_qkv + (size_t)row * 1536 + c0);
    float vals[4] = {v.x, v.y, v.z, v.w};
#pragma unroll
    for (int u = 0; u < 4; ++u) {
        int c = c0 + u;
        int h = c / 192;
        int r = c - h * 192;
        int d = r / 3;
        int j = r - d * 3;
        size_t dst = ((size_t)(n * HH + h) * TT + t) * DD + d;
        if (j == 0)      g_q[dst] = vals[u] * QSCALE;
        else if (j == 1) g_k[dst] = vals[u];
        else             g_v[dst] = vals[u];
    }
}

// ---------------- FlashAttention-2, compensated tf32, 32-key tiles (R7) --------
#define KT   32
#define LDK  68
#define LDV  72
#define LDP  36
#define OFF_K0 0
#define OFF_K1 (KT * LDK)
#define OFF_V0 (2 * KT * LDK)
#define OFF_V1 (OFF_V0 + KT * LDV)
#define OFF_P  (OFF_V0 + 2 * KT * LDV)
#define ATTN_SMEM_FLOATS (OFF_P + 4 * 16 * LDP)
#define ATTN_SMEM_BYTES  (ATTN_SMEM_FLOATS * 4)   // 45056

__global__ __launch_bounds__(128)
void attn_mma_kernel()
{
    extern __shared__ float sm[];

    const int tid  = threadIdx.x;
    const int warp = tid >> 5, lane = tid & 31;
    const int gid  = lane >> 2, tig = lane & 3;
    const int qt   = gridDim.x - 1 - blockIdx.x;
    const int nh   = blockIdx.y;
    const int row0 = qt * 64 + warp * 16;

    const float* kb = g_k + (size_t)nh * TT * DD;
    const float* vb = g_v + (size_t)nh * TT * DD;

    const uint32_t sbase = (uint32_t)__cvta_generic_to_shared(sm);

    uint32_t qfb[8][4], qfs[8][4];
    {
        const float* qp = g_q + ((size_t)nh * TT + row0) * DD;
#pragma unroll
        for (int kt = 0; kt < 8; ++kt) {
            tfsplit(qp[gid * DD + kt * 8 + tig],           qfb[kt][0], qfs[kt][0]);
            tfsplit(qp[(gid + 8) * DD + kt * 8 + tig],     qfb[kt][1], qfs[kt][1]);
            tfsplit(qp[gid * DD + kt * 8 + tig + 4],       qfb[kt][2], qfs[kt][2]);
            tfsplit(qp[(gid + 8) * DD + kt * 8 + tig + 4], qfb[kt][3], qfs[kt][3]);
        }
    }

    float o[8][4];
#pragma unroll
    for (int nt = 0; nt < 8; ++nt)
#pragma unroll
        for (int j = 0; j < 4; ++j) o[nt][j] = 0.f;
    float m0 = -INFINITY, m1 = -INFINITY, l0 = 0.f, l1 = 0.f;

    const int ntiles = 2 * qt + 2;

    auto prefetch = [&](int t) {
        const size_t gb = (size_t)t * KT * DD;
        const uint32_t kOff = (t & 1) ? OFF_K1 : OFF_K0;
        const uint32_t vOff = (t & 1) ? OFF_V1 : OFF_V0;
#pragma unroll
        for (int i = 0; i < 4; ++i) {
            int idx = i * 128 + tid;
            int r   = idx >> 4;
            int c4  = (idx & 15) * 4;
            cp_async16(sbase + (kOff + r * LDK + c4) * 4, kb + gb + r * DD + c4);
            cp_async16(sbase + (vOff + r * LDV + c4) * 4, vb + gb + r * DD + c4);
        }
        cp_commit();
    };

    prefetch(0);

    float* Pw = sm + OFF_P + warp * 16 * LDP;

#pragma unroll 1
    for (int kt_i = 0; kt_i < ntiles; ++kt_i) {
        cp_wait<0>();
        __syncthreads();
        if (kt_i + 1 < ntiles) prefetch(kt_i + 1);

        const float* Kt = sm + ((kt_i & 1) ? OFF_K1 : OFF_K0);
        const float* Vt = sm + ((kt_i & 1) ? OFF_V1 : OFF_V0);

        float cs[4][4];
#pragma unroll
        for (int nt = 0; nt < 4; ++nt) {
#pragma unroll
            for (int j = 0; j < 4; ++j) cs[nt][j] = 0.f;
#pragma unroll
            for (int dk = 0; dk < 8; ++dk) {
                uint32_t bb0, bs0, bb1, bs1;
                tfsplit(Kt[(nt * 8 + gid) * LDK + dk * 8 + tig],     bb0, bs0);
                tfsplit(Kt[(nt * 8 + gid) * LDK + dk * 8 + tig + 4], bb1, bs1);
                mma_tf32(cs[nt], qfb[dk], bb0, bb1);
                mma_tf32(cs[nt], qfb[dk], bs0, bs1);
                mma_tf32(cs[nt], qfs[dk], bb0, bb1);
            }
        }

        if (kt_i >= 2 * qt) {
            const int rl0 = row0 + gid;
            const int rl1 = rl0 + 8;
#pragma unroll
            for (int nt = 0; nt < 4; ++nt) {
                int j = kt_i * KT + nt * 8 + 2 * tig;
                if (j     > rl0) cs[nt][0] = -INFINITY;
                if (j + 1 > rl0) cs[nt][1] = -INFINITY;
                if (j     > rl1) cs[nt][2] = -INFINITY;
                if (j + 1 > rl1) cs[nt][3] = -INFINITY;
            }
        }

        float mx0 = -INFINITY, mx1 = -INFINITY;
#pragma unroll
        for (int nt = 0; nt < 4; ++nt) {
            mx0 = fmaxf(mx0, fmaxf(cs[nt][0], cs[nt][1]));
            mx1 = fmaxf(mx1, fmaxf(cs[nt][2], cs[nt][3]));
        }
        mx0 = fmaxf(mx0, __shfl_xor_sync(0xffffffffu, mx0, 1));
        mx0 = fmaxf(mx0, __shfl_xor_sync(0xffffffffu, mx0, 2));
        mx1 = fmaxf(mx1, __shfl_xor_sync(0xffffffffu, mx1, 1));
        mx1 = fmaxf(mx1, __shfl_xor_sync(0xffffffffu, mx1, 2));

        const float mn0 = fmaxf(m0, mx0);
        const float mn1 = fmaxf(m1, mx1);
        const float cor0 = ex2(m0 - mn0);
        const float cor1 = ex2(m1 - mn1);
        l0 *= cor0; l1 *= cor1;
#pragma unroll
        for (int nt = 0; nt < 8; ++nt) {
            o[nt][0] *= cor0; o[nt][1] *= cor0;
            o[nt][2] *= cor1; o[nt][3] *= cor1;
        }

        float rs0 = 0.f, rs1 = 0.f;
#pragma unroll
        for (int nt = 0; nt < 4; ++nt) {
            float p0 = ex2(cs[nt][0] - mn0);
            float p1 = ex2(cs[nt][1] - mn0);
            float p2 = ex2(cs[nt][2] - mn1);
            float p3 = ex2(cs[nt][3] - mn1);
            rs0 += p0 + p1; rs1 += p2 + p3;
            int col = nt * 8 + 2 * tig;
            *(float2*)(Pw + gid * LDP + col)       = make_float2(p0, p1);
            *(float2*)(Pw + (gid + 8) * LDP + col) = make_float2(p2, p3);
        }
        rs0 += __shfl_xor_sync(0xffffffffu, rs0, 1);
        rs0 += __shfl_xor_sync(0xffffffffu, rs0, 2);
        rs1 += __shfl_xor_sync(0xffffffffu, rs1, 1);
        rs1 += __shfl_xor_sync(0xffffffffu, rs1, 2);
        l0 += rs0; l1 += rs1;
        m0 = mn0; m1 = mn1;

        __syncwarp();

#pragma unroll
        for (int kk = 0; kk < 4; ++kk) {
            uint32_t ab[4], as_[4];
            tfsplit(Pw[gid * LDP + kk * 8 + tig],           ab[0], as_[0]);
            tfsplit(Pw[(gid + 8) * LDP + kk * 8 + tig],     ab[1], as_[1]);
            tfsplit(Pw[gid * LDP + kk * 8 + tig + 4],       ab[2], as_[2]);
            tfsplit(Pw[(gid + 8) * LDP + kk * 8 + tig + 4], ab[3], as_[3]);
#pragma unroll
            for (int nt = 0; nt < 8; ++nt) {
                uint32_t bb0, bs0, bb1, bs1;
                tfsplit(Vt[(kk * 8 + tig) * LDV + nt * 8 + gid],     bb0, bs0);
                tfsplit(Vt[(kk * 8 + tig + 4) * LDV + nt * 8 + gid], bb1, bs1);
                mma_tf32(o[nt], ab,  bb0, bb1);
                mma_tf32(o[nt], ab,  bs0, bs1);
                mma_tf32(o[nt], as_, bb0, bb1);
            }
        }
    }

    const float i0 = 1.f / l0;
    const float i1 = 1.f / l1;
    const int n = nh >> 3, hh = nh & 7;
    const int rg0 = row0 + gid;
#pragma unroll
    for (int nt = 0; nt < 8; ++nt) {
        int col = hh * DD + nt * 8 + 2 * tig;
        *(float2*)(g_att + (size_t)(n * TT + rg0) * DMOD + col) =
            make_float2(o[nt][0] * i0, o[nt][1] * i0);
        *(float2*)(g_att + (size_t)(n * TT + rg0 + 8) * DMOD + col) =
            make_float2(o[nt][2] * i1, o[nt][3] * i1);
    }
}

// ---------------- fused residual add + LayerNorm -------------------------------
template<bool WRITE_TF>
__global__ __launch_bounds__(256)
void add_ln_kernel(const float* __restrict__ a, const float* __restrict__ b,
                   const float* __restrict__ gamma, const float* __restrict__ beta,
                   float* __restrict__ out)
{
    int row = blockIdx.x;
    int tid = threadIdx.x;
    const float* ar = a + (size_t)row * DMOD;
    const float* br = b + (size_t)row * DMOD;

    float x0 = ar[tid]       + br[tid];
    float x1 = ar[tid + 256] + br[tid + 256];

    float sum = x0 + x1;
    float sq  = x0 * x0 + x1 * x1;
#pragma unroll
    for (int off = 16; off; off >>= 1) {
        sum += __shfl_xor_sync(0xffffffffu, sum, off);
        sq  += __shfl_xor_sync(0xffffffffu, sq,  off);
    }
    __shared__ float s1[8], s2[8];
    int wid = tid >> 5, lane = tid & 31;
    if (lane == 0) { s1[wid] = sum; s2[wid] = sq; }
    __syncthreads();
    float S = 0.f, Q = 0.f;
#pragma unroll
    for (int i = 0; i < 8; ++i) { S += s1[i]; Q += s2[i]; }

    float mean = S * (1.f / DMOD);
    float var  = Q * (1.f / DMOD) - mean * mean;
    float rstd = 1.f / sqrtf(var + 1e-3f);

    float y0 = gamma[tid]       * (x0 - mean) * rstd + beta[tid];
    float y1 = gamma[tid + 256] * (x1 - mean) * rstd + beta[tid + 256];
    out[(size_t)row * DMOD + tid]       = y0;
    out[(size_t)row * DMOD + tid + 256] = y1;
    if (WRITE_TF) {
        g_htf[(size_t)row * DMOD + tid]       = f2tff(y0);
        g_htf[(size_t)row * DMOD + tid + 256] = f2tff(y1);
    }
}

// ---------------- launch ------------------------------------------------------
extern "C" void kernel_launch(void* const* d_in, const int* in_sizes, int n_in,
                              void* d_out, int out_size)
{
    const int*   x     = (const int*)  d_in[0];
    const float* emb   = (const float*)d_in[1];
    const float* Wqkv  = (const float*)d_in[2];
    const float* bqkv  = (const float*)d_in[3];
    const float* Wff   = (const float*)d_in[4];
    const float* bff   = (const float*)d_in[5];
    const float* Wo    = (const float*)d_in[6];
    const float* bo    = (const float*)d_in[7];
    const float* g1    = (const float*)d_in[8];
    const float* beta1 = (const float*)d_in[9];
    const float* g2    = (const float*)d_in[10];
    const float* beta2 = (const float*)d_in[11];
    float* out = (float*)d_out;

    float *h, *qkv, *att, *ff1, *ff2, *htf, *wqkv, *wff, *wo;
    cudaGetSymbolAddress((void**)&h,    g_h);
    cudaGetSymbolAddress((void**)&htf,  g_htf);
    cudaGetSymbolAddress((void**)&qkv,  g_qkv);
    cudaGetSymbolAddress((void**)&att,  g_att);
    cudaGetSymbolAddress((void**)&ff1,  g_ff1);
    cudaGetSymbolAddress((void**)&ff2,  g_ff2);
    cudaGetSymbolAddress((void**)&wqkv, g_wqkv);
    cudaGetSymbolAddress((void**)&wff,  g_wff);
    cudaGetSymbolAddress((void**)&wo,   g_wo);

    cudaFuncSetAttribute(attn_mma_kernel,
                         cudaFuncAttributeMaxDynamicSharedMemorySize, ATTN_SMEM_BYTES);

    round_copy_kernel<<<592, 256>>>(Wqkv, wqkv, NLAY * DMOD * 3 * DMOD / 4);
    round_copy_kernel<<<592, 256>>>(Wff,  wff,  NLAY * DMOD * DFFV / 4);
    round_copy_kernel<<<592, 256>>>(Wo,   wo,   NLAY * DFFV * DMOD / 4);

    embed_kernel<<<ROWS, 128>>>(x, emb);

    for (int l = 0; l < NLAY; ++l) {
        gemm_tf32<0><<<dim3(1536 / 128, ROWS / 128), 256>>>(
            htf, wqkv + (size_t)l * DMOD * 3 * DMOD, bqkv + (size_t)l * 3 * DMOD,
            qkv, ROWS, 3 * DMOD, DMOD);

        split_qkv_kernel<<<ROWS, 384>>>();

        attn_mma_kernel<<<dim3(TT / 64, NH), 128, ATTN_SMEM_BYTES>>>();

        add_ln_kernel<true><<<ROWS, 256>>>(h, att,
            g1 + (size_t)l * DMOD, beta1 + (size_t)l * DMOD, h);

        gemm_tf32<1><<<dim3(DFFV / 128, ROWS / 128), 256>>>(
            htf, wff + (size_t)l * DMOD * DFFV, bff + (size_t)l * DFFV,
            ff1, ROWS, DFFV, DMOD);

        gemm_tf32<0><<<dim3(DMOD / 128, ROWS / 128), 256>>>(
            ff1, wo + (size_t)l * DFFV * DMOD, bo + (size_t)l * DMOD,
            ff2, ROWS, DMOD, DFFV);

        if (l == NLAY - 1)
            add_ln_kernel<false><<<ROWS, 256>>>(h, ff2,
                g2 + (size_t)l * DMOD, beta2 + (size_t)l * DMOD, out);
        else
            add_ln_kernel<true><<<ROWS, 256>>>(h, ff2,
                g2 + (size_t)l * DMOD, beta2 + (size_t)l * DMOD, h);
    }
}

// round 10
// speedup vs baseline: 1.4778x; 1.4778x over previous
#include <cuda_runtime.h>
#include <math.h>
#include <stdint.h>

#define NB   4
#define TT   1024
#define HH   8
#define DD   64
#define DMOD 512
#define DFFV 1024
#define NLAY 6
#define ROWS (NB * TT)   // 4096
#define NH   (NB * HH)   // 32

#define QSCALE (0.125f * 1.4426950408889634f)

// ---------------- scratch (static device globals; no allocation) -------------
__device__ float g_h   [ROWS * DMOD];
__device__ float g_htf [ROWS * DMOD];           // tf32-rounded copy of g_h
__device__ float g_qkv [ROWS * 3 * DMOD];
__device__ float g_att [ROWS * DMOD];
__device__ float g_ff1 [ROWS * DFFV];           // tf32-rounded relu output
__device__ float g_ff2 [ROWS * DMOD];
__device__ float g_q   [NH * TT * DD];
__device__ float g_k   [NH * TT * DD];
__device__ float g_v   [NH * TT * DD];
// tf32-pre-rounded weights
__device__ float g_wqkv[NLAY * DMOD * 3 * DMOD];
__device__ float g_wff [NLAY * DMOD * DFFV];
__device__ float g_wo  [NLAY * DFFV * DMOD];

// ---------------- common PTX helpers -------------------------------------------
__device__ __forceinline__ uint32_t f2tf(float f)
{
    uint32_t r;
    asm("cvt.rna.tf32.f32 %0, %1;" : "=r"(r) : "f"(f));
    return r;
}
__device__ __forceinline__ float f2tff(float f) { return __uint_as_float(f2tf(f)); }
__device__ __forceinline__ void tfsplit(float x, uint32_t& big, uint32_t& small)
{
    big   = f2tf(x);
    small = f2tf(x - __uint_as_float(big));
}
__device__ __forceinline__ void mma_tf32(float* c, const uint32_t* a, uint32_t b0, uint32_t b1)
{
    asm volatile(
        "mma.sync.aligned.m16n8k8.row.col.f32.tf32.tf32.f32 "
        "{%0,%1,%2,%3}, {%4,%5,%6,%7}, {%8,%9}, {%0,%1,%2,%3};"
        : "+f"(c[0]), "+f"(c[1]), "+f"(c[2]), "+f"(c[3])
        : "r"(a[0]), "r"(a[1]), "r"(a[2]), "r"(a[3]), "r"(b0), "r"(b1));
}
__device__ __forceinline__ void cp_async16(uint32_t saddr, const void* gaddr)
{
    asm volatile("cp.async.cg.shared.global [%0], [%1], 16;" :: "r"(saddr), "l"(gaddr));
}
__device__ __forceinline__ void cp_commit() { asm volatile("cp.async.commit_group;"); }
template<int N> __device__ __forceinline__ void cp_wait() {
    asm volatile("cp.async.wait_group %0;" :: "n"(N));
}
__device__ __forceinline__ float ex2(float x)
{
    float r;
    asm("ex2.approx.ftz.f32 %0, %1;" : "=f"(r) : "f"(x));
    return r;
}

// ---------------- weight pre-rounding prepass ----------------------------------
__global__ __launch_bounds__(256)
void round_copy_kernel(const float* __restrict__ src, float* __restrict__ dst, int n4)
{
    int i = blockIdx.x * blockDim.x + threadIdx.x;
    for (; i < n4; i += gridDim.x * blockDim.x) {
        float4 v = ((const float4*)src)[i];
        v.x = f2tff(v.x); v.y = f2tff(v.y); v.z = f2tff(v.z); v.w = f2tff(v.w);
        ((float4*)dst)[i] = v;
    }
}

// ---------------- embedding + positional encoding (all-fp32, MUFU) -------------
__global__ void embed_kernel(const int* __restrict__ x, const float* __restrict__ emb)
{
    int row = blockIdx.x;
    int t   = row & (TT - 1);
    int tok = x[row];
    const float* e = emb + (size_t)tok * DMOD;
    float tf = (float)t;
    for (int i = threadIdx.x; i < DMOD; i += blockDim.x) {
        float expo = -2.0f * (float)(i >> 1) * (1.0f / (float)DMOD);
        float rate = powf(10000.0f, expo);
        float ang  = tf * rate;
        float s, c;
        sincosf(ang, &s, &c);
        float p   = (i & 1) ? c : s;
        float val = e[i] * 22.62741699796952f + p;  // sqrt(512)
        g_h  [(size_t)row * DMOD + i] = val;
        g_htf[(size_t)row * DMOD + i] = f2tff(val);
    }
}

// ---------------- TF32 GEMM — cvt-free, 3-stage cp.async pipeline --------------
#define LDA 20u
#define LDB 136u
#define STG 3

template<int MODE>
__global__ __launch_bounds__(256)
void gemm_tf32(const float* __restrict__ A, const float* __restrict__ B,
               const float* __restrict__ bias, float* __restrict__ C,
               int M, int N, int K)
{
    __shared__ float As[STG][128 * LDA];
    __shared__ float Bs[STG][16 * LDB];

    const int tid  = threadIdx.x;
    const int bm   = blockIdx.y * 128;
    const int bn   = blockIdx.x * 128;

    const int am = tid >> 1, ak = (tid & 1) * 8;
    const int bk = tid >> 4, bcol = (tid & 15) * 8;

    const uint32_t sA = (uint32_t)__cvta_generic_to_shared(&As[0][0]);
    const uint32_t sB = (uint32_t)__cvta_generic_to_shared(&Bs[0][0]);

    const int warp = tid >> 5, lane = tid & 31;
    const int gid  = lane >> 2, tig = lane & 3;
    const int wm   = (warp & 3) * 32;
    const int wn   = (warp >> 2) * 64;

    float c[2][8][4];
#pragma unroll
    for (int mt = 0; mt < 2; ++mt)
#pragma unroll
        for (int nt = 0; nt < 8; ++nt)
#pragma unroll
            for (int j = 0; j < 4; ++j) c[mt][nt][j] = 0.f;

    const int nIter = K >> 4;

    auto issue = [&](int t) {
        const int buf = t % STG;
        const float* Ap = A + (size_t)(bm + am) * K + t * 16 + ak;
        const float* Bp = B + (size_t)(t * 16 + bk) * N + bn + bcol;
        uint32_t sa = sA + (buf * 128 * LDA + am * LDA + ak) * 4;
        uint32_t sb = sB + (buf * 16 * LDB + bk * LDB + bcol) * 4;
        cp_async16(sa,      Ap);
        cp_async16(sa + 16, Ap + 4);
        cp_async16(sb,      Bp);
        cp_async16(sb + 16, Bp + 4);
        cp_commit();
    };

    issue(0);
    if (nIter > 1) issue(1);

    for (int it = 0; it < nIter; ++it) {
        if (it + 1 < nIter) cp_wait<1>(); else cp_wait<0>();
        __syncthreads();
        if (it + 2 < nIter) issue(it + 2);

        const float* Ac = As[it % STG];
        const float* Bc = Bs[it % STG];
#pragma unroll
        for (int ks = 0; ks < 2; ++ks) {
            const int kb = ks * 8;
            uint32_t a[2][4], b[8][2];
#pragma unroll
            for (int mt = 0; mt < 2; ++mt) {
                const int r = wm + mt * 16 + gid;
                a[mt][0] = __float_as_uint(Ac[(uint32_t)r * LDA + kb + tig]);
                a[mt][1] = __float_as_uint(Ac[(uint32_t)(r + 8) * LDA + kb + tig]);
                a[mt][2] = __float_as_uint(Ac[(uint32_t)r * LDA + kb + tig + 4]);
                a[mt][3] = __float_as_uint(Ac[(uint32_t)(r + 8) * LDA + kb + tig + 4]);
            }
#pragma unroll
            for (int nt = 0; nt < 8; ++nt) {
                const int col = wn + nt * 8 + gid;
                b[nt][0] = __float_as_uint(Bc[(uint32_t)(kb + tig) * LDB + col]);
                b[nt][1] = __float_as_uint(Bc[(uint32_t)(kb + tig + 4) * LDB + col]);
            }
#pragma unroll
            for (int mt = 0; mt < 2; ++mt)
#pragma unroll
                for (int nt = 0; nt < 8; ++nt)
                    mma_tf32(c[mt][nt], a[mt], b[nt][0], b[nt][1]);
        }
    }

#pragma unroll
    for (int mt = 0; mt < 2; ++mt) {
        const int row0 = bm + wm + mt * 16 + gid;
#pragma unroll
        for (int nt = 0; nt < 8; ++nt) {
            const int coln = bn + wn + nt * 8 + 2 * tig;
            const float2 bv = *(const float2*)(bias + coln);
            float2 v0, v1;
            v0.x = c[mt][nt][0] + bv.x; v0.y = c[mt][nt][1] + bv.y;
            v1.x = c[mt][nt][2] + bv.x; v1.y = c[mt][nt][3] + bv.y;
            if (MODE == 1) {
                v0.x = f2tff(fmaxf(v0.x, 0.f)); v0.y = f2tff(fmaxf(v0.y, 0.f));
                v1.x = f2tff(fmaxf(v1.x, 0.f)); v1.y = f2tff(fmaxf(v1.y, 0.f));
            }
            *(float2*)(C + (size_t)row0 * N + coln)       = v0;
            *(float2*)(C + (size_t)(row0 + 8) * N + coln) = v1;
        }
    }
}

// ---------------- split qkv into contiguous [nh][t][d] (fp32) ------------------
__global__ __launch_bounds__(384)
void split_qkv_kernel()
{
    int row = blockIdx.x;
    int n   = row >> 10;
    int t   = row & (TT - 1);
    int c0  = threadIdx.x * 4;
    float4 v = *(const float4*)(g_qkv + (size_t)row * 1536 + c0);
    float vals[4] = {v.x, v.y, v.z, v.w};
#pragma unroll
    for (int u = 0; u < 4; ++u) {
        int c = c0 + u;
        int h = c / 192;
        int r = c - h * 192;
        int d = r / 3;
        int j = r - d * 3;
        size_t dst = ((size_t)(n * HH + h) * TT + t) * DD + d;
        if (j == 0)      g_q[dst] = vals[u] * QSCALE;
        else if (j == 1) g_k[dst] = vals[u];
        else             g_v[dst] = vals[u];
    }
}

// ---------------- FlashAttention-2, compensated tf32, 32-key tiles --------------
// V is split (big/small) cooperatively once per tile into shared Vb/Vs.
#define KT   32
#define LDK  68
#define LDV  72
#define LDP  36
#define OFF_K0 0
#define OFF_K1 (KT * LDK)
#define OFF_V0 (2 * KT * LDK)
#define OFF_V1 (OFF_V0 + KT * LDV)
#define OFF_P  (OFF_V0 + 2 * KT * LDV)
#define OFF_VB (OFF_P + 4 * 16 * LDP)            // 11264
#define OFF_VS (OFF_VB + KT * LDV)               // 13568
#define ATTN_SMEM_FLOATS (OFF_VS + KT * LDV)     // 15872
#define ATTN_SMEM_BYTES  (ATTN_SMEM_FLOATS * 4)  // 63488

__global__ __launch_bounds__(128)
void attn_mma_kernel()
{
    extern __shared__ float sm[];

    const int tid  = threadIdx.x;
    const int warp = tid >> 5, lane = tid & 31;
    const int gid  = lane >> 2, tig = lane & 3;
    const int qt   = gridDim.x - 1 - blockIdx.x;
    const int nh   = blockIdx.y;
    const int row0 = qt * 64 + warp * 16;

    const float* kb = g_k + (size_t)nh * TT * DD;
    const float* vb = g_v + (size_t)nh * TT * DD;

    const uint32_t sbase = (uint32_t)__cvta_generic_to_shared(sm);

    uint32_t qfb[8][4], qfs[8][4];
    {
        const float* qp = g_q + ((size_t)nh * TT + row0) * DD;
#pragma unroll
        for (int kt = 0; kt < 8; ++kt) {
            tfsplit(qp[gid * DD + kt * 8 + tig],           qfb[kt][0], qfs[kt][0]);
            tfsplit(qp[(gid + 8) * DD + kt * 8 + tig],     qfb[kt][1], qfs[kt][1]);
            tfsplit(qp[gid * DD + kt * 8 + tig + 4],       qfb[kt][2], qfs[kt][2]);
            tfsplit(qp[(gid + 8) * DD + kt * 8 + tig + 4], qfb[kt][3], qfs[kt][3]);
        }
    }

    float o[8][4];
#pragma unroll
    for (int nt = 0; nt < 8; ++nt)
#pragma unroll
        for (int j = 0; j < 4; ++j) o[nt][j] = 0.f;
    float m0 = -INFINITY, m1 = -INFINITY, l0 = 0.f, l1 = 0.f;

    const int ntiles = 2 * qt + 2;

    auto prefetch = [&](int t) {
        const size_t gb = (size_t)t * KT * DD;
        const uint32_t kOff = (t & 1) ? OFF_K1 : OFF_K0;
        const uint32_t vOff = (t & 1) ? OFF_V1 : OFF_V0;
#pragma unroll
        for (int i = 0; i < 4; ++i) {
            int idx = i * 128 + tid;
            int r   = idx >> 4;
            int c4  = (idx & 15) * 4;
            cp_async16(sbase + (kOff + r * LDK + c4) * 4, kb + gb + r * DD + c4);
            cp_async16(sbase + (vOff + r * LDV + c4) * 4, vb + gb + r * DD + c4);
        }
        cp_commit();
    };

    prefetch(0);

    float* Pw = sm + OFF_P + warp * 16 * LDP;
    float* Vb = sm + OFF_VB;
    float* Vs = sm + OFF_VS;

#pragma unroll 1
    for (int kt_i = 0; kt_i < ntiles; ++kt_i) {
        cp_wait<0>();
        __syncthreads();       // tile resident AND previous Vb/Vs consumers done
        if (kt_i + 1 < ntiles) prefetch(kt_i + 1);

        const float* Kt = sm + ((kt_i & 1) ? OFF_K1 : OFF_K0);
        const float* Vt = sm + ((kt_i & 1) ? OFF_V1 : OFF_V0);

        // ---- cooperative V split: 2048 elements, 16 per thread, once per tile ----
#pragma unroll
        for (int i = 0; i < 16; ++i) {
            int idx = i * 128 + tid;
            int r   = idx >> 6, cc = idx & 63;
            uint32_t b, s;
            tfsplit(Vt[r * LDV + cc], b, s);
            Vb[r * LDV + cc] = __uint_as_float(b);
            Vs[r * LDV + cc] = __uint_as_float(s);
        }
        __syncthreads();       // Vb/Vs ready for all warps

        // ---- S = Q @ K^T (16x32 per warp), compensated ----
        float cs[4][4];
#pragma unroll
        for (int nt = 0; nt < 4; ++nt) {
#pragma unroll
            for (int j = 0; j < 4; ++j) cs[nt][j] = 0.f;
#pragma unroll
            for (int dk = 0; dk < 8; ++dk) {
                uint32_t bb0, bs0, bb1, bs1;
                tfsplit(Kt[(nt * 8 + gid) * LDK + dk * 8 + tig],     bb0, bs0);
                tfsplit(Kt[(nt * 8 + gid) * LDK + dk * 8 + tig + 4], bb1, bs1);
                mma_tf32(cs[nt], qfb[dk], bb0, bb1);
                mma_tf32(cs[nt], qfb[dk], bs0, bs1);
                mma_tf32(cs[nt], qfs[dk], bb0, bb1);
            }
        }

        if (kt_i >= 2 * qt) {
            const int rl0 = row0 + gid;
            const int rl1 = rl0 + 8;
#pragma unroll
            for (int nt = 0; nt < 4; ++nt) {
                int j = kt_i * KT + nt * 8 + 2 * tig;
                if (j     > rl0) cs[nt][0] = -INFINITY;
                if (j + 1 > rl0) cs[nt][1] = -INFINITY;
                if (j     > rl1) cs[nt][2] = -INFINITY;
                if (j + 1 > rl1) cs[nt][3] = -INFINITY;
            }
        }

        float mx0 = -INFINITY, mx1 = -INFINITY;
#pragma unroll
        for (int nt = 0; nt < 4; ++nt) {
            mx0 = fmaxf(mx0, fmaxf(cs[nt][0], cs[nt][1]));
            mx1 = fmaxf(mx1, fmaxf(cs[nt][2], cs[nt][3]));
        }
        mx0 = fmaxf(mx0, __shfl_xor_sync(0xffffffffu, mx0, 1));
        mx0 = fmaxf(mx0, __shfl_xor_sync(0xffffffffu, mx0, 2));
        mx1 = fmaxf(mx1, __shfl_xor_sync(0xffffffffu, mx1, 1));
        mx1 = fmaxf(mx1, __shfl_xor_sync(0xffffffffu, mx1, 2));

        const float mn0 = fmaxf(m0, mx0);
        const float mn1 = fmaxf(m1, mx1);
        const float cor0 = ex2(m0 - mn0);
        const float cor1 = ex2(m1 - mn1);
        l0 *= cor0; l1 *= cor1;
#pragma unroll
        for (int nt = 0; nt < 8; ++nt) {
            o[nt][0] *= cor0; o[nt][1] *= cor0;
            o[nt][2] *= cor1; o[nt][3] *= cor1;
        }

        float rs0 = 0.f, rs1 = 0.f;
#pragma unroll
        for (int nt = 0; nt < 4; ++nt) {
            float p0 = ex2(cs[nt][0] - mn0);
            float p1 = ex2(cs[nt][1] - mn0);
            float p2 = ex2(cs[nt][2] - mn1);
            float p3 = ex2(cs[nt][3] - mn1);
            rs0 += p0 + p1; rs1 += p2 + p3;
            int col = nt * 8 + 2 * tig;
            *(float2*)(Pw + gid * LDP + col)       = make_float2(p0, p1);
            *(float2*)(Pw + (gid + 8) * LDP + col) = make_float2(p2, p3);
        }
        rs0 += __shfl_xor_sync(0xffffffffu, rs0, 1);
        rs0 += __shfl_xor_sync(0xffffffffu, rs0, 2);
        rs1 += __shfl_xor_sync(0xffffffffu, rs1, 1);
        rs1 += __shfl_xor_sync(0xffffffffu, rs1, 2);
        l0 += rs0; l1 += rs1;
        m0 = mn0; m1 = mn1;

        __syncwarp();

        // ---- O += P @ V (pre-split V: pure LDS + mma) ----
#pragma unroll
        for (int kk = 0; kk < 4; ++kk) {
            uint32_t ab[4], as_[4];
            tfsplit(Pw[gid * LDP + kk * 8 + tig],           ab[0], as_[0]);
            tfsplit(Pw[(gid + 8) * LDP + kk * 8 + tig],     ab[1], as_[1]);
            tfsplit(Pw[gid * LDP + kk * 8 + tig + 4],       ab[2], as_[2]);
            tfsplit(Pw[(gid + 8) * LDP + kk * 8 + tig + 4], ab[3], as_[3]);
#pragma unroll
            for (int nt = 0; nt < 8; ++nt) {
                const int r0 = (kk * 8 + tig) * LDV + nt * 8 + gid;
                const int r1 = (kk * 8 + tig + 4) * LDV + nt * 8 + gid;
                uint32_t bb0 = __float_as_uint(Vb[r0]);
                uint32_t bb1 = __float_as_uint(Vb[r1]);
                uint32_t bs0 = __float_as_uint(Vs[r0]);
                uint32_t bs1 = __float_as_uint(Vs[r1]);
                mma_tf32(o[nt], ab,  bb0, bb1);
                mma_tf32(o[nt], ab,  bs0, bs1);
                mma_tf32(o[nt], as_, bb0, bb1);
            }
        }
    }

    const float i0 = 1.f / l0;
    const float i1 = 1.f / l1;
    const int n = nh >> 3, hh = nh & 7;
    const int rg0 = row0 + gid;
#pragma unroll
    for (int nt = 0; nt < 8; ++nt) {
        int col = hh * DD + nt * 8 + 2 * tig;
        *(float2*)(g_att + (size_t)(n * TT + rg0) * DMOD + col) =
            make_float2(o[nt][0] * i0, o[nt][1] * i0);
        *(float2*)(g_att + (size_t)(n * TT + rg0 + 8) * DMOD + col) =
            make_float2(o[nt][2] * i1, o[nt][3] * i1);
    }
}

// ---------------- fused residual add + LayerNorm -------------------------------
template<bool WRITE_TF>
__global__ __launch_bounds__(256)
void add_ln_kernel(const float* __restrict__ a, const float* __restrict__ b,
                   const float* __restrict__ gamma, const float* __restrict__ beta,
                   float* __restrict__ out)
{
    int row = blockIdx.x;
    int tid = threadIdx.x;
    const float* ar = a + (size_t)row * DMOD;
    const float* br = b + (size_t)row * DMOD;

    float x0 = ar[tid]       + br[tid];
    float x1 = ar[tid + 256] + br[tid + 256];

    float sum = x0 + x1;
    float sq  = x0 * x0 + x1 * x1;
#pragma unroll
    for (int off = 16; off; off >>= 1) {
        sum += __shfl_xor_sync(0xffffffffu, sum, off);
        sq  += __shfl_xor_sync(0xffffffffu, sq,  off);
    }
    __shared__ float s1[8], s2[8];
    int wid = tid >> 5, lane = tid & 31;
    if (lane == 0) { s1[wid] = sum; s2[wid] = sq; }
    __syncthreads();
    float S = 0.f, Q = 0.f;
#pragma unroll
    for (int i = 0; i < 8; ++i) { S += s1[i]; Q += s2[i]; }

    float mean = S * (1.f / DMOD);
    float var  = Q * (1.f / DMOD) - mean * mean;
    float rstd = 1.f / sqrtf(var + 1e-3f);

    float y0 = gamma[tid]       * (x0 - mean) * rstd + beta[tid];
    float y1 = gamma[tid + 256] * (x1 - mean) * rstd + beta[tid + 256];
    out[(size_t)row * DMOD + tid]       = y0;
    out[(size_t)row * DMOD + tid + 256] = y1;
    if (WRITE_TF) {
        g_htf[(size_t)row * DMOD + tid]       = f2tff(y0);
        g_htf[(size_t)row * DMOD + tid + 256] = f2tff(y1);
    }
}

// ---------------- launch ------------------------------------------------------
extern "C" void kernel_launch(void* const* d_in, const int* in_sizes, int n_in,
                              void* d_out, int out_size)
{
    const int*   x     = (const int*)  d_in[0];
    const float* emb   = (const float*)d_in[1];
    const float* Wqkv  = (const float*)d_in[2];
    const float* bqkv  = (const float*)d_in[3];
    const float* Wff   = (const float*)d_in[4];
    const float* bff   = (const float*)d_in[5];
    const float* Wo    = (const float*)d_in[6];
    const float* bo    = (const float*)d_in[7];
    const float* g1    = (const float*)d_in[8];
    const float* beta1 = (const float*)d_in[9];
    const float* g2    = (const float*)d_in[10];
    const float* beta2 = (const float*)d_in[11];
    float* out = (float*)d_out;

    float *h, *qkv, *att, *ff1, *ff2, *htf, *wqkv, *wff, *wo;
    cudaGetSymbolAddress((void**)&h,    g_h);
    cudaGetSymbolAddress((void**)&htf,  g_htf);
    cudaGetSymbolAddress((void**)&qkv,  g_qkv);
    cudaGetSymbolAddress((void**)&att,  g_att);
    cudaGetSymbolAddress((void**)&ff1,  g_ff1);
    cudaGetSymbolAddress((void**)&ff2,  g_ff2);
    cudaGetSymbolAddress((void**)&wqkv, g_wqkv);
    cudaGetSymbolAddress((void**)&wff,  g_wff);
    cudaGetSymbolAddress((void**)&wo,   g_wo);

    cudaFuncSetAttribute(attn_mma_kernel,
                         cudaFuncAttributeMaxDynamicSharedMemorySize, ATTN_SMEM_BYTES);

    round_copy_kernel<<<592, 256>>>(Wqkv, wqkv, NLAY * DMOD * 3 * DMOD / 4);
    round_copy_kernel<<<592, 256>>>(Wff,  wff,  NLAY * DMOD * DFFV / 4);
    round_copy_kernel<<<592, 256>>>(Wo,   wo,   NLAY * DFFV * DMOD / 4);

    embed_kernel<<<ROWS, 128>>>(x, emb);

    for (int l = 0; l < NLAY; ++l) {
        gemm_tf32<0><<<dim3(1536 / 128, ROWS / 128), 256>>>(
            htf, wqkv + (size_t)l * DMOD * 3 * DMOD, bqkv + (size_t)l * 3 * DMOD,
            qkv, ROWS, 3 * DMOD, DMOD);

        split_qkv_kernel<<<ROWS, 384>>>();

        attn_mma_kernel<<<dim3(TT / 64, NH), 128, ATTN_SMEM_BYTES>>>();

        add_ln_kernel<true><<<ROWS, 256>>>(h, att,
            g1 + (size_t)l * DMOD, beta1 + (size_t)l * DMOD, h);

        gemm_tf32<1><<<dim3(DFFV / 128, ROWS / 128), 256>>>(
            htf, wff + (size_t)l * DMOD * DFFV, bff + (size_t)l * DFFV,
            ff1, ROWS, DFFV, DMOD);

        gemm_tf32<0><<<dim3(DMOD / 128, ROWS / 128), 256>>>(
            ff1, wo + (size_t)l * DFFV * DMOD, bo + (size_t)l * DMOD,
            ff2, ROWS, DMOD, DFFV);

        if (l == NLAY - 1)
            add_ln_kernel<false><<<ROWS, 256>>>(h, ff2,
                g2 + (size_t)l * DMOD, beta2 + (size_t)l * DMOD, out);
        else
            add_ln_kernel<true><<<ROWS, 256>>>(h, ff2,
                g2 + (size_t)l * DMOD, beta2 + (size_t)l * DMOD, h);
    }
}

// round 11
// speedup vs baseline: 1.5794x; 1.0687x over previous
#include <cuda_runtime.h>
#include <math.h>
#include <stdint.h>

#define NB   4
#define TT   1024
#define HH   8
#define DD   64
#define DMOD 512
#define DFFV 1024
#define NLAY 6
#define ROWS (NB * TT)   // 4096
#define NH   (NB * HH)   // 32

#define QSCALE (0.125f * 1.4426950408889634f)

// ---------------- scratch (static device globals; no allocation) -------------
__device__ float g_h   [ROWS * DMOD];
__device__ float g_htf [ROWS * DMOD];
__device__ float g_qkv [ROWS * 3 * DMOD];
__device__ float g_att [ROWS * DMOD];
__device__ float g_ff1 [ROWS * DFFV];
__device__ float g_ff2 [ROWS * DMOD];
__device__ float g_q   [NH * TT * DD];
__device__ float g_kb  [NH * TT * DD];   // tf32 big part of K
__device__ float g_ks  [NH * TT * DD];   // tf32 small part of K
__device__ float g_vb  [NH * TT * DD];   // tf32 big part of V
__device__ float g_vs  [NH * TT * DD];   // tf32 small part of V
// tf32-pre-rounded weights
__device__ float g_wqkv[NLAY * DMOD * 3 * DMOD];
__device__ float g_wff [NLAY * DMOD * DFFV];
__device__ float g_wo  [NLAY * DFFV * DMOD];

// ---------------- common PTX helpers -------------------------------------------
__device__ __forceinline__ uint32_t f2tf(float f)
{
    uint32_t r;
    asm("cvt.rna.tf32.f32 %0, %1;" : "=r"(r) : "f"(f));
    return r;
}
__device__ __forceinline__ float f2tff(float f) { return __uint_as_float(f2tf(f)); }
__device__ __forceinline__ void tfsplit(float x, uint32_t& big, uint32_t& small)
{
    big   = f2tf(x);
    small = f2tf(x - __uint_as_float(big));
}
__device__ __forceinline__ void mma_tf32(float* c, const uint32_t* a, uint32_t b0, uint32_t b1)
{
    asm volatile(
        "mma.sync.aligned.m16n8k8.row.col.f32.tf32.tf32.f32 "
        "{%0,%1,%2,%3}, {%4,%5,%6,%7}, {%8,%9}, {%0,%1,%2,%3};"
        : "+f"(c[0]), "+f"(c[1]), "+f"(c[2]), "+f"(c[3])
        : "r"(a[0]), "r"(a[1]), "r"(a[2]), "r"(a[3]), "r"(b0), "r"(b1));
}
__device__ __forceinline__ void cp_async16(uint32_t saddr, const void* gaddr)
{
    asm volatile("cp.async.cg.shared.global [%0], [%1], 16;" :: "r"(saddr), "l"(gaddr));
}
__device__ __forceinline__ void cp_commit() { asm volatile("cp.async.commit_group;"); }
template<int N> __device__ __forceinline__ void cp_wait() {
    asm volatile("cp.async.wait_group %0;" :: "n"(N));
}
__device__ __forceinline__ float ex2(float x)
{
    float r;
    asm("ex2.approx.ftz.f32 %0, %1;" : "=f"(r) : "f"(x));
    return r;
}

// ---------------- weight pre-rounding prepass ----------------------------------
__global__ __launch_bounds__(256)
void round_copy_kernel(const float* __restrict__ src, float* __restrict__ dst, int n4)
{
    int i = blockIdx.x * blockDim.x + threadIdx.x;
    for (; i < n4; i += gridDim.x * blockDim.x) {
        float4 v = ((const float4*)src)[i];
        v.x = f2tff(v.x); v.y = f2tff(v.y); v.z = f2tff(v.z); v.w = f2tff(v.w);
        ((float4*)dst)[i] = v;
    }
}

// ---------------- embedding + positional encoding (all-fp32, MUFU) -------------
__global__ void embed_kernel(const int* __restrict__ x, const float* __restrict__ emb)
{
    int row = blockIdx.x;
    int t   = row & (TT - 1);
    int tok = x[row];
    const float* e = emb + (size_t)tok * DMOD;
    float tf = (float)t;
    for (int i = threadIdx.x; i < DMOD; i += blockDim.x) {
        float expo = -2.0f * (float)(i >> 1) * (1.0f / (float)DMOD);
        float rate = powf(10000.0f, expo);
        float ang  = tf * rate;
        float s, c;
        sincosf(ang, &s, &c);
        float p   = (i & 1) ? c : s;
        float val = e[i] * 22.62741699796952f + p;  // sqrt(512)
        g_h  [(size_t)row * DMOD + i] = val;
        g_htf[(size_t)row * DMOD + i] = f2tff(val);
    }
}

// ---------------- TF32 GEMM — cvt-free, 3-stage cp.async pipeline --------------
#define LDA 20u
#define LDB 136u
#define STG 3

template<int MODE>
__global__ __launch_bounds__(256)
void gemm_tf32(const float* __restrict__ A, const float* __restrict__ B,
               const float* __restrict__ bias, float* __restrict__ C,
               int M, int N, int K)
{
    __shared__ float As[STG][128 * LDA];
    __shared__ float Bs[STG][16 * LDB];

    const int tid  = threadIdx.x;
    const int bm   = blockIdx.y * 128;
    const int bn   = blockIdx.x * 128;

    const int am = tid >> 1, ak = (tid & 1) * 8;
    const int bk = tid >> 4, bcol = (tid & 15) * 8;

    const uint32_t sA = (uint32_t)__cvta_generic_to_shared(&As[0][0]);
    const uint32_t sB = (uint32_t)__cvta_generic_to_shared(&Bs[0][0]);

    const int warp = tid >> 5, lane = tid & 31;
    const int gid  = lane >> 2, tig = lane & 3;
    const int wm   = (warp & 3) * 32;
    const int wn   = (warp >> 2) * 64;

    float c[2][8][4];
#pragma unroll
    for (int mt = 0; mt < 2; ++mt)
#pragma unroll
        for (int nt = 0; nt < 8; ++nt)
#pragma unroll
            for (int j = 0; j < 4; ++j) c[mt][nt][j] = 0.f;

    const int nIter = K >> 4;

    auto issue = [&](int t) {
        const int buf = t % STG;
        const float* Ap = A + (size_t)(bm + am) * K + t * 16 + ak;
        const float* Bp = B + (size_t)(t * 16 + bk) * N + bn + bcol;
        uint32_t sa = sA + (buf * 128 * LDA + am * LDA + ak) * 4;
        uint32_t sb = sB + (buf * 16 * LDB + bk * LDB + bcol) * 4;
        cp_async16(sa,      Ap);
        cp_async16(sa + 16, Ap + 4);
        cp_async16(sb,      Bp);
        cp_async16(sb + 16, Bp + 4);
        cp_commit();
    };

    issue(0);
    if (nIter > 1) issue(1);

    for (int it = 0; it < nIter; ++it) {
        if (it + 1 < nIter) cp_wait<1>(); else cp_wait<0>();
        __syncthreads();
        if (it + 2 < nIter) issue(it + 2);

        const float* Ac = As[it % STG];
        const float* Bc = Bs[it % STG];
#pragma unroll
        for (int ks = 0; ks < 2; ++ks) {
            const int kb = ks * 8;
            uint32_t a[2][4], b[8][2];
#pragma unroll
            for (int mt = 0; mt < 2; ++mt) {
                const int r = wm + mt * 16 + gid;
                a[mt][0] = __float_as_uint(Ac[(uint32_t)r * LDA + kb + tig]);
                a[mt][1] = __float_as_uint(Ac[(uint32_t)(r + 8) * LDA + kb + tig]);
                a[mt][2] = __float_as_uint(Ac[(uint32_t)r * LDA + kb + tig + 4]);
                a[mt][3] = __float_as_uint(Ac[(uint32_t)(r + 8) * LDA + kb + tig + 4]);
            }
#pragma unroll
            for (int nt = 0; nt < 8; ++nt) {
                const int col = wn + nt * 8 + gid;
                b[nt][0] = __float_as_uint(Bc[(uint32_t)(kb + tig) * LDB + col]);
                b[nt][1] = __float_as_uint(Bc[(uint32_t)(kb + tig + 4) * LDB + col]);
            }
#pragma unroll
            for (int mt = 0; mt < 2; ++mt)
#pragma unroll
                for (int nt = 0; nt < 8; ++nt)
                    mma_tf32(c[mt][nt], a[mt], b[nt][0], b[nt][1]);
        }
    }

#pragma unroll
    for (int mt = 0; mt < 2; ++mt) {
        const int row0 = bm + wm + mt * 16 + gid;
#pragma unroll
        for (int nt = 0; nt < 8; ++nt) {
            const int coln = bn + wn + nt * 8 + 2 * tig;
            const float2 bv = *(const float2*)(bias + coln);
            float2 v0, v1;
            v0.x = c[mt][nt][0] + bv.x; v0.y = c[mt][nt][1] + bv.y;
            v1.x = c[mt][nt][2] + bv.x; v1.y = c[mt][nt][3] + bv.y;
            if (MODE == 1) {
                v0.x = f2tff(fmaxf(v0.x, 0.f)); v0.y = f2tff(fmaxf(v0.y, 0.f));
                v1.x = f2tff(fmaxf(v1.x, 0.f)); v1.y = f2tff(fmaxf(v1.y, 0.f));
            }
            *(float2*)(C + (size_t)row0 * N + coln)       = v0;
            *(float2*)(C + (size_t)(row0 + 8) * N + coln) = v1;
        }
    }
}

// ---------------- split qkv: q (fp32 scaled) + PRE-SPLIT kb/ks/vb/vs -----------
__global__ __launch_bounds__(384)
void split_qkv_kernel()
{
    int row = blockIdx.x;
    int n   = row >> 10;
    int t   = row & (TT - 1);
    int c0  = threadIdx.x * 4;
    float4 v = *(const float4*)(g_qkv + (size_t)row * 1536 + c0);
    float vals[4] = {v.x, v.y, v.z, v.w};
#pragma unroll
    for (int u = 0; u < 4; ++u) {
        int c = c0 + u;
        int h = c / 192;
        int r = c - h * 192;
        int d = r / 3;
        int j = r - d * 3;
        size_t dst = ((size_t)(n * HH + h) * TT + t) * DD + d;
        if (j == 0) {
            g_q[dst] = vals[u] * QSCALE;
        } else {
            uint32_t b, s;
            tfsplit(vals[u], b, s);
            if (j == 1) { g_kb[dst] = __uint_as_float(b); g_ks[dst] = __uint_as_float(s); }
            else        { g_vb[dst] = __uint_as_float(b); g_vs[dst] = __uint_as_float(s); }
        }
    }
}

// ---------------- FlashAttention-2, pre-split K/V, 32-key tiles ----------------
// Inner loops are pure LDS + HMMA (only P is split in registers).
#define KT   32
#define LDK  68
#define LDV  72
#define LDP  36
#define KB_T (KT * LDK)                           // 2176 floats per K tile
#define VB_T (KT * LDV)                           // 2304 floats per V tile
#define OFF_KB 0
#define OFF_KS (2 * KB_T)                         // 4352
#define OFF_VB (4 * KB_T)                         // 8704
#define OFF_VS (OFF_VB + 2 * VB_T)                // 13312
#define OFF_P  (OFF_VB + 4 * VB_T)                // 17920
#define ATTN_SMEM_FLOATS (OFF_P + 4 * 16 * LDP)   // 20224
#define ATTN_SMEM_BYTES  (ATTN_SMEM_FLOATS * 4)   // 80896

__global__ __launch_bounds__(128)
void attn_mma_kernel()
{
    extern __shared__ float sm[];

    const int tid  = threadIdx.x;
    const int warp = tid >> 5, lane = tid & 31;
    const int gid  = lane >> 2, tig = lane & 3;
    const int qt   = gridDim.x - 1 - blockIdx.x;   // heavy q-tiles first
    const int nh   = blockIdx.y;
    const int row0 = qt * 64 + warp * 16;

    const float* kbp = g_kb + (size_t)nh * TT * DD;
    const float* ksp = g_ks + (size_t)nh * TT * DD;
    const float* vbp = g_vb + (size_t)nh * TT * DD;
    const float* vsp = g_vs + (size_t)nh * TT * DD;

    const uint32_t sbase = (uint32_t)__cvta_generic_to_shared(sm);

    uint32_t qfb[8][4], qfs[8][4];
    {
        const float* qp = g_q + ((size_t)nh * TT + row0) * DD;
#pragma unroll
        for (int kt = 0; kt < 8; ++kt) {
            tfsplit(qp[gid * DD + kt * 8 + tig],           qfb[kt][0], qfs[kt][0]);
            tfsplit(qp[(gid + 8) * DD + kt * 8 + tig],     qfb[kt][1], qfs[kt][1]);
            tfsplit(qp[gid * DD + kt * 8 + tig + 4],       qfb[kt][2], qfs[kt][2]);
            tfsplit(qp[(gid + 8) * DD + kt * 8 + tig + 4], qfb[kt][3], qfs[kt][3]);
        }
    }

    float o[8][4];
#pragma unroll
    for (int nt = 0; nt < 8; ++nt)
#pragma unroll
        for (int j = 0; j < 4; ++j) o[nt][j] = 0.f;
    float m0 = -INFINITY, m1 = -INFINITY, l0 = 0.f, l1 = 0.f;

    const int ntiles = 2 * qt + 2;

    // 4 arrays x 512 float4 per tile; 128 threads -> 16 cp.async/thread
    auto prefetch = [&](int t) {
        const size_t gb = (size_t)t * KT * DD;
        const int buf = t & 1;
        const uint32_t kbOff = OFF_KB + buf * KB_T;
        const uint32_t ksOff = OFF_KS + buf * KB_T;
        const uint32_t vbOff = OFF_VB + buf * VB_T;
        const uint32_t vsOff = OFF_VS + buf * VB_T;
#pragma unroll
        for (int i = 0; i < 4; ++i) {
            int idx = i * 128 + tid;
            int r   = idx >> 4;
            int c4  = (idx & 15) * 4;
            const size_t g = gb + r * DD + c4;
            cp_async16(sbase + (kbOff + r * LDK + c4) * 4, kbp + g);
            cp_async16(sbase + (ksOff + r * LDK + c4) * 4, ksp + g);
            cp_async16(sbase + (vbOff + r * LDV + c4) * 4, vbp + g);
            cp_async16(sbase + (vsOff + r * LDV + c4) * 4, vsp + g);
        }
        cp_commit();
    };

    prefetch(0);

    float* Pw = sm + OFF_P + warp * 16 * LDP;

#pragma unroll 1
    for (int kt_i = 0; kt_i < ntiles; ++kt_i) {
        cp_wait<0>();
        __syncthreads();
        if (kt_i + 1 < ntiles) prefetch(kt_i + 1);

        const int buf = kt_i & 1;
        const float* Kb = sm + OFF_KB + buf * KB_T;
        const float* Ks = sm + OFF_KS + buf * KB_T;
        const float* Vb = sm + OFF_VB + buf * VB_T;
        const float* Vs = sm + OFF_VS + buf * VB_T;

        // ---- S = Q @ K^T (16x32 per warp): pure LDS + mma ----
        float cs[4][4];
#pragma unroll
        for (int nt = 0; nt < 4; ++nt) {
#pragma unroll
            for (int j = 0; j < 4; ++j) cs[nt][j] = 0.f;
#pragma unroll
            for (int dk = 0; dk < 8; ++dk) {
                const int r0 = (nt * 8 + gid) * LDK + dk * 8 + tig;
                uint32_t bb0 = __float_as_uint(Kb[r0]);
                uint32_t bb1 = __float_as_uint(Kb[r0 + 4]);
                uint32_t bs0 = __float_as_uint(Ks[r0]);
                uint32_t bs1 = __float_as_uint(Ks[r0 + 4]);
                mma_tf32(cs[nt], qfb[dk], bb0, bb1);
                mma_tf32(cs[nt], qfb[dk], bs0, bs1);
                mma_tf32(cs[nt], qfs[dk], bb0, bb1);
            }
        }

        if (kt_i >= 2 * qt) {
            const int rl0 = row0 + gid;
            const int rl1 = rl0 + 8;
#pragma unroll
            for (int nt = 0; nt < 4; ++nt) {
                int j = kt_i * KT + nt * 8 + 2 * tig;
                if (j     > rl0) cs[nt][0] = -INFINITY;
                if (j + 1 > rl0) cs[nt][1] = -INFINITY;
                if (j     > rl1) cs[nt][2] = -INFINITY;
                if (j + 1 > rl1) cs[nt][3] = -INFINITY;
            }
        }

        float mx0 = -INFINITY, mx1 = -INFINITY;
#pragma unroll
        for (int nt = 0; nt < 4; ++nt) {
            mx0 = fmaxf(mx0, fmaxf(cs[nt][0], cs[nt][1]));
            mx1 = fmaxf(mx1, fmaxf(cs[nt][2], cs[nt][3]));
        }
        mx0 = fmaxf(mx0, __shfl_xor_sync(0xffffffffu, mx0, 1));
        mx0 = fmaxf(mx0, __shfl_xor_sync(0xffffffffu, mx0, 2));
        mx1 = fmaxf(mx1, __shfl_xor_sync(0xffffffffu, mx1, 1));
        mx1 = fmaxf(mx1, __shfl_xor_sync(0xffffffffu, mx1, 2));

        const float mn0 = fmaxf(m0, mx0);
        const float mn1 = fmaxf(m1, mx1);
        const float cor0 = ex2(m0 - mn0);
        const float cor1 = ex2(m1 - mn1);
        l0 *= cor0; l1 *= cor1;
#pragma unroll
        for (int nt = 0; nt < 8; ++nt) {
            o[nt][0] *= cor0; o[nt][1] *= cor0;
            o[nt][2] *= cor1; o[nt][3] *= cor1;
        }

        float rs0 = 0.f, rs1 = 0.f;
#pragma unroll
        for (int nt = 0; nt < 4; ++nt) {
            float p0 = ex2(cs[nt][0] - mn0);
            float p1 = ex2(cs[nt][1] - mn0);
            float p2 = ex2(cs[nt][2] - mn1);
            float p3 = ex2(cs[nt][3] - mn1);
            rs0 += p0 + p1; rs1 += p2 + p3;
            int col = nt * 8 + 2 * tig;
            *(float2*)(Pw + gid * LDP + col)       = make_float2(p0, p1);
            *(float2*)(Pw + (gid + 8) * LDP + col) = make_float2(p2, p3);
        }
        rs0 += __shfl_xor_sync(0xffffffffu, rs0, 1);
        rs0 += __shfl_xor_sync(0xffffffffu, rs0, 2);
        rs1 += __shfl_xor_sync(0xffffffffu, rs1, 1);
        rs1 += __shfl_xor_sync(0xffffffffu, rs1, 2);
        l0 += rs0; l1 += rs1;
        m0 = mn0; m1 = mn1;

        __syncwarp();

        // ---- O += P @ V: P split in registers, V pre-split (pure LDS + mma) ----
#pragma unroll
        for (int kk = 0; kk < 4; ++kk) {
            uint32_t ab[4], as_[4];
            tfsplit(Pw[gid * LDP + kk * 8 + tig],           ab[0], as_[0]);
            tfsplit(Pw[(gid + 8) * LDP + kk * 8 + tig],     ab[1], as_[1]);
            tfsplit(Pw[gid * LDP + kk * 8 + tig + 4],       ab[2], as_[2]);
            tfsplit(Pw[(gid + 8) * LDP + kk * 8 + tig + 4], ab[3], as_[3]);
#pragma unroll
            for (int nt = 0; nt < 8; ++nt) {
                const int r0 = (kk * 8 + tig) * LDV + nt * 8 + gid;
                const int r1 = (kk * 8 + tig + 4) * LDV + nt * 8 + gid;
                uint32_t bb0 = __float_as_uint(Vb[r0]);
                uint32_t bb1 = __float_as_uint(Vb[r1]);
                uint32_t bs0 = __float_as_uint(Vs[r0]);
                uint32_t bs1 = __float_as_uint(Vs[r1]);
                mma_tf32(o[nt], ab,  bb0, bb1);
                mma_tf32(o[nt], ab,  bs0, bs1);
                mma_tf32(o[nt], as_, bb0, bb1);
            }
        }
    }

    const float i0 = 1.f / l0;
    const float i1 = 1.f / l1;
    const int n = nh >> 3, hh = nh & 7;
    const int rg0 = row0 + gid;
#pragma unroll
    for (int nt = 0; nt < 8; ++nt) {
        int col = hh * DD + nt * 8 + 2 * tig;
        *(float2*)(g_att + (size_t)(n * TT + rg0) * DMOD + col) =
            make_float2(o[nt][0] * i0, o[nt][1] * i0);
        *(float2*)(g_att + (size_t)(n * TT + rg0 + 8) * DMOD + col) =
            make_float2(o[nt][2] * i1, o[nt][3] * i1);
    }
}

// ---------------- fused residual add + LayerNorm -------------------------------
template<bool WRITE_TF>
__global__ __launch_bounds__(256)
void add_ln_kernel(const float* __restrict__ a, const float* __restrict__ b,
                   const float* __restrict__ gamma, const float* __restrict__ beta,
                   float* __restrict__ out)
{
    int row = blockIdx.x;
    int tid = threadIdx.x;
    const float* ar = a + (size_t)row * DMOD;
    const float* br = b + (size_t)row * DMOD;

    float x0 = ar[tid]       + br[tid];
    float x1 = ar[tid + 256] + br[tid + 256];

    float sum = x0 + x1;
    float sq  = x0 * x0 + x1 * x1;
#pragma unroll
    for (int off = 16; off; off >>= 1) {
        sum += __shfl_xor_sync(0xffffffffu, sum, off);
        sq  += __shfl_xor_sync(0xffffffffu, sq,  off);
    }
    __shared__ float s1[8], s2[8];
    int wid = tid >> 5, lane = tid & 31;
    if (lane == 0) { s1[wid] = sum; s2[wid] = sq; }
    __syncthreads();
    float S = 0.f, Q = 0.f;
#pragma unroll
    for (int i = 0; i < 8; ++i) { S += s1[i]; Q += s2[i]; }

    float mean = S * (1.f / DMOD);
    float var  = Q * (1.f / DMOD) - mean * mean;
    float rstd = 1.f / sqrtf(var + 1e-3f);

    float y0 = gamma[tid]       * (x0 - mean) * rstd + beta[tid];
    float y1 = gamma[tid + 256] * (x1 - mean) * rstd + beta[tid + 256];
    out[(size_t)row * DMOD + tid]       = y0;
    out[(size_t)row * DMOD + tid + 256] = y1;
    if (WRITE_TF) {
        g_htf[(size_t)row * DMOD + tid]       = f2tff(y0);
        g_htf[(size_t)row * DMOD + tid + 256] = f2tff(y1);
    }
}

// ---------------- launch ------------------------------------------------------
extern "C" void kernel_launch(void* const* d_in, const int* in_sizes, int n_in,
                              void* d_out, int out_size)
{
    const int*   x     = (const int*)  d_in[0];
    const float* emb   = (const float*)d_in[1];
    const float* Wqkv  = (const float*)d_in[2];
    const float* bqkv  = (const float*)d_in[3];
    const float* Wff   = (const float*)d_in[4];
    const float* bff   = (const float*)d_in[5];
    const float* Wo    = (const float*)d_in[6];
    const float* bo    = (const float*)d_in[7];
    const float* g1    = (const float*)d_in[8];
    const float* beta1 = (const float*)d_in[9];
    const float* g2    = (const float*)d_in[10];
    const float* beta2 = (const float*)d_in[11];
    float* out = (float*)d_out;

    float *h, *qkv, *att, *ff1, *ff2, *htf, *wqkv, *wff, *wo;
    cudaGetSymbolAddress((void**)&h,    g_h);
    cudaGetSymbolAddress((void**)&htf,  g_htf);
    cudaGetSymbolAddress((void**)&qkv,  g_qkv);
    cudaGetSymbolAddress((void**)&att,  g_att);
    cudaGetSymbolAddress((void**)&ff1,  g_ff1);
    cudaGetSymbolAddress((void**)&ff2,  g_ff2);
    cudaGetSymbolAddress((void**)&wqkv, g_wqkv);
    cudaGetSymbolAddress((void**)&wff,  g_wff);
    cudaGetSymbolAddress((void**)&wo,   g_wo);

    cudaFuncSetAttribute(attn_mma_kernel,
                         cudaFuncAttributeMaxDynamicSharedMemorySize, ATTN_SMEM_BYTES);

    round_copy_kernel<<<592, 256>>>(Wqkv, wqkv, NLAY * DMOD * 3 * DMOD / 4);
    round_copy_kernel<<<592, 256>>>(Wff,  wff,  NLAY * DMOD * DFFV / 4);
    round_copy_kernel<<<592, 256>>>(Wo,   wo,   NLAY * DFFV * DMOD / 4);

    embed_kernel<<<ROWS, 128>>>(x, emb);

    for (int l = 0; l < NLAY; ++l) {
        gemm_tf32<0><<<dim3(1536 / 128, ROWS / 128), 256>>>(
            htf, wqkv + (size_t)l * DMOD * 3 * DMOD, bqkv + (size_t)l * 3 * DMOD,
            qkv, ROWS, 3 * DMOD, DMOD);

        split_qkv_kernel<<<ROWS, 384>>>();

        attn_mma_kernel<<<dim3(TT / 64, NH), 128, ATTN_SMEM_BYTES>>>();

        add_ln_kernel<true><<<ROWS, 256>>>(h, att,
            g1 + (size_t)l * DMOD, beta1 + (size_t)l * DMOD, h);

        gemm_tf32<1><<<dim3(DFFV / 128, ROWS / 128), 256>>>(
            htf, wff + (size_t)l * DMOD * DFFV, bff + (size_t)l * DFFV,
            ff1, ROWS, DFFV, DMOD);

        gemm_tf32<0><<<dim3(DMOD / 128, ROWS / 128), 256>>>(
            ff1, wo + (size_t)l * DFFV * DMOD, bo + (size_t)l * DMOD,
            ff2, ROWS, DMOD, DFFV);

        if (l == NLAY - 1)
            add_ln_kernel<false><<<ROWS, 256>>>(h, ff2,
                g2 + (size_t)l * DMOD, beta2 + (size_t)l * DMOD, out);
        else
            add_ln_kernel<true><<<ROWS, 256>>>(h, ff2,
                g2 + (size_t)l * DMOD, beta2 + (size_t)l * DMOD, h);
    }
}

// round 12
// speedup vs baseline: 1.6776x; 1.0622x over previous
#include <cuda_runtime.h>
#include <math.h>
#include <stdint.h>

#define NB   4
#define TT   1024
#define HH   8
#define DD   64
#define DMOD 512
#define DFFV 1024
#define NLAY 6
#define ROWS (NB * TT)   // 4096
#define NH   (NB * HH)   // 32

#define QSCALE (0.125f * 1.4426950408889634f)

// ---------------- scratch (static device globals; no allocation) -------------
__device__ float g_h   [ROWS * DMOD];
__device__ float g_htf [ROWS * DMOD];
__device__ float g_qkv [ROWS * 3 * DMOD];
__device__ float g_att [ROWS * DMOD];
__device__ float g_ff1 [ROWS * DFFV];
__device__ float g_ff2 [ROWS * DMOD];
__device__ float g_q   [NH * TT * DD];
__device__ float g_kb  [NH * TT * DD];   // tf32-rounded K (single-rounded)
__device__ float g_vb  [NH * TT * DD];   // tf32 big part of V
__device__ float g_vs  [NH * TT * DD];   // tf32 small part of V
// tf32-pre-rounded weights
__device__ float g_wqkv[NLAY * DMOD * 3 * DMOD];
__device__ float g_wff [NLAY * DMOD * DFFV];
__device__ float g_wo  [NLAY * DFFV * DMOD];

// ---------------- common PTX helpers -------------------------------------------
__device__ __forceinline__ uint32_t f2tf(float f)
{
    uint32_t r;
    asm("cvt.rna.tf32.f32 %0, %1;" : "=r"(r) : "f"(f));
    return r;
}
__device__ __forceinline__ float f2tff(float f) { return __uint_as_float(f2tf(f)); }
__device__ __forceinline__ void tfsplit(float x, uint32_t& big, uint32_t& small)
{
    big   = f2tf(x);
    small = f2tf(x - __uint_as_float(big));
}
__device__ __forceinline__ void mma_tf32(float* c, const uint32_t* a, uint32_t b0, uint32_t b1)
{
    asm volatile(
        "mma.sync.aligned.m16n8k8.row.col.f32.tf32.tf32.f32 "
        "{%0,%1,%2,%3}, {%4,%5,%6,%7}, {%8,%9}, {%0,%1,%2,%3};"
        : "+f"(c[0]), "+f"(c[1]), "+f"(c[2]), "+f"(c[3])
        : "r"(a[0]), "r"(a[1]), "r"(a[2]), "r"(a[3]), "r"(b0), "r"(b1));
}
__device__ __forceinline__ void cp_async16(uint32_t saddr, const void* gaddr)
{
    asm volatile("cp.async.cg.shared.global [%0], [%1], 16;" :: "r"(saddr), "l"(gaddr));
}
__device__ __forceinline__ void cp_commit() { asm volatile("cp.async.commit_group;"); }
template<int N> __device__ __forceinline__ void cp_wait() {
    asm volatile("cp.async.wait_group %0;" :: "n"(N));
}
__device__ __forceinline__ float ex2(float x)
{
    float r;
    asm("ex2.approx.ftz.f32 %0, %1;" : "=f"(r) : "f"(x));
    return r;
}

// ---------------- weight pre-rounding prepass ----------------------------------
__global__ __launch_bounds__(256)
void round_copy_kernel(const float* __restrict__ src, float* __restrict__ dst, int n4)
{
    int i = blockIdx.x * blockDim.x + threadIdx.x;
    for (; i < n4; i += gridDim.x * blockDim.x) {
        float4 v = ((const float4*)src)[i];
        v.x = f2tff(v.x); v.y = f2tff(v.y); v.z = f2tff(v.z); v.w = f2tff(v.w);
        ((float4*)dst)[i] = v;
    }
}

// ---------------- embedding + positional encoding (all-fp32, MUFU) -------------
__global__ void embed_kernel(const int* __restrict__ x, const float* __restrict__ emb)
{
    int row = blockIdx.x;
    int t   = row & (TT - 1);
    int tok = x[row];
    const float* e = emb + (size_t)tok * DMOD;
    float tf = (float)t;
    for (int i = threadIdx.x; i < DMOD; i += blockDim.x) {
        float expo = -2.0f * (float)(i >> 1) * (1.0f / (float)DMOD);
        float rate = powf(10000.0f, expo);
        float ang  = tf * rate;
        float s, c;
        sincosf(ang, &s, &c);
        float p   = (i & 1) ? c : s;
        float val = e[i] * 22.62741699796952f + p;  // sqrt(512)
        g_h  [(size_t)row * DMOD + i] = val;
        g_htf[(size_t)row * DMOD + i] = f2tff(val);
    }
}

// ---------------- TF32 GEMM — cvt-free, 3-stage cp.async pipeline --------------
#define LDA 20u
#define LDB 136u
#define STG 3

template<int MODE>
__global__ __launch_bounds__(256)
void gemm_tf32(const float* __restrict__ A, const float* __restrict__ B,
               const float* __restrict__ bias, float* __restrict__ C,
               int M, int N, int K)
{
    __shared__ float As[STG][128 * LDA];
    __shared__ float Bs[STG][16 * LDB];

    const int tid  = threadIdx.x;
    const int bm   = blockIdx.y * 128;
    const int bn   = blockIdx.x * 128;

    const int am = tid >> 1, ak = (tid & 1) * 8;
    const int bk = tid >> 4, bcol = (tid & 15) * 8;

    const uint32_t sA = (uint32_t)__cvta_generic_to_shared(&As[0][0]);
    const uint32_t sB = (uint32_t)__cvta_generic_to_shared(&Bs[0][0]);

    const int warp = tid >> 5, lane = tid & 31;
    const int gid  = lane >> 2, tig = lane & 3;
    const int wm   = (warp & 3) * 32;
    const int wn   = (warp >> 2) * 64;

    float c[2][8][4];
#pragma unroll
    for (int mt = 0; mt < 2; ++mt)
#pragma unroll
        for (int nt = 0; nt < 8; ++nt)
#pragma unroll
            for (int j = 0; j < 4; ++j) c[mt][nt][j] = 0.f;

    const int nIter = K >> 4;

    auto issue = [&](int t) {
        const int buf = t % STG;
        const float* Ap = A + (size_t)(bm + am) * K + t * 16 + ak;
        const float* Bp = B + (size_t)(t * 16 + bk) * N + bn + bcol;
        uint32_t sa = sA + (buf * 128 * LDA + am * LDA + ak) * 4;
        uint32_t sb = sB + (buf * 16 * LDB + bk * LDB + bcol) * 4;
        cp_async16(sa,      Ap);
        cp_async16(sa + 16, Ap + 4);
        cp_async16(sb,      Bp);
        cp_async16(sb + 16, Bp + 4);
        cp_commit();
    };

    issue(0);
    if (nIter > 1) issue(1);

    for (int it = 0; it < nIter; ++it) {
        if (it + 1 < nIter) cp_wait<1>(); else cp_wait<0>();
        __syncthreads();
        if (it + 2 < nIter) issue(it + 2);

        const float* Ac = As[it % STG];
        const float* Bc = Bs[it % STG];
#pragma unroll
        for (int ks = 0; ks < 2; ++ks) {
            const int kb = ks * 8;
            uint32_t a[2][4], b[8][2];
#pragma unroll
            for (int mt = 0; mt < 2; ++mt) {
                const int r = wm + mt * 16 + gid;
                a[mt][0] = __float_as_uint(Ac[(uint32_t)r * LDA + kb + tig]);
                a[mt][1] = __float_as_uint(Ac[(uint32_t)(r + 8) * LDA + kb + tig]);
                a[mt][2] = __float_as_uint(Ac[(uint32_t)r * LDA + kb + tig + 4]);
                a[mt][3] = __float_as_uint(Ac[(uint32_t)(r + 8) * LDA + kb + tig + 4]);
            }
#pragma unroll
            for (int nt = 0; nt < 8; ++nt) {
                const int col = wn + nt * 8 + gid;
                b[nt][0] = __float_as_uint(Bc[(uint32_t)(kb + tig) * LDB + col]);
                b[nt][1] = __float_as_uint(Bc[(uint32_t)(kb + tig + 4) * LDB + col]);
            }
#pragma unroll
            for (int mt = 0; mt < 2; ++mt)
#pragma unroll
                for (int nt = 0; nt < 8; ++nt)
                    mma_tf32(c[mt][nt], a[mt], b[nt][0], b[nt][1]);
        }
    }

#pragma unroll
    for (int mt = 0; mt < 2; ++mt) {
        const int row0 = bm + wm + mt * 16 + gid;
#pragma unroll
        for (int nt = 0; nt < 8; ++nt) {
            const int coln = bn + wn + nt * 8 + 2 * tig;
            const float2 bv = *(const float2*)(bias + coln);
            float2 v0, v1;
            v0.x = c[mt][nt][0] + bv.x; v0.y = c[mt][nt][1] + bv.y;
            v1.x = c[mt][nt][2] + bv.x; v1.y = c[mt][nt][3] + bv.y;
            if (MODE == 1) {
                v0.x = f2tff(fmaxf(v0.x, 0.f)); v0.y = f2tff(fmaxf(v0.y, 0.f));
                v1.x = f2tff(fmaxf(v1.x, 0.f)); v1.y = f2tff(fmaxf(v1.y, 0.f));
            }
            *(float2*)(C + (size_t)row0 * N + coln)       = v0;
            *(float2*)(C + (size_t)(row0 + 8) * N + coln) = v1;
        }
    }
}

// ---------------- split qkv: q (fp32 scaled), K tf32-rounded, V pre-split -------
__global__ __launch_bounds__(384)
void split_qkv_kernel()
{
    int row = blockIdx.x;
    int n   = row >> 10;
    int t   = row & (TT - 1);
    int c0  = threadIdx.x * 4;
    float4 v = *(const float4*)(g_qkv + (size_t)row * 1536 + c0);
    float vals[4] = {v.x, v.y, v.z, v.w};
#pragma unroll
    for (int u = 0; u < 4; ++u) {
        int c = c0 + u;
        int h = c / 192;
        int r = c - h * 192;
        int d = r / 3;
        int j = r - d * 3;
        size_t dst = ((size_t)(n * HH + h) * TT + t) * DD + d;
        if (j == 0) {
            g_q[dst] = vals[u] * QSCALE;
        } else if (j == 1) {
            g_kb[dst] = f2tff(vals[u]);          // single tf32 rounding of K
        } else {
            uint32_t b, s;
            tfsplit(vals[u], b, s);
            g_vb[dst] = __uint_as_float(b);
            g_vs[dst] = __uint_as_float(s);
        }
    }
}

// ---------------- FlashAttention-2: q compensated, K single, V compensated -----
// smem 63.5KB -> 3 blocks/SM (12 warps). QK: 2 mma/group. PV: 3 mma/group.
#define KT   32
#define LDK  68
#define LDV  72
#define LDP  36
#define KB_T (KT * LDK)                           // 2176
#define VB_T (KT * LDV)                           // 2304
#define OFF_KB 0
#define OFF_VB (2 * KB_T)                         // 4352
#define OFF_VS (OFF_VB + 2 * VB_T)                // 8960
#define OFF_P  (OFF_VS + 2 * VB_T)                // 13568
#define ATTN_SMEM_FLOATS (OFF_P + 4 * 16 * LDP)   // 15872
#define ATTN_SMEM_BYTES  (ATTN_SMEM_FLOATS * 4)   // 63488

__global__ __launch_bounds__(128)
void attn_mma_kernel()
{
    extern __shared__ float sm[];

    const int tid  = threadIdx.x;
    const int warp = tid >> 5, lane = tid & 31;
    const int gid  = lane >> 2, tig = lane & 3;
    const int qt   = gridDim.x - 1 - blockIdx.x;   // heavy q-tiles first
    const int nh   = blockIdx.y;
    const int row0 = qt * 64 + warp * 16;

    const float* kbp = g_kb + (size_t)nh * TT * DD;
    const float* vbp = g_vb + (size_t)nh * TT * DD;
    const float* vsp = g_vs + (size_t)nh * TT * DD;

    const uint32_t sbase = (uint32_t)__cvta_generic_to_shared(sm);

    uint32_t qfb[8][4], qfs[8][4];
    {
        const float* qp = g_q + ((size_t)nh * TT + row0) * DD;
#pragma unroll
        for (int kt = 0; kt < 8; ++kt) {
            tfsplit(qp[gid * DD + kt * 8 + tig],           qfb[kt][0], qfs[kt][0]);
            tfsplit(qp[(gid + 8) * DD + kt * 8 + tig],     qfb[kt][1], qfs[kt][1]);
            tfsplit(qp[gid * DD + kt * 8 + tig + 4],       qfb[kt][2], qfs[kt][2]);
            tfsplit(qp[(gid + 8) * DD + kt * 8 + tig + 4], qfb[kt][3], qfs[kt][3]);
        }
    }

    float o[8][4];
#pragma unroll
    for (int nt = 0; nt < 8; ++nt)
#pragma unroll
        for (int j = 0; j < 4; ++j) o[nt][j] = 0.f;
    float m0 = -INFINITY, m1 = -INFINITY, l0 = 0.f, l1 = 0.f;

    const int ntiles = 2 * qt + 2;

    // 3 arrays x 512 float4 per tile; 128 threads -> 12 cp.async/thread
    auto prefetch = [&](int t) {
        const size_t gb = (size_t)t * KT * DD;
        const int buf = t & 1;
        const uint32_t kbOff = OFF_KB + buf * KB_T;
        const uint32_t vbOff = OFF_VB + buf * VB_T;
        const uint32_t vsOff = OFF_VS + buf * VB_T;
#pragma unroll
        for (int i = 0; i < 4; ++i) {
            int idx = i * 128 + tid;
            int r   = idx >> 4;
            int c4  = (idx & 15) * 4;
            const size_t g = gb + r * DD + c4;
            cp_async16(sbase + (kbOff + r * LDK + c4) * 4, kbp + g);
            cp_async16(sbase + (vbOff + r * LDV + c4) * 4, vbp + g);
            cp_async16(sbase + (vsOff + r * LDV + c4) * 4, vsp + g);
        }
        cp_commit();
    };

    prefetch(0);

    float* Pw = sm + OFF_P + warp * 16 * LDP;

#pragma unroll 1
    for (int kt_i = 0; kt_i < ntiles; ++kt_i) {
        cp_wait<0>();
        __syncthreads();
        if (kt_i + 1 < ntiles) prefetch(kt_i + 1);

        const int buf = kt_i & 1;
        const float* Kb = sm + OFF_KB + buf * KB_T;
        const float* Vb = sm + OFF_VB + buf * VB_T;
        const float* Vs = sm + OFF_VS + buf * VB_T;

        // ---- S = (q_big + q_small) @ Kb^T : 2 mma per group ----
        float cs[4][4];
#pragma unroll
        for (int nt = 0; nt < 4; ++nt) {
#pragma unroll
            for (int j = 0; j < 4; ++j) cs[nt][j] = 0.f;
#pragma unroll
            for (int dk = 0; dk < 8; ++dk) {
                const int r0 = (nt * 8 + gid) * LDK + dk * 8 + tig;
                uint32_t bb0 = __float_as_uint(Kb[r0]);
                uint32_t bb1 = __float_as_uint(Kb[r0 + 4]);
                mma_tf32(cs[nt], qfb[dk], bb0, bb1);
                mma_tf32(cs[nt], qfs[dk], bb0, bb1);
            }
        }

        if (kt_i >= 2 * qt) {
            const int rl0 = row0 + gid;
            const int rl1 = rl0 + 8;
#pragma unroll
            for (int nt = 0; nt < 4; ++nt) {
                int j = kt_i * KT + nt * 8 + 2 * tig;
                if (j     > rl0) cs[nt][0] = -INFINITY;
                if (j + 1 > rl0) cs[nt][1] = -INFINITY;
                if (j     > rl1) cs[nt][2] = -INFINITY;
                if (j + 1 > rl1) cs[nt][3] = -INFINITY;
            }
        }

        float mx0 = -INFINITY, mx1 = -INFINITY;
#pragma unroll
        for (int nt = 0; nt < 4; ++nt) {
            mx0 = fmaxf(mx0, fmaxf(cs[nt][0], cs[nt][1]));
            mx1 = fmaxf(mx1, fmaxf(cs[nt][2], cs[nt][3]));
        }
        mx0 = fmaxf(mx0, __shfl_xor_sync(0xffffffffu, mx0, 1));
        mx0 = fmaxf(mx0, __shfl_xor_sync(0xffffffffu, mx0, 2));
        mx1 = fmaxf(mx1, __shfl_xor_sync(0xffffffffu, mx1, 1));
        mx1 = fmaxf(mx1, __shfl_xor_sync(0xffffffffu, mx1, 2));

        const float mn0 = fmaxf(m0, mx0);
        const float mn1 = fmaxf(m1, mx1);
        const float cor0 = ex2(m0 - mn0);
        const float cor1 = ex2(m1 - mn1);
        l0 *= cor0; l1 *= cor1;
#pragma unroll
        for (int nt = 0; nt < 8; ++nt) {
            o[nt][0] *= cor0; o[nt][1] *= cor0;
            o[nt][2] *= cor1; o[nt][3] *= cor1;
        }

        float rs0 = 0.f, rs1 = 0.f;
#pragma unroll
        for (int nt = 0; nt < 4; ++nt) {
            float p0 = ex2(cs[nt][0] - mn0);
            float p1 = ex2(cs[nt][1] - mn0);
            float p2 = ex2(cs[nt][2] - mn1);
            float p3 = ex2(cs[nt][3] - mn1);
            rs0 += p0 + p1; rs1 += p2 + p3;
            int col = nt * 8 + 2 * tig;
            *(float2*)(Pw + gid * LDP + col)       = make_float2(p0, p1);
            *(float2*)(Pw + (gid + 8) * LDP + col) = make_float2(p2, p3);
        }
        rs0 += __shfl_xor_sync(0xffffffffu, rs0, 1);
        rs0 += __shfl_xor_sync(0xffffffffu, rs0, 2);
        rs1 += __shfl_xor_sync(0xffffffffu, rs1, 1);
        rs1 += __shfl_xor_sync(0xffffffffu, rs1, 2);
        l0 += rs0; l1 += rs1;
        m0 = mn0; m1 = mn1;

        __syncwarp();

        // ---- O += P @ V: full 3-term compensation (P reg-split, V pre-split) ----
#pragma unroll
        for (int kk = 0; kk < 4; ++kk) {
            uint32_t ab[4], as_[4];
            tfsplit(Pw[gid * LDP + kk * 8 + tig],           ab[0], as_[0]);
            tfsplit(Pw[(gid + 8) * LDP + kk * 8 + tig],     ab[1], as_[1]);
            tfsplit(Pw[gid * LDP + kk * 8 + tig + 4],       ab[2], as_[2]);
            tfsplit(Pw[(gid + 8) * LDP + kk * 8 + tig + 4], ab[3], as_[3]);
#pragma unroll
            for (int nt = 0; nt < 8; ++nt) {
                const int r0 = (kk * 8 + tig) * LDV + nt * 8 + gid;
                const int r1 = (kk * 8 + tig + 4) * LDV + nt * 8 + gid;
                uint32_t bb0 = __float_as_uint(Vb[r0]);
                uint32_t bb1 = __float_as_uint(Vb[r1]);
                uint32_t bs0 = __float_as_uint(Vs[r0]);
                uint32_t bs1 = __float_as_uint(Vs[r1]);
                mma_tf32(o[nt], ab,  bb0, bb1);
                mma_tf32(o[nt], ab,  bs0, bs1);
                mma_tf32(o[nt], as_, bb0, bb1);
            }
        }
    }

    const float i0 = 1.f / l0;
    const float i1 = 1.f / l1;
    const int n = nh >> 3, hh = nh & 7;
    const int rg0 = row0 + gid;
#pragma unroll
    for (int nt = 0; nt < 8; ++nt) {
        int col = hh * DD + nt * 8 + 2 * tig;
        *(float2*)(g_att + (size_t)(n * TT + rg0) * DMOD + col) =
            make_float2(o[nt][0] * i0, o[nt][1] * i0);
        *(float2*)(g_att + (size_t)(n * TT + rg0 + 8) * DMOD + col) =
            make_float2(o[nt][2] * i1, o[nt][3] * i1);
    }
}

// ---------------- fused residual add + LayerNorm -------------------------------
template<bool WRITE_TF>
__global__ __launch_bounds__(256)
void add_ln_kernel(const float* __restrict__ a, const float* __restrict__ b,
                   const float* __restrict__ gamma, const float* __restrict__ beta,
                   float* __restrict__ out)
{
    int row = blockIdx.x;
    int tid = threadIdx.x;
    const float* ar = a + (size_t)row * DMOD;
    const float* br = b + (size_t)row * DMOD;

    float x0 = ar[tid]       + br[tid];
    float x1 = ar[tid + 256] + br[tid + 256];

    float sum = x0 + x1;
    float sq  = x0 * x0 + x1 * x1;
#pragma unroll
    for (int off = 16; off; off >>= 1) {
        sum += __shfl_xor_sync(0xffffffffu, sum, off);
        sq  += __shfl_xor_sync(0xffffffffu, sq,  off);
    }
    __shared__ float s1[8], s2[8];
    int wid = tid >> 5, lane = tid & 31;
    if (lane == 0) { s1[wid] = sum; s2[wid] = sq; }
    __syncthreads();
    float S = 0.f, Q = 0.f;
#pragma unroll
    for (int i = 0; i < 8; ++i) { S += s1[i]; Q += s2[i]; }

    float mean = S * (1.f / DMOD);
    float var  = Q * (1.f / DMOD) - mean * mean;
    float rstd = 1.f / sqrtf(var + 1e-3f);

    float y0 = gamma[tid]       * (x0 - mean) * rstd + beta[tid];
    float y1 = gamma[tid + 256] * (x1 - mean) * rstd + beta[tid + 256];
    out[(size_t)row * DMOD + tid]       = y0;
    out[(size_t)row * DMOD + tid + 256] = y1;
    if (WRITE_TF) {
        g_htf[(size_t)row * DMOD + tid]       = f2tff(y0);
        g_htf[(size_t)row * DMOD + tid + 256] = f2tff(y1);
    }
}

// ---------------- launch ------------------------------------------------------
extern "C" void kernel_launch(void* const* d_in, const int* in_sizes, int n_in,
                              void* d_out, int out_size)
{
    const int*   x     = (const int*)  d_in[0];
    const float* emb   = (const float*)d_in[1];
    const float* Wqkv  = (const float*)d_in[2];
    const float* bqkv  = (const float*)d_in[3];
    const float* Wff   = (const float*)d_in[4];
    const float* bff   = (const float*)d_in[5];
    const float* Wo    = (const float*)d_in[6];
    const float* bo    = (const float*)d_in[7];
    const float* g1    = (const float*)d_in[8];
    const float* beta1 = (const float*)d_in[9];
    const float* g2    = (const float*)d_in[10];
    const float* beta2 = (const float*)d_in[11];
    float* out = (float*)d_out;

    float *h, *qkv, *att, *ff1, *ff2, *htf, *wqkv, *wff, *wo;
    cudaGetSymbolAddress((void**)&h,    g_h);
    cudaGetSymbolAddress((void**)&htf,  g_htf);
    cudaGetSymbolAddress((void**)&qkv,  g_qkv);
    cudaGetSymbolAddress((void**)&att,  g_att);
    cudaGetSymbolAddress((void**)&ff1,  g_ff1);
    cudaGetSymbolAddress((void**)&ff2,  g_ff2);
    cudaGetSymbolAddress((void**)&wqkv, g_wqkv);
    cudaGetSymbolAddress((void**)&wff,  g_wff);
    cudaGetSymbolAddress((void**)&wo,   g_wo);

    cudaFuncSetAttribute(attn_mma_kernel,
                         cudaFuncAttributeMaxDynamicSharedMemorySize, ATTN_SMEM_BYTES);

    round_copy_kernel<<<592, 256>>>(Wqkv, wqkv, NLAY * DMOD * 3 * DMOD / 4);
    round_copy_kernel<<<592, 256>>>(Wff,  wff,  NLAY * DMOD * DFFV / 4);
    round_copy_kernel<<<592, 256>>>(Wo,   wo,   NLAY * DFFV * DMOD / 4);

    embed_kernel<<<ROWS, 128>>>(x, emb);

    for (int l = 0; l < NLAY; ++l) {
        gemm_tf32<0><<<dim3(1536 / 128, ROWS / 128), 256>>>(
            htf, wqkv + (size_t)l * DMOD * 3 * DMOD, bqkv + (size_t)l * 3 * DMOD,
            qkv, ROWS, 3 * DMOD, DMOD);

        split_qkv_kernel<<<ROWS, 384>>>();

        attn_mma_kernel<<<dim3(TT / 64, NH), 128, ATTN_SMEM_BYTES>>>();

        add_ln_kernel<true><<<ROWS, 256>>>(h, att,
            g1 + (size_t)l * DMOD, beta1 + (size_t)l * DMOD, h);

        gemm_tf32<1><<<dim3(DFFV / 128, ROWS / 128), 256>>>(
            htf, wff + (size_t)l * DMOD * DFFV, bff + (size_t)l * DFFV,
            ff1, ROWS, DFFV, DMOD);

        gemm_tf32<0><<<dim3(DMOD / 128, ROWS / 128), 256>>>(
            ff1, wo + (size_t)l * DFFV * DMOD, bo + (size_t)l * DMOD,
            ff2, ROWS, DMOD, DFFV);

        if (l == NLAY - 1)
            add_ln_kernel<false><<<ROWS, 256>>>(h, ff2,
                g2 + (size_t)l * DMOD, beta2 + (size_t)l * DMOD, out);
        else
            add_ln_kernel<true><<<ROWS, 256>>>(h, ff2,
                g2 + (size_t)l * DMOD, beta2 + (size_t)l * DMOD, h);
    }
}

// round 13
// speedup vs baseline: 1.8793x; 1.1202x over previous
#include <cuda_runtime.h>
#include <math.h>
#include <stdint.h>

#define NB   4
#define TT   1024
#define HH   8
#define DD   64
#define DMOD 512
#define DFFV 1024
#define NLAY 6
#define ROWS (NB * TT)   // 4096
#define NH   (NB * HH)   // 32

#define QSCALE (0.125f * 1.4426950408889634f)

// ---------------- scratch (static device globals; no allocation) -------------
__device__ float g_h   [ROWS * DMOD];
__device__ float g_htf [ROWS * DMOD];
__device__ float g_qkv [ROWS * 3 * DMOD];
__device__ float g_att [ROWS * DMOD];
__device__ float g_ff1 [ROWS * DFFV];
__device__ float g_ff2 [ROWS * DMOD];
__device__ float g_q   [NH * TT * DD];
__device__ float g_kb  [NH * TT * DD];   // tf32-rounded K (single-rounded)
__device__ float g_vb  [NH * TT * DD];   // tf32-rounded V (single-rounded)
// tf32-pre-rounded weights
__device__ float g_wqkv[NLAY * DMOD * 3 * DMOD];
__device__ float g_wff [NLAY * DMOD * DFFV];
__device__ float g_wo  [NLAY * DFFV * DMOD];

// ---------------- common PTX helpers -------------------------------------------
__device__ __forceinline__ uint32_t f2tf(float f)
{
    uint32_t r;
    asm("cvt.rna.tf32.f32 %0, %1;" : "=r"(r) : "f"(f));
    return r;
}
__device__ __forceinline__ float f2tff(float f) { return __uint_as_float(f2tf(f)); }
__device__ __forceinline__ void tfsplit(float x, uint32_t& big, uint32_t& small)
{
    big   = f2tf(x);
    small = f2tf(x - __uint_as_float(big));
}
__device__ __forceinline__ void mma_tf32(float* c, const uint32_t* a, uint32_t b0, uint32_t b1)
{
    asm volatile(
        "mma.sync.aligned.m16n8k8.row.col.f32.tf32.tf32.f32 "
        "{%0,%1,%2,%3}, {%4,%5,%6,%7}, {%8,%9}, {%0,%1,%2,%3};"
        : "+f"(c[0]), "+f"(c[1]), "+f"(c[2]), "+f"(c[3])
        : "r"(a[0]), "r"(a[1]), "r"(a[2]), "r"(a[3]), "r"(b0), "r"(b1));
}
__device__ __forceinline__ void cp_async16(uint32_t saddr, const void* gaddr)
{
    asm volatile("cp.async.cg.shared.global [%0], [%1], 16;" :: "r"(saddr), "l"(gaddr));
}
__device__ __forceinline__ void cp_commit() { asm volatile("cp.async.commit_group;"); }
template<int N> __device__ __forceinline__ void cp_wait() {
    asm volatile("cp.async.wait_group %0;" :: "n"(N));
}
__device__ __forceinline__ float ex2(float x)
{
    float r;
    asm("ex2.approx.ftz.f32 %0, %1;" : "=f"(r) : "f"(x));
    return r;
}

// ---------------- weight pre-rounding prepass ----------------------------------
__global__ __launch_bounds__(256)
void round_copy_kernel(const float* __restrict__ src, float* __restrict__ dst, int n4)
{
    int i = blockIdx.x * blockDim.x + threadIdx.x;
    for (; i < n4; i += gridDim.x * blockDim.x) {
        float4 v = ((const float4*)src)[i];
        v.x = f2tff(v.x); v.y = f2tff(v.y); v.z = f2tff(v.z); v.w = f2tff(v.w);
        ((float4*)dst)[i] = v;
    }
}

// ---------------- embedding + positional encoding (all-fp32, MUFU) -------------
__global__ void embed_kernel(const int* __restrict__ x, const float* __restrict__ emb)
{
    int row = blockIdx.x;
    int t   = row & (TT - 1);
    int tok = x[row];
    const float* e = emb + (size_t)tok * DMOD;
    float tf = (float)t;
    for (int i = threadIdx.x; i < DMOD; i += blockDim.x) {
        float expo = -2.0f * (float)(i >> 1) * (1.0f / (float)DMOD);
        float rate = powf(10000.0f, expo);
        float ang  = tf * rate;
        float s, c;
        sincosf(ang, &s, &c);
        float p   = (i & 1) ? c : s;
        float val = e[i] * 22.62741699796952f + p;  // sqrt(512)
        g_h  [(size_t)row * DMOD + i] = val;
        g_htf[(size_t)row * DMOD + i] = f2tff(val);
    }
}

// ---------------- TF32 GEMM — cvt-free, 3-stage cp.async pipeline --------------
#define LDA 20u
#define LDB 136u
#define STG 3

template<int MODE>
__global__ __launch_bounds__(256)
void gemm_tf32(const float* __restrict__ A, const float* __restrict__ B,
               const float* __restrict__ bias, float* __restrict__ C,
               int M, int N, int K)
{
    __shared__ float As[STG][128 * LDA];
    __shared__ float Bs[STG][16 * LDB];

    const int tid  = threadIdx.x;
    const int bm   = blockIdx.y * 128;
    const int bn   = blockIdx.x * 128;

    const int am = tid >> 1, ak = (tid & 1) * 8;
    const int bk = tid >> 4, bcol = (tid & 15) * 8;

    const uint32_t sA = (uint32_t)__cvta_generic_to_shared(&As[0][0]);
    const uint32_t sB = (uint32_t)__cvta_generic_to_shared(&Bs[0][0]);

    const int warp = tid >> 5, lane = tid & 31;
    const int gid  = lane >> 2, tig = lane & 3;
    const int wm   = (warp & 3) * 32;
    const int wn   = (warp >> 2) * 64;

    float c[2][8][4];
#pragma unroll
    for (int mt = 0; mt < 2; ++mt)
#pragma unroll
        for (int nt = 0; nt < 8; ++nt)
#pragma unroll
            for (int j = 0; j < 4; ++j) c[mt][nt][j] = 0.f;

    const int nIter = K >> 4;

    auto issue = [&](int t) {
        const int buf = t % STG;
        const float* Ap = A + (size_t)(bm + am) * K + t * 16 + ak;
        const float* Bp = B + (size_t)(t * 16 + bk) * N + bn + bcol;
        uint32_t sa = sA + (buf * 128 * LDA + am * LDA + ak) * 4;
        uint32_t sb = sB + (buf * 16 * LDB + bk * LDB + bcol) * 4;
        cp_async16(sa,      Ap);
        cp_async16(sa + 16, Ap + 4);
        cp_async16(sb,      Bp);
        cp_async16(sb + 16, Bp + 4);
        cp_commit();
    };

    issue(0);
    if (nIter > 1) issue(1);

    for (int it = 0; it < nIter; ++it) {
        if (it + 1 < nIter) cp_wait<1>(); else cp_wait<0>();
        __syncthreads();
        if (it + 2 < nIter) issue(it + 2);

        const float* Ac = As[it % STG];
        const float* Bc = Bs[it % STG];
#pragma unroll
        for (int ks = 0; ks < 2; ++ks) {
            const int kb = ks * 8;
            uint32_t a[2][4], b[8][2];
#pragma unroll
            for (int mt = 0; mt < 2; ++mt) {
                const int r = wm + mt * 16 + gid;
                a[mt][0] = __float_as_uint(Ac[(uint32_t)r * LDA + kb + tig]);
                a[mt][1] = __float_as_uint(Ac[(uint32_t)(r + 8) * LDA + kb + tig]);
                a[mt][2] = __float_as_uint(Ac[(uint32_t)r * LDA + kb + tig + 4]);
                a[mt][3] = __float_as_uint(Ac[(uint32_t)(r + 8) * LDA + kb + tig + 4]);
            }
#pragma unroll
            for (int nt = 0; nt < 8; ++nt) {
                const int col = wn + nt * 8 + gid;
                b[nt][0] = __float_as_uint(Bc[(uint32_t)(kb + tig) * LDB + col]);
                b[nt][1] = __float_as_uint(Bc[(uint32_t)(kb + tig + 4) * LDB + col]);
            }
#pragma unroll
            for (int mt = 0; mt < 2; ++mt)
#pragma unroll
                for (int nt = 0; nt < 8; ++nt)
                    mma_tf32(c[mt][nt], a[mt], b[nt][0], b[nt][1]);
        }
    }

#pragma unroll
    for (int mt = 0; mt < 2; ++mt) {
        const int row0 = bm + wm + mt * 16 + gid;
#pragma unroll
        for (int nt = 0; nt < 8; ++nt) {
            const int coln = bn + wn + nt * 8 + 2 * tig;
            const float2 bv = *(const float2*)(bias + coln);
            float2 v0, v1;
            v0.x = c[mt][nt][0] + bv.x; v0.y = c[mt][nt][1] + bv.y;
            v1.x = c[mt][nt][2] + bv.x; v1.y = c[mt][nt][3] + bv.y;
            if (MODE == 1) {
                v0.x = f2tff(fmaxf(v0.x, 0.f)); v0.y = f2tff(fmaxf(v0.y, 0.f));
                v1.x = f2tff(fmaxf(v1.x, 0.f)); v1.y = f2tff(fmaxf(v1.y, 0.f));
            }
            *(float2*)(C + (size_t)row0 * N + coln)       = v0;
            *(float2*)(C + (size_t)(row0 + 8) * N + coln) = v1;
        }
    }
}

// ---------------- split qkv: q (fp32 scaled), K and V tf32-rounded -------------
__global__ __launch_bounds__(384)
void split_qkv_kernel()
{
    int row = blockIdx.x;
    int n   = row >> 10;
    int t   = row & (TT - 1);
    int c0  = threadIdx.x * 4;
    float4 v = *(const float4*)(g_qkv + (size_t)row * 1536 + c0);
    float vals[4] = {v.x, v.y, v.z, v.w};
#pragma unroll
    for (int u = 0; u < 4; ++u) {
        int c = c0 + u;
        int h = c / 192;
        int r = c - h * 192;
        int d = r / 3;
        int j = r - d * 3;
        size_t dst = ((size_t)(n * HH + h) * TT + t) * DD + d;
        if (j == 0)      g_q [dst] = vals[u] * QSCALE;
        else if (j == 1) g_kb[dst] = f2tff(vals[u]);
        else             g_vb[dst] = f2tff(vals[u]);
    }
}

// ---------------- FlashAttention-2: q & P compensated, K & V single ------------
// smem 45KB -> 3 blocks/SM. QK: 2 mma/group. PV: 2 mma/group.
#define KT   32
#define LDK  68
#define LDV  72
#define LDP  36
#define KB_T (KT * LDK)                           // 2176
#define VB_T (KT * LDV)                           // 2304
#define OFF_KB 0
#define OFF_VB (2 * KB_T)                         // 4352
#define OFF_P  (OFF_VB + 2 * VB_T)                // 8960
#define ATTN_SMEM_FLOATS (OFF_P + 4 * 16 * LDP)   // 11264
#define ATTN_SMEM_BYTES  (ATTN_SMEM_FLOATS * 4)   // 45056

__global__ __launch_bounds__(128)
void attn_mma_kernel()
{
    extern __shared__ float sm[];

    const int tid  = threadIdx.x;
    const int warp = tid >> 5, lane = tid & 31;
    const int gid  = lane >> 2, tig = lane & 3;
    const int qt   = gridDim.x - 1 - blockIdx.x;   // heavy q-tiles first
    const int nh   = blockIdx.y;
    const int row0 = qt * 64 + warp * 16;

    const float* kbp = g_kb + (size_t)nh * TT * DD;
    const float* vbp = g_vb + (size_t)nh * TT * DD;

    const uint32_t sbase = (uint32_t)__cvta_generic_to_shared(sm);

    uint32_t qfb[8][4], qfs[8][4];
    {
        const float* qp = g_q + ((size_t)nh * TT + row0) * DD;
#pragma unroll
        for (int kt = 0; kt < 8; ++kt) {
            tfsplit(qp[gid * DD + kt * 8 + tig],           qfb[kt][0], qfs[kt][0]);
            tfsplit(qp[(gid + 8) * DD + kt * 8 + tig],     qfb[kt][1], qfs[kt][1]);
            tfsplit(qp[gid * DD + kt * 8 + tig + 4],       qfb[kt][2], qfs[kt][2]);
            tfsplit(qp[(gid + 8) * DD + kt * 8 + tig + 4], qfb[kt][3], qfs[kt][3]);
        }
    }

    float o[8][4];
#pragma unroll
    for (int nt = 0; nt < 8; ++nt)
#pragma unroll
        for (int j = 0; j < 4; ++j) o[nt][j] = 0.f;
    float m0 = -INFINITY, m1 = -INFINITY, l0 = 0.f, l1 = 0.f;

    const int ntiles = 2 * qt + 2;

    // 2 arrays x 512 float4 per tile; 128 threads -> 8 cp.async/thread
    auto prefetch = [&](int t) {
        const size_t gb = (size_t)t * KT * DD;
        const int buf = t & 1;
        const uint32_t kbOff = OFF_KB + buf * KB_T;
        const uint32_t vbOff = OFF_VB + buf * VB_T;
#pragma unroll
        for (int i = 0; i < 4; ++i) {
            int idx = i * 128 + tid;
            int r   = idx >> 4;
            int c4  = (idx & 15) * 4;
            const size_t g = gb + r * DD + c4;
            cp_async16(sbase + (kbOff + r * LDK + c4) * 4, kbp + g);
            cp_async16(sbase + (vbOff + r * LDV + c4) * 4, vbp + g);
        }
        cp_commit();
    };

    prefetch(0);

    float* Pw = sm + OFF_P + warp * 16 * LDP;

#pragma unroll 1
    for (int kt_i = 0; kt_i < ntiles; ++kt_i) {
        cp_wait<0>();
        __syncthreads();
        if (kt_i + 1 < ntiles) prefetch(kt_i + 1);

        const int buf = kt_i & 1;
        const float* Kb = sm + OFF_KB + buf * KB_T;
        const float* Vb = sm + OFF_VB + buf * VB_T;

        // ---- S = (q_big + q_small) @ Kb^T : 2 mma per group ----
        float cs[4][4];
#pragma unroll
        for (int nt = 0; nt < 4; ++nt) {
#pragma unroll
            for (int j = 0; j < 4; ++j) cs[nt][j] = 0.f;
#pragma unroll
            for (int dk = 0; dk < 8; ++dk) {
                const int r0 = (nt * 8 + gid) * LDK + dk * 8 + tig;
                uint32_t bb0 = __float_as_uint(Kb[r0]);
                uint32_t bb1 = __float_as_uint(Kb[r0 + 4]);
                mma_tf32(cs[nt], qfb[dk], bb0, bb1);
                mma_tf32(cs[nt], qfs[dk], bb0, bb1);
            }
        }

        if (kt_i >= 2 * qt) {
            const int rl0 = row0 + gid;
            const int rl1 = rl0 + 8;
#pragma unroll
            for (int nt = 0; nt < 4; ++nt) {
                int j = kt_i * KT + nt * 8 + 2 * tig;
                if (j     > rl0) cs[nt][0] = -INFINITY;
                if (j + 1 > rl0) cs[nt][1] = -INFINITY;
                if (j     > rl1) cs[nt][2] = -INFINITY;
                if (j + 1 > rl1) cs[nt][3] = -INFINITY;
            }
        }

        float mx0 = -INFINITY, mx1 = -INFINITY;
#pragma unroll
        for (int nt = 0; nt < 4; ++nt) {
            mx0 = fmaxf(mx0, fmaxf(cs[nt][0], cs[nt][1]));
            mx1 = fmaxf(mx1, fmaxf(cs[nt][2], cs[nt][3]));
        }
        mx0 = fmaxf(mx0, __shfl_xor_sync(0xffffffffu, mx0, 1));
        mx0 = fmaxf(mx0, __shfl_xor_sync(0xffffffffu, mx0, 2));
        mx1 = fmaxf(mx1, __shfl_xor_sync(0xffffffffu, mx1, 1));
        mx1 = fmaxf(mx1, __shfl_xor_sync(0xffffffffu, mx1, 2));

        const float mn0 = fmaxf(m0, mx0);
        const float mn1 = fmaxf(m1, mx1);
        const float cor0 = ex2(m0 - mn0);
        const float cor1 = ex2(m1 - mn1);
        l0 *= cor0; l1 *= cor1;
#pragma unroll
        for (int nt = 0; nt < 8; ++nt) {
            o[nt][0] *= cor0; o[nt][1] *= cor0;
            o[nt][2] *= cor1; o[nt][3] *= cor1;
        }

        float rs0 = 0.f, rs1 = 0.f;
#pragma unroll
        for (int nt = 0; nt < 4; ++nt) {
            float p0 = ex2(cs[nt][0] - mn0);
            float p1 = ex2(cs[nt][1] - mn0);
            float p2 = ex2(cs[nt][2] - mn1);
            float p3 = ex2(cs[nt][3] - mn1);
            rs0 += p0 + p1; rs1 += p2 + p3;
            int col = nt * 8 + 2 * tig;
            *(float2*)(Pw + gid * LDP + col)       = make_float2(p0, p1);
            *(float2*)(Pw + (gid + 8) * LDP + col) = make_float2(p2, p3);
        }
        rs0 += __shfl_xor_sync(0xffffffffu, rs0, 1);
        rs0 += __shfl_xor_sync(0xffffffffu, rs0, 2);
        rs1 += __shfl_xor_sync(0xffffffffu, rs1, 1);
        rs1 += __shfl_xor_sync(0xffffffffu, rs1, 2);
        l0 += rs0; l1 += rs1;
        m0 = mn0; m1 = mn1;

        __syncwarp();

        // ---- O += P @ V: P compensated (reg split), V single: 2 mma/group ----
#pragma unroll
        for (int kk = 0; kk < 4; ++kk) {
            uint32_t ab[4], as_[4];
            tfsplit(Pw[gid * LDP + kk * 8 + tig],           ab[0], as_[0]);
            tfsplit(Pw[(gid + 8) * LDP + kk * 8 + tig],     ab[1], as_[1]);
            tfsplit(Pw[gid * LDP + kk * 8 + tig + 4],       ab[2], as_[2]);
            tfsplit(Pw[(gid + 8) * LDP + kk * 8 + tig + 4], ab[3], as_[3]);
#pragma unroll
            for (int nt = 0; nt < 8; ++nt) {
                const int r0 = (kk * 8 + tig) * LDV + nt * 8 + gid;
                const int r1 = (kk * 8 + tig + 4) * LDV + nt * 8 + gid;
                uint32_t bb0 = __float_as_uint(Vb[r0]);
                uint32_t bb1 = __float_as_uint(Vb[r1]);
                mma_tf32(o[nt], ab,  bb0, bb1);
                mma_tf32(o[nt], as_, bb0, bb1);
            }
        }
    }

    const float i0 = 1.f / l0;
    const float i1 = 1.f / l1;
    const int n = nh >> 3, hh = nh & 7;
    const int rg0 = row0 + gid;
#pragma unroll
    for (int nt = 0; nt < 8; ++nt) {
        int col = hh * DD + nt * 8 + 2 * tig;
        *(float2*)(g_att + (size_t)(n * TT + rg0) * DMOD + col) =
            make_float2(o[nt][0] * i0, o[nt][1] * i0);
        *(float2*)(g_att + (size_t)(n * TT + rg0 + 8) * DMOD + col) =
            make_float2(o[nt][2] * i1, o[nt][3] * i1);
    }
}

// ---------------- fused residual add + LayerNorm -------------------------------
template<bool WRITE_TF>
__global__ __launch_bounds__(256)
void add_ln_kernel(const float* __restrict__ a, const float* __restrict__ b,
                   const float* __restrict__ gamma, const float* __restrict__ beta,
                   float* __restrict__ out)
{
    int row = blockIdx.x;
    int tid = threadIdx.x;
    const float* ar = a + (size_t)row * DMOD;
    const float* br = b + (size_t)row * DMOD;

    float x0 = ar[tid]       + br[tid];
    float x1 = ar[tid + 256] + br[tid + 256];

    float sum = x0 + x1;
    float sq  = x0 * x0 + x1 * x1;
#pragma unroll
    for (int off = 16; off; off >>= 1) {
        sum += __shfl_xor_sync(0xffffffffu, sum, off);
        sq  += __shfl_xor_sync(0xffffffffu, sq,  off);
    }
    __shared__ float s1[8], s2[8];
    int wid = tid >> 5, lane = tid & 31;
    if (lane == 0) { s1[wid] = sum; s2[wid] = sq; }
    __syncthreads();
    float S = 0.f, Q = 0.f;
#pragma unroll
    for (int i = 0; i < 8; ++i) { S += s1[i]; Q += s2[i]; }

    float mean = S * (1.f / DMOD);
    float var  = Q * (1.f / DMOD) - mean * mean;
    float rstd = 1.f / sqrtf(var + 1e-3f);

    float y0 = gamma[tid]       * (x0 - mean) * rstd + beta[tid];
    float y1 = gamma[tid + 256] * (x1 - mean) * rstd + beta[tid + 256];
    out[(size_t)row * DMOD + tid]       = y0;
    out[(size_t)row * DMOD + tid + 256] = y1;
    if (WRITE_TF) {
        g_htf[(size_t)row * DMOD + tid]       = f2tff(y0);
        g_htf[(size_t)row * DMOD + tid + 256] = f2tff(y1);
    }
}

// ---------------- launch ------------------------------------------------------
extern "C" void kernel_launch(void* const* d_in, const int* in_sizes, int n_in,
                              void* d_out, int out_size)
{
    const int*   x     = (const int*)  d_in[0];
    const float* emb   = (const float*)d_in[1];
    const float* Wqkv  = (const float*)d_in[2];
    const float* bqkv  = (const float*)d_in[3];
    const float* Wff   = (const float*)d_in[4];
    const float* bff   = (const float*)d_in[5];
    const float* Wo    = (const float*)d_in[6];
    const float* bo    = (const float*)d_in[7];
    const float* g1    = (const float*)d_in[8];
    const float* beta1 = (const float*)d_in[9];
    const float* g2    = (const float*)d_in[10];
    const float* beta2 = (const float*)d_in[11];
    float* out = (float*)d_out;

    float *h, *qkv, *att, *ff1, *ff2, *htf, *wqkv, *wff, *wo;
    cudaGetSymbolAddress((void**)&h,    g_h);
    cudaGetSymbolAddress((void**)&htf,  g_htf);
    cudaGetSymbolAddress((void**)&qkv,  g_qkv);
    cudaGetSymbolAddress((void**)&att,  g_att);
    cudaGetSymbolAddress((void**)&ff1,  g_ff1);
    cudaGetSymbolAddress((void**)&ff2,  g_ff2);
    cudaGetSymbolAddress((void**)&wqkv, g_wqkv);
    cudaGetSymbolAddress((void**)&wff,  g_wff);
    cudaGetSymbolAddress((void**)&wo,   g_wo);

    cudaFuncSetAttribute(attn_mma_kernel,
                         cudaFuncAttributeMaxDynamicSharedMemorySize, ATTN_SMEM_BYTES);

    round_copy_kernel<<<592, 256>>>(Wqkv, wqkv, NLAY * DMOD * 3 * DMOD / 4);
    round_copy_kernel<<<592, 256>>>(Wff,  wff,  NLAY * DMOD * DFFV / 4);
    round_copy_kernel<<<592, 256>>>(Wo,   wo,   NLAY * DFFV * DMOD / 4);

    embed_kernel<<<ROWS, 128>>>(x, emb);

    for (int l = 0; l < NLAY; ++l) {
        gemm_tf32<0><<<dim3(1536 / 128, ROWS / 128), 256>>>(
            htf, wqkv + (size_t)l * DMOD * 3 * DMOD, bqkv + (size_t)l * 3 * DMOD,
            qkv, ROWS, 3 * DMOD, DMOD);

        split_qkv_kernel<<<ROWS, 384>>>();

        attn_mma_kernel<<<dim3(TT / 64, NH), 128, ATTN_SMEM_BYTES>>>();

        add_ln_kernel<true><<<ROWS, 256>>>(h, att,
            g1 + (size_t)l * DMOD, beta1 + (size_t)l * DMOD, h);

        gemm_tf32<1><<<dim3(DFFV / 128, ROWS / 128), 256>>>(
            htf, wff + (size_t)l * DMOD * DFFV, bff + (size_t)l * DFFV,
            ff1, ROWS, DFFV, DMOD);

        gemm_tf32<0><<<dim3(DMOD / 128, ROWS / 128), 256>>>(
            ff1, wo + (size_t)l * DFFV * DMOD, bo + (size_t)l * DMOD,
            ff2, ROWS, DMOD, DFFV);

        if (l == NLAY - 1)
            add_ln_kernel<false><<<ROWS, 256>>>(h, ff2,
                g2 + (size_t)l * DMOD, beta2 + (size_t)l * DMOD, out);
        else
            add_ln_kernel<true><<<ROWS, 256>>>(h, ff2,
                g2 + (size_t)l * DMOD, beta2 + (size_t)l * DMOD, h);
    }
}

// round 14
// speedup vs baseline: 2.5076x; 1.3344x over previous
#include <cuda_runtime.h>
#include <cuda_fp16.h>
#include <math.h>
#include <stdint.h>

#define NB   4
#define TT   1024
#define HH   8
#define DD   64
#define DMOD 512
#define DFFV 1024
#define NLAY 6
#define ROWS (NB * TT)   // 4096
#define NH   (NB * HH)   // 32

#define QSCALE (0.125f * 1.4426950408889634f)

// ---------------- scratch (static device globals; no allocation) -------------
__device__ float  g_h   [ROWS * DMOD];
__device__ __half g_hh  [ROWS * DMOD];           // fp16 copy of g_h (GEMM A)
__device__ float  g_qkv [ROWS * 3 * DMOD];
__device__ float  g_att [ROWS * DMOD];
__device__ __half g_ff1 [ROWS * DFFV];           // fp16 relu output (FF2 A)
__device__ float  g_ff2 [ROWS * DMOD];
__device__ float  g_q   [NH * TT * DD];
__device__ float  g_kb  [NH * TT * DD];          // tf32-rounded K
__device__ float  g_vb  [NH * TT * DD];          // tf32-rounded V
// fp16 weights, TRANSPOSED to [N][K]
__device__ __half g_wqkv[NLAY * DMOD * 3 * DMOD];
__device__ __half g_wff [NLAY * DMOD * DFFV];
__device__ __half g_wo  [NLAY * DFFV * DMOD];

// ---------------- common PTX helpers -------------------------------------------
__device__ __forceinline__ uint32_t f2tf(float f)
{
    uint32_t r;
    asm("cvt.rna.tf32.f32 %0, %1;" : "=r"(r) : "f"(f));
    return r;
}
__device__ __forceinline__ float f2tff(float f) { return __uint_as_float(f2tf(f)); }
__device__ __forceinline__ void tfsplit(float x, uint32_t& big, uint32_t& small)
{
    big   = f2tf(x);
    small = f2tf(x - __uint_as_float(big));
}
__device__ __forceinline__ void mma_tf32(float* c, const uint32_t* a, uint32_t b0, uint32_t b1)
{
    asm volatile(
        "mma.sync.aligned.m16n8k8.row.col.f32.tf32.tf32.f32 "
        "{%0,%1,%2,%3}, {%4,%5,%6,%7}, {%8,%9}, {%0,%1,%2,%3};"
        : "+f"(c[0]), "+f"(c[1]), "+f"(c[2]), "+f"(c[3])
        : "r"(a[0]), "r"(a[1]), "r"(a[2]), "r"(a[3]), "r"(b0), "r"(b1));
}
__device__ __forceinline__ void mma_f16(float* c, const uint32_t* a, uint32_t b0, uint32_t b1)
{
    asm volatile(
        "mma.sync.aligned.m16n8k16.row.col.f32.f16.f16.f32 "
        "{%0,%1,%2,%3}, {%4,%5,%6,%7}, {%8,%9}, {%0,%1,%2,%3};"
        : "+f"(c[0]), "+f"(c[1]), "+f"(c[2]), "+f"(c[3])
        : "r"(a[0]), "r"(a[1]), "r"(a[2]), "r"(a[3]), "r"(b0), "r"(b1));
}
__device__ __forceinline__ void cp_async16(uint32_t saddr, const void* gaddr)
{
    asm volatile("cp.async.cg.shared.global [%0], [%1], 16;" :: "r"(saddr), "l"(gaddr));
}
__device__ __forceinline__ void cp_commit() { asm volatile("cp.async.commit_group;"); }
template<int N> __device__ __forceinline__ void cp_wait() {
    asm volatile("cp.async.wait_group %0;" :: "n"(N));
}
__device__ __forceinline__ float ex2(float x)
{
    float r;
    asm("ex2.approx.ftz.f32 %0, %1;" : "=f"(r) : "f"(x));
    return r;
}

// ---------------- weight transpose + fp16 convert prepass ----------------------
// src: [L][K][N] fp32 -> dst: [L][N][K] fp16. grid (N/32, K/32, L), block (32,8).
__global__ __launch_bounds__(256)
void transpose_w_kernel(const float* __restrict__ src, __half* __restrict__ dst,
                        int K, int N)
{
    __shared__ __half tile[32][33];
    const size_t lo = (size_t)blockIdx.z * K * N;
    const int k0 = blockIdx.y * 32, n0 = blockIdx.x * 32;
#pragma unroll
    for (int i = threadIdx.y; i < 32; i += 8)
        tile[i][threadIdx.x] = __float2half(src[lo + (size_t)(k0 + i) * N + n0 + threadIdx.x]);
    __syncthreads();
#pragma unroll
    for (int i = threadIdx.y; i < 32; i += 8)
        dst[lo + (size_t)(n0 + i) * K + k0 + threadIdx.x] = tile[threadIdx.x][i];
}

// ---------------- embedding + positional encoding (all-fp32, MUFU) -------------
__global__ void embed_kernel(const int* __restrict__ x, const float* __restrict__ emb)
{
    int row = blockIdx.x;
    int t   = row & (TT - 1);
    int tok = x[row];
    const float* e = emb + (size_t)tok * DMOD;
    float tf = (float)t;
    for (int i = threadIdx.x; i < DMOD; i += blockDim.x) {
        float expo = -2.0f * (float)(i >> 1) * (1.0f / (float)DMOD);
        float rate = powf(10000.0f, expo);
        float ang  = tf * rate;
        float s, c;
        sincosf(ang, &s, &c);
        float p   = (i & 1) ? c : s;
        float val = e[i] * 22.62741699796952f + p;  // sqrt(512)
        g_h [(size_t)row * DMOD + i] = val;
        g_hh[(size_t)row * DMOD + i] = __float2half(val);
    }
}

// ---------------- FP16 GEMM — m16n8k16, 3-stage cp.async pipeline --------------
// A: [M][K] half.  B: [N][K] half (pre-transposed).  bias fp32.
// MODE 0: fp32 out.  MODE 1: relu -> fp16 out.
#define LDAH 40
#define STG  3

template<int MODE>
__global__ __launch_bounds__(256)
void gemm_f16(const __half* __restrict__ A, const __half* __restrict__ B,
              const float* __restrict__ bias, void* __restrict__ Cv,
              int M, int N, int K)
{
    __shared__ __half As[STG][128 * LDAH];
    __shared__ __half Bs[STG][128 * LDAH];

    const int tid  = threadIdx.x;
    const int bm   = blockIdx.y * 128;
    const int bn   = blockIdx.x * 128;

    // loads: tile 128 rows x 32 halves (64B = 4 chunks of 16B); 512 chunks, 2/thread
    const int r0 = tid >> 1;              // chunk row for c = 2*tid
    const int o0 = (tid & 1) * 16;        // halves offset (0 or 16) — 2 chunks each

    const uint32_t sA = (uint32_t)__cvta_generic_to_shared(&As[0][0]);
    const uint32_t sB = (uint32_t)__cvta_generic_to_shared(&Bs[0][0]);

    const int warp = tid >> 5, lane = tid & 31;
    const int gid  = lane >> 2, tig = lane & 3;
    const int wm   = (warp & 3) * 32;
    const int wn   = (warp >> 2) * 64;

    float c[2][8][4];
#pragma unroll
    for (int mt = 0; mt < 2; ++mt)
#pragma unroll
        for (int nt = 0; nt < 8; ++nt)
#pragma unroll
            for (int j = 0; j < 4; ++j) c[mt][nt][j] = 0.f;

    const int nIter = K >> 5;             // BK = 32

    auto issue = [&](int t) {
        const int buf = t % STG;
        const __half* Ap = A + (size_t)(bm + r0) * K + t * 32 + o0;
        const __half* Bp = B + (size_t)(bn + r0) * K + t * 32 + o0;
        uint32_t sa = sA + (buf * 128 * LDAH + r0 * LDAH + o0) * 2;
        uint32_t sb = sB + (buf * 128 * LDAH + r0 * LDAH + o0) * 2;
        cp_async16(sa,      Ap);
        cp_async16(sa + 16, Ap + 8);
        cp_async16(sb,      Bp);
        cp_async16(sb + 16, Bp + 8);
        cp_commit();
    };

    issue(0);
    if (nIter > 1) issue(1);

    for (int it = 0; it < nIter; ++it) {
        if (it + 1 < nIter) cp_wait<1>(); else cp_wait<0>();
        __syncthreads();
        if (it + 2 < nIter) issue(it + 2);

        const __half* Ac = As[it % STG];
        const __half* Bc = Bs[it % STG];
#pragma unroll
        for (int ks = 0; ks < 2; ++ks) {
            const int kb = ks * 16;
            uint32_t a[2][4], b[8][2];
#pragma unroll
            for (int mt = 0; mt < 2; ++mt) {
                const int r = wm + mt * 16 + gid;
                a[mt][0] = *(const uint32_t*)&Ac[(uint32_t)r * LDAH + kb + 2 * tig];
                a[mt][1] = *(const uint32_t*)&Ac[(uint32_t)(r + 8) * LDAH + kb + 2 * tig];
                a[mt][2] = *(const uint32_t*)&Ac[(uint32_t)r * LDAH + kb + 2 * tig + 8];
                a[mt][3] = *(const uint32_t*)&Ac[(uint32_t)(r + 8) * LDAH + kb + 2 * tig + 8];
            }
#pragma unroll
            for (int nt = 0; nt < 8; ++nt) {
                const int col = wn + nt * 8 + gid;
                b[nt][0] = *(const uint32_t*)&Bc[(uint32_t)col * LDAH + kb + 2 * tig];
                b[nt][1] = *(const uint32_t*)&Bc[(uint32_t)col * LDAH + kb + 2 * tig + 8];
            }
#pragma unroll
            for (int mt = 0; mt < 2; ++mt)
#pragma unroll
                for (int nt = 0; nt < 8; ++nt)
                    mma_f16(c[mt][nt], a[mt], b[nt][0], b[nt][1]);
        }
    }

    // ---- epilogue ----
#pragma unroll
    for (int mt = 0; mt < 2; ++mt) {
        const int row0 = bm + wm + mt * 16 + gid;
#pragma unroll
        for (int nt = 0; nt < 8; ++nt) {
            const int coln = bn + wn + nt * 8 + 2 * tig;
            const float2 bv = *(const float2*)(bias + coln);
            float2 v0, v1;
            v0.x = c[mt][nt][0] + bv.x; v0.y = c[mt][nt][1] + bv.y;
            v1.x = c[mt][nt][2] + bv.x; v1.y = c[mt][nt][3] + bv.y;
            if (MODE == 1) {
                __half* C = (__half*)Cv;
                __half2 h0 = __floats2half2_rn(fmaxf(v0.x, 0.f), fmaxf(v0.y, 0.f));
                __half2 h1 = __floats2half2_rn(fmaxf(v1.x, 0.f), fmaxf(v1.y, 0.f));
                *(__half2*)(C + (size_t)row0 * N + coln)       = h0;
                *(__half2*)(C + (size_t)(row0 + 8) * N + coln) = h1;
            } else {
                float* C = (float*)Cv;
                *(float2*)(C + (size_t)row0 * N + coln)       = v0;
                *(float2*)(C + (size_t)(row0 + 8) * N + coln) = v1;
            }
        }
    }
}

// ---------------- split qkv: q (fp32 scaled), K and V tf32-rounded -------------
__global__ __launch_bounds__(384)
void split_qkv_kernel()
{
    int row = blockIdx.x;
    int n   = row >> 10;
    int t   = row & (TT - 1);
    int c0  = threadIdx.x * 4;
    float4 v = *(const float4*)(g_qkv + (size_t)row * 1536 + c0);
    float vals[4] = {v.x, v.y, v.z, v.w};
#pragma unroll
    for (int u = 0; u < 4; ++u) {
        int c = c0 + u;
        int h = c / 192;
        int r = c - h * 192;
        int d = r / 3;
        int j = r - d * 3;
        size_t dst = ((size_t)(n * HH + h) * TT + t) * DD + d;
        if (j == 0)      g_q [dst] = vals[u] * QSCALE;
        else if (j == 1) g_kb[dst] = f2tff(vals[u]);
        else             g_vb[dst] = f2tff(vals[u]);
    }
}

// ---------------- FlashAttention-2: q & P compensated, K & V single (R13) ------
#define KT   32
#define LDK  68
#define LDV  72
#define LDP  36
#define KB_T (KT * LDK)
#define VB_T (KT * LDV)
#define OFF_KB 0
#define OFF_VB (2 * KB_T)
#define OFF_P  (OFF_VB + 2 * VB_T)
#define ATTN_SMEM_FLOATS (OFF_P + 4 * 16 * LDP)
#define ATTN_SMEM_BYTES  (ATTN_SMEM_FLOATS * 4)   // 45056

__global__ __launch_bounds__(128)
void attn_mma_kernel()
{
    extern __shared__ float sm[];

    const int tid  = threadIdx.x;
    const int warp = tid >> 5, lane = tid & 31;
    const int gid  = lane >> 2, tig = lane & 3;
    const int qt   = gridDim.x - 1 - blockIdx.x;
    const int nh   = blockIdx.y;
    const int row0 = qt * 64 + warp * 16;

    const float* kbp = g_kb + (size_t)nh * TT * DD;
    const float* vbp = g_vb + (size_t)nh * TT * DD;

    const uint32_t sbase = (uint32_t)__cvta_generic_to_shared(sm);

    uint32_t qfb[8][4], qfs[8][4];
    {
        const float* qp = g_q + ((size_t)nh * TT + row0) * DD;
#pragma unroll
        for (int kt = 0; kt < 8; ++kt) {
            tfsplit(qp[gid * DD + kt * 8 + tig],           qfb[kt][0], qfs[kt][0]);
            tfsplit(qp[(gid + 8) * DD + kt * 8 + tig],     qfb[kt][1], qfs[kt][1]);
            tfsplit(qp[gid * DD + kt * 8 + tig + 4],       qfb[kt][2], qfs[kt][2]);
            tfsplit(qp[(gid + 8) * DD + kt * 8 + tig + 4], qfb[kt][3], qfs[kt][3]);
        }
    }

    float o[8][4];
#pragma unroll
    for (int nt = 0; nt < 8; ++nt)
#pragma unroll
        for (int j = 0; j < 4; ++j) o[nt][j] = 0.f;
    float m0 = -INFINITY, m1 = -INFINITY, l0 = 0.f, l1 = 0.f;

    const int ntiles = 2 * qt + 2;

    auto prefetch = [&](int t) {
        const size_t gb = (size_t)t * KT * DD;
        const int buf = t & 1;
        const uint32_t kbOff = OFF_KB + buf * KB_T;
        const uint32_t vbOff = OFF_VB + buf * VB_T;
#pragma unroll
        for (int i = 0; i < 4; ++i) {
            int idx = i * 128 + tid;
            int r   = idx >> 4;
            int c4  = (idx & 15) * 4;
            const size_t g = gb + r * DD + c4;
            cp_async16(sbase + (kbOff + r * LDK + c4) * 4, kbp + g);
            cp_async16(sbase + (vbOff + r * LDV + c4) * 4, vbp + g);
        }
        cp_commit();
    };

    prefetch(0);

    float* Pw = sm + OFF_P + warp * 16 * LDP;

#pragma unroll 1
    for (int kt_i = 0; kt_i < ntiles; ++kt_i) {
        cp_wait<0>();
        __syncthreads();
        if (kt_i + 1 < ntiles) prefetch(kt_i + 1);

        const int buf = kt_i & 1;
        const float* Kb = sm + OFF_KB + buf * KB_T;
        const float* Vb = sm + OFF_VB + buf * VB_T;

        float cs[4][4];
#pragma unroll
        for (int nt = 0; nt < 4; ++nt) {
#pragma unroll
            for (int j = 0; j < 4; ++j) cs[nt][j] = 0.f;
#pragma unroll
            for (int dk = 0; dk < 8; ++dk) {
                const int r0 = (nt * 8 + gid) * LDK + dk * 8 + tig;
                uint32_t bb0 = __float_as_uint(Kb[r0]);
                uint32_t bb1 = __float_as_uint(Kb[r0 + 4]);
                mma_tf32(cs[nt], qfb[dk], bb0, bb1);
                mma_tf32(cs[nt], qfs[dk], bb0, bb1);
            }
        }

        if (kt_i >= 2 * qt) {
            const int rl0 = row0 + gid;
            const int rl1 = rl0 + 8;
#pragma unroll
            for (int nt = 0; nt < 4; ++nt) {
                int j = kt_i * KT + nt * 8 + 2 * tig;
                if (j     > rl0) cs[nt][0] = -INFINITY;
                if (j + 1 > rl0) cs[nt][1] = -INFINITY;
                if (j     > rl1) cs[nt][2] = -INFINITY;
                if (j + 1 > rl1) cs[nt][3] = -INFINITY;
            }
        }

        float mx0 = -INFINITY, mx1 = -INFINITY;
#pragma unroll
        for (int nt = 0; nt < 4; ++nt) {
            mx0 = fmaxf(mx0, fmaxf(cs[nt][0], cs[nt][1]));
            mx1 = fmaxf(mx1, fmaxf(cs[nt][2], cs[nt][3]));
        }
        mx0 = fmaxf(mx0, __shfl_xor_sync(0xffffffffu, mx0, 1));
        mx0 = fmaxf(mx0, __shfl_xor_sync(0xffffffffu, mx0, 2));
        mx1 = fmaxf(mx1, __shfl_xor_sync(0xffffffffu, mx1, 1));
        mx1 = fmaxf(mx1, __shfl_xor_sync(0xffffffffu, mx1, 2));

        const float mn0 = fmaxf(m0, mx0);
        const float mn1 = fmaxf(m1, mx1);
        const float cor0 = ex2(m0 - mn0);
        const float cor1 = ex2(m1 - mn1);
        l0 *= cor0; l1 *= cor1;
#pragma unroll
        for (int nt = 0; nt < 8; ++nt) {
            o[nt][0] *= cor0; o[nt][1] *= cor0;
            o[nt][2] *= cor1; o[nt][3] *= cor1;
        }

        float rs0 = 0.f, rs1 = 0.f;
#pragma unroll
        for (int nt = 0; nt < 4; ++nt) {
            float p0 = ex2(cs[nt][0] - mn0);
            float p1 = ex2(cs[nt][1] - mn0);
            float p2 = ex2(cs[nt][2] - mn1);
            float p3 = ex2(cs[nt][3] - mn1);
            rs0 += p0 + p1; rs1 += p2 + p3;
            int col = nt * 8 + 2 * tig;
            *(float2*)(Pw + gid * LDP + col)       = make_float2(p0, p1);
            *(float2*)(Pw + (gid + 8) * LDP + col) = make_float2(p2, p3);
        }
        rs0 += __shfl_xor_sync(0xffffffffu, rs0, 1);
        rs0 += __shfl_xor_sync(0xffffffffu, rs0, 2);
        rs1 += __shfl_xor_sync(0xffffffffu, rs1, 1);
        rs1 += __shfl_xor_sync(0xffffffffu, rs1, 2);
        l0 += rs0; l1 += rs1;
        m0 = mn0; m1 = mn1;

        __syncwarp();

#pragma unroll
        for (int kk = 0; kk < 4; ++kk) {
            uint32_t ab[4], as_[4];
            tfsplit(Pw[gid * LDP + kk * 8 + tig],           ab[0], as_[0]);
            tfsplit(Pw[(gid + 8) * LDP + kk * 8 + tig],     ab[1], as_[1]);
            tfsplit(Pw[gid * LDP + kk * 8 + tig + 4],       ab[2], as_[2]);
            tfsplit(Pw[(gid + 8) * LDP + kk * 8 + tig + 4], ab[3], as_[3]);
#pragma unroll
            for (int nt = 0; nt < 8; ++nt) {
                const int r0 = (kk * 8 + tig) * LDV + nt * 8 + gid;
                const int r1 = (kk * 8 + tig + 4) * LDV + nt * 8 + gid;
                uint32_t bb0 = __float_as_uint(Vb[r0]);
                uint32_t bb1 = __float_as_uint(Vb[r1]);
                mma_tf32(o[nt], ab,  bb0, bb1);
                mma_tf32(o[nt], as_, bb0, bb1);
            }
        }
    }

    const float i0 = 1.f / l0;
    const float i1 = 1.f / l1;
    const int n = nh >> 3, hh = nh & 7;
    const int rg0 = row0 + gid;
#pragma unroll
    for (int nt = 0; nt < 8; ++nt) {
        int col = hh * DD + nt * 8 + 2 * tig;
        *(float2*)(g_att + (size_t)(n * TT + rg0) * DMOD + col) =
            make_float2(o[nt][0] * i0, o[nt][1] * i0);
        *(float2*)(g_att + (size_t)(n * TT + rg0 + 8) * DMOD + col) =
            make_float2(o[nt][2] * i1, o[nt][3] * i1);
    }
}

// ---------------- fused residual add + LayerNorm -------------------------------
// WRITE_H16: also write fp16 copy to g_hh (next GEMM's A).
template<bool WRITE_H16>
__global__ __launch_bounds__(256)
void add_ln_kernel(const float* __restrict__ a, const float* __restrict__ b,
                   const float* __restrict__ gamma, const float* __restrict__ beta,
                   float* __restrict__ out)
{
    int row = blockIdx.x;
    int tid = threadIdx.x;
    const float* ar = a + (size_t)row * DMOD;
    const float* br = b + (size_t)row * DMOD;

    float x0 = ar[tid]       + br[tid];
    float x1 = ar[tid + 256] + br[tid + 256];

    float sum = x0 + x1;
    float sq  = x0 * x0 + x1 * x1;
#pragma unroll
    for (int off = 16; off; off >>= 1) {
        sum += __shfl_xor_sync(0xffffffffu, sum, off);
        sq  += __shfl_xor_sync(0xffffffffu, sq,  off);
    }
    __shared__ float s1[8], s2[8];
    int wid = tid >> 5, lane = tid & 31;
    if (lane == 0) { s1[wid] = sum; s2[wid] = sq; }
    __syncthreads();
    float S = 0.f, Q = 0.f;
#pragma unroll
    for (int i = 0; i < 8; ++i) { S += s1[i]; Q += s2[i]; }

    float mean = S * (1.f / DMOD);
    float var  = Q * (1.f / DMOD) - mean * mean;
    float rstd = 1.f / sqrtf(var + 1e-3f);

    float y0 = gamma[tid]       * (x0 - mean) * rstd + beta[tid];
    float y1 = gamma[tid + 256] * (x1 - mean) * rstd + beta[tid + 256];
    out[(size_t)row * DMOD + tid]       = y0;
    out[(size_t)row * DMOD + tid + 256] = y1;
    if (WRITE_H16) {
        g_hh[(size_t)row * DMOD + tid]       = __float2half(y0);
        g_hh[(size_t)row * DMOD + tid + 256] = __float2half(y1);
    }
}

// ---------------- launch ------------------------------------------------------
extern "C" void kernel_launch(void* const* d_in, const int* in_sizes, int n_in,
                              void* d_out, int out_size)
{
    const int*   x     = (const int*)  d_in[0];
    const float* emb   = (const float*)d_in[1];
    const float* Wqkv  = (const float*)d_in[2];
    const float* bqkv  = (const float*)d_in[3];
    const float* Wff   = (const float*)d_in[4];
    const float* bff   = (const float*)d_in[5];
    const float* Wo    = (const float*)d_in[6];
    const float* bo    = (const float*)d_in[7];
    const float* g1    = (const float*)d_in[8];
    const float* beta1 = (const float*)d_in[9];
    const float* g2    = (const float*)d_in[10];
    const float* beta2 = (const float*)d_in[11];
    float* out = (float*)d_out;

    float *h, *qkv, *att, *ff2;
    __half *hh, *ff1, *wqkv, *wff, *wo;
    cudaGetSymbolAddress((void**)&h,    g_h);
    cudaGetSymbolAddress((void**)&hh,   g_hh);
    cudaGetSymbolAddress((void**)&qkv,  g_qkv);
    cudaGetSymbolAddress((void**)&att,  g_att);
    cudaGetSymbolAddress((void**)&ff1,  g_ff1);
    cudaGetSymbolAddress((void**)&ff2,  g_ff2);
    cudaGetSymbolAddress((void**)&wqkv, g_wqkv);
    cudaGetSymbolAddress((void**)&wff,  g_wff);
    cudaGetSymbolAddress((void**)&wo,   g_wo);

    cudaFuncSetAttribute(attn_mma_kernel,
                         cudaFuncAttributeMaxDynamicSharedMemorySize, ATTN_SMEM_BYTES);

    // prepass: transpose + fp16-convert all weights: [K][N] -> [N][K]
    transpose_w_kernel<<<dim3(1536 / 32, DMOD / 32, NLAY), dim3(32, 8)>>>(
        Wqkv, wqkv, DMOD, 3 * DMOD);
    transpose_w_kernel<<<dim3(DFFV / 32, DMOD / 32, NLAY), dim3(32, 8)>>>(
        Wff, wff, DMOD, DFFV);
    transpose_w_kernel<<<dim3(DMOD / 32, DFFV / 32, NLAY), dim3(32, 8)>>>(
        Wo, wo, DFFV, DMOD);

    embed_kernel<<<ROWS, 128>>>(x, emb);

    for (int l = 0; l < NLAY; ++l) {
        // QKV: [4096,512]h @ [1536,512]h^T -> fp32
        gemm_f16<0><<<dim3(1536 / 128, ROWS / 128), 256>>>(
            hh, wqkv + (size_t)l * DMOD * 3 * DMOD, bqkv + (size_t)l * 3 * DMOD,
            qkv, ROWS, 3 * DMOD, DMOD);

        split_qkv_kernel<<<ROWS, 384>>>();

        attn_mma_kernel<<<dim3(TT / 64, NH), 128, ATTN_SMEM_BYTES>>>();

        add_ln_kernel<true><<<ROWS, 256>>>(h, att,
            g1 + (size_t)l * DMOD, beta1 + (size_t)l * DMOD, h);

        // FF1: relu -> fp16
        gemm_f16<1><<<dim3(DFFV / 128, ROWS / 128), 256>>>(
            hh, wff + (size_t)l * DMOD * DFFV, bff + (size_t)l * DFFV,
            ff1, ROWS, DFFV, DMOD);

        // FF2: fp16 A (relu out) -> fp32
        gemm_f16<0><<<dim3(DMOD / 128, ROWS / 128), 256>>>(
            ff1, wo + (size_t)l * DFFV * DMOD, bo + (size_t)l * DMOD,
            ff2, ROWS, DMOD, DFFV);

        if (l == NLAY - 1)
            add_ln_kernel<false><<<ROWS, 256>>>(h, ff2,
                g2 + (size_t)l * DMOD, beta2 + (size_t)l * DMOD, out);
        else
            add_ln_kernel<true><<<ROWS, 256>>>(h, ff2,
                g2 + (size_t)l * DMOD, beta2 + (size_t)l * DMOD, h);
    }
}

// round 15
// speedup vs baseline: 2.6259x; 1.0472x over previous
#include <cuda_runtime.h>
#include <cuda_fp16.h>
#include <math.h>
#include <stdint.h>

#define NB   4
#define TT   1024
#define HH   8
#define DD   64
#define DMOD 512
#define DFFV 1024
#define NLAY 6
#define ROWS (NB * TT)   // 4096
#define NH   (NB * HH)   // 32

#define QSCALE (0.125f * 1.4426950408889634f)

// ---------------- scratch (static device globals; no allocation) -------------
__device__ float  g_h   [ROWS * DMOD];
__device__ __half g_hh  [ROWS * DMOD];           // fp16 copy of g_h (GEMM A)
__device__ float  g_qkv [ROWS * 3 * DMOD];
__device__ float  g_att [ROWS * DMOD];
__device__ __half g_ff1 [ROWS * DFFV];           // fp16 relu output (FF2 A)
__device__ float  g_ff2 [ROWS * DMOD];
__device__ float  g_q   [NH * TT * DD];          // fp32 (compensated in attn)
__device__ __half g_kh  [NH * TT * DD];          // fp16 K [nh][t][d]
__device__ __half g_vh  [NH * TT * DD];          // fp16 V [nh][t][d]
__device__ __half g_vt  [NH * DD * TT];          // fp16 V transposed [nh][d][t]
// fp16 weights, TRANSPOSED to [N][K]
__device__ __half g_wqkv[NLAY * DMOD * 3 * DMOD];
__device__ __half g_wff [NLAY * DMOD * DFFV];
__device__ __half g_wo  [NLAY * DFFV * DMOD];

// ---------------- common PTX helpers -------------------------------------------
__device__ __forceinline__ void mma_f16(float* c, const uint32_t* a, uint32_t b0, uint32_t b1)
{
    asm volatile(
        "mma.sync.aligned.m16n8k16.row.col.f32.f16.f16.f32 "
        "{%0,%1,%2,%3}, {%4,%5,%6,%7}, {%8,%9}, {%0,%1,%2,%3};"
        : "+f"(c[0]), "+f"(c[1]), "+f"(c[2]), "+f"(c[3])
        : "r"(a[0]), "r"(a[1]), "r"(a[2]), "r"(a[3]), "r"(b0), "r"(b1));
}
__device__ __forceinline__ void cp_async16(uint32_t saddr, const void* gaddr)
{
    asm volatile("cp.async.cg.shared.global [%0], [%1], 16;" :: "r"(saddr), "l"(gaddr));
}
__device__ __forceinline__ void cp_commit() { asm volatile("cp.async.commit_group;"); }
template<int N> __device__ __forceinline__ void cp_wait() {
    asm volatile("cp.async.wait_group %0;" :: "n"(N));
}
__device__ __forceinline__ float ex2(float x)
{
    float r;
    asm("ex2.approx.ftz.f32 %0, %1;" : "=f"(r) : "f"(x));
    return r;
}
__device__ __forceinline__ uint32_t packh2(__half lo, __half hi)
{
    return (uint32_t)__half_as_ushort(lo) | ((uint32_t)__half_as_ushort(hi) << 16);
}
// fp16 big/small split of an fp32 value pair, packed
__device__ __forceinline__ void h2split(float f0, float f1, uint32_t& big, uint32_t& small)
{
    __half b0 = __float2half_rn(f0), b1 = __float2half_rn(f1);
    __half s0 = __float2half_rn(f0 - __half2float(b0));
    __half s1 = __float2half_rn(f1 - __half2float(b1));
    big   = packh2(b0, b1);
    small = packh2(s0, s1);
}

// ---------------- weight transpose + fp16 convert prepass ----------------------
__global__ __launch_bounds__(256)
void transpose_w_kernel(const float* __restrict__ src, __half* __restrict__ dst,
                        int K, int N)
{
    __shared__ __half tile[32][33];
    const size_t lo = (size_t)blockIdx.z * K * N;
    const int k0 = blockIdx.y * 32, n0 = blockIdx.x * 32;
#pragma unroll
    for (int i = threadIdx.y; i < 32; i += 8)
        tile[i][threadIdx.x] = __float2half(src[lo + (size_t)(k0 + i) * N + n0 + threadIdx.x]);
    __syncthreads();
#pragma unroll
    for (int i = threadIdx.y; i < 32; i += 8)
        dst[lo + (size_t)(n0 + i) * K + k0 + threadIdx.x] = tile[threadIdx.x][i];
}

// ---------------- per-layer V transpose: [nh][t][d] -> [nh][d][t] ---------------
__global__ __launch_bounds__(256)
void vt_kernel()
{
    __shared__ __half tile[64][65];
    const int nh = blockIdx.y;
    const int t0 = blockIdx.x * 64;
    const __half* src = g_vh + (size_t)nh * TT * DD;
    __half*       dst = g_vt + (size_t)nh * DD * TT;
#pragma unroll
    for (int i = threadIdx.y; i < 64; i += 8) {
        tile[i][threadIdx.x]      = src[(size_t)(t0 + i) * DD + threadIdx.x];
        tile[i][threadIdx.x + 32] = src[(size_t)(t0 + i) * DD + threadIdx.x + 32];
    }
    __syncthreads();
#pragma unroll
    for (int i = threadIdx.y; i < 64; i += 8) {
        dst[(size_t)i * TT + t0 + threadIdx.x]      = tile[threadIdx.x][i];
        dst[(size_t)i * TT + t0 + threadIdx.x + 32] = tile[threadIdx.x + 32][i];
    }
}

// ---------------- embedding + positional encoding (all-fp32, MUFU) -------------
__global__ void embed_kernel(const int* __restrict__ x, const float* __restrict__ emb)
{
    int row = blockIdx.x;
    int t   = row & (TT - 1);
    int tok = x[row];
    const float* e = emb + (size_t)tok * DMOD;
    float tf = (float)t;
    for (int i = threadIdx.x; i < DMOD; i += blockDim.x) {
        float expo = -2.0f * (float)(i >> 1) * (1.0f / (float)DMOD);
        float rate = powf(10000.0f, expo);
        float ang  = tf * rate;
        float s, c;
        sincosf(ang, &s, &c);
        float p   = (i & 1) ? c : s;
        float val = e[i] * 22.62741699796952f + p;  // sqrt(512)
        g_h [(size_t)row * DMOD + i] = val;
        g_hh[(size_t)row * DMOD + i] = __float2half(val);
    }
}

// ---------------- FP16 GEMM — m16n8k16, 3-stage cp.async pipeline (R14) --------
#define LDAH 40
#define STG  3

template<int MODE>
__global__ __launch_bounds__(256)
void gemm_f16(const __half* __restrict__ A, const __half* __restrict__ B,
              const float* __restrict__ bias, void* __restrict__ Cv,
              int M, int N, int K)
{
    __shared__ __half As[STG][128 * LDAH];
    __shared__ __half Bs[STG][128 * LDAH];

    const int tid  = threadIdx.x;
    const int bm   = blockIdx.y * 128;
    const int bn   = blockIdx.x * 128;

    const int r0 = tid >> 1;
    const int o0 = (tid & 1) * 16;

    const uint32_t sA = (uint32_t)__cvta_generic_to_shared(&As[0][0]);
    const uint32_t sB = (uint32_t)__cvta_generic_to_shared(&Bs[0][0]);

    const int warp = tid >> 5, lane = tid & 31;
    const int gid  = lane >> 2, tig = lane & 3;
    const int wm   = (warp & 3) * 32;
    const int wn   = (warp >> 2) * 64;

    float c[2][8][4];
#pragma unroll
    for (int mt = 0; mt < 2; ++mt)
#pragma unroll
        for (int nt = 0; nt < 8; ++nt)
#pragma unroll
            for (int j = 0; j < 4; ++j) c[mt][nt][j] = 0.f;

    const int nIter = K >> 5;

    auto issue = [&](int t) {
        const int buf = t % STG;
        const __half* Ap = A + (size_t)(bm + r0) * K + t * 32 + o0;
        const __half* Bp = B + (size_t)(bn + r0) * K + t * 32 + o0;
        uint32_t sa = sA + (buf * 128 * LDAH + r0 * LDAH + o0) * 2;
        uint32_t sb = sB + (buf * 128 * LDAH + r0 * LDAH + o0) * 2;
        cp_async16(sa,      Ap);
        cp_async16(sa + 16, Ap + 8);
        cp_async16(sb,      Bp);
        cp_async16(sb + 16, Bp + 8);
        cp_commit();
    };

    issue(0);
    if (nIter > 1) issue(1);

    for (int it = 0; it < nIter; ++it) {
        if (it + 1 < nIter) cp_wait<1>(); else cp_wait<0>();
        __syncthreads();
        if (it + 2 < nIter) issue(it + 2);

        const __half* Ac = As[it % STG];
        const __half* Bc = Bs[it % STG];
#pragma unroll
        for (int ks = 0; ks < 2; ++ks) {
            const int kb = ks * 16;
            uint32_t a[2][4], b[8][2];
#pragma unroll
            for (int mt = 0; mt < 2; ++mt) {
                const int r = wm + mt * 16 + gid;
                a[mt][0] = *(const uint32_t*)&Ac[(uint32_t)r * LDAH + kb + 2 * tig];
                a[mt][1] = *(const uint32_t*)&Ac[(uint32_t)(r + 8) * LDAH + kb + 2 * tig];
                a[mt][2] = *(const uint32_t*)&Ac[(uint32_t)r * LDAH + kb + 2 * tig + 8];
                a[mt][3] = *(const uint32_t*)&Ac[(uint32_t)(r + 8) * LDAH + kb + 2 * tig + 8];
            }
#pragma unroll
            for (int nt = 0; nt < 8; ++nt) {
                const int col = wn + nt * 8 + gid;
                b[nt][0] = *(const uint32_t*)&Bc[(uint32_t)col * LDAH + kb + 2 * tig];
                b[nt][1] = *(const uint32_t*)&Bc[(uint32_t)col * LDAH + kb + 2 * tig + 8];
            }
#pragma unroll
            for (int mt = 0; mt < 2; ++mt)
#pragma unroll
                for (int nt = 0; nt < 8; ++nt)
                    mma_f16(c[mt][nt], a[mt], b[nt][0], b[nt][1]);
        }
    }

#pragma unroll
    for (int mt = 0; mt < 2; ++mt) {
        const int row0 = bm + wm + mt * 16 + gid;
#pragma unroll
        for (int nt = 0; nt < 8; ++nt) {
            const int coln = bn + wn + nt * 8 + 2 * tig;
            const float2 bv = *(const float2*)(bias + coln);
            float2 v0, v1;
            v0.x = c[mt][nt][0] + bv.x; v0.y = c[mt][nt][1] + bv.y;
            v1.x = c[mt][nt][2] + bv.x; v1.y = c[mt][nt][3] + bv.y;
            if (MODE == 1) {
                __half* C = (__half*)Cv;
                __half2 h0 = __floats2half2_rn(fmaxf(v0.x, 0.f), fmaxf(v0.y, 0.f));
                __half2 h1 = __floats2half2_rn(fmaxf(v1.x, 0.f), fmaxf(v1.y, 0.f));
                *(__half2*)(C + (size_t)row0 * N + coln)       = h0;
                *(__half2*)(C + (size_t)(row0 + 8) * N + coln) = h1;
            } else {
                float* C = (float*)Cv;
                *(float2*)(C + (size_t)row0 * N + coln)       = v0;
                *(float2*)(C + (size_t)(row0 + 8) * N + coln) = v1;
            }
        }
    }
}

// ---------------- split qkv: q fp32 (scaled), K/V fp16 -------------------------
__global__ __launch_bounds__(384)
void split_qkv_kernel()
{
    int row = blockIdx.x;
    int n   = row >> 10;
    int t   = row & (TT - 1);
    int c0  = threadIdx.x * 4;
    float4 v = *(const float4*)(g_qkv + (size_t)row * 1536 + c0);
    float vals[4] = {v.x, v.y, v.z, v.w};
#pragma unroll
    for (int u = 0; u < 4; ++u) {
        int c = c0 + u;
        int h = c / 192;
        int r = c - h * 192;
        int d = r / 3;
        int j = r - d * 3;
        size_t dst = ((size_t)(n * HH + h) * TT + t) * DD + d;
        if (j == 0)      g_q [dst] = vals[u] * QSCALE;
        else if (j == 1) g_kh[dst] = __float2half(vals[u]);
        else             g_vh[dst] = __float2half(vals[u]);
    }
}

// ---------------- FlashAttention-2, fp16 mma, compensated Q & P ----------------
// smem (halves): K 2x32x72, Vt 2x64x40, Pb/Ps 4 warps x 16 x 40
#define KT    32
#define LDKH  72
#define LDVH  40
#define LDPW  20                                   // u32 words per P row
#define OFF_KB 0
#define OFF_VT (2 * KT * LDKH)                     // 4608
#define OFF_PB (OFF_VT + 2 * DD * LDVH)            // 9728
#define OFF_PS (OFF_PB + 4 * 16 * 2 * LDPW)        // 12288
#define ATTN_SMEM_HALVES (OFF_PS + 4 * 16 * 2 * LDPW)  // 14848
#define ATTN_SMEM_BYTES  (ATTN_SMEM_HALVES * 2)        // 29696

__global__ __launch_bounds__(128)
void attn_mma_kernel()
{
    extern __shared__ __half smh[];

    const int tid  = threadIdx.x;
    const int warp = tid >> 5, lane = tid & 31;
    const int gid  = lane >> 2, tig = lane & 3;
    const int qt   = gridDim.x - 1 - blockIdx.x;   // heavy q-tiles first
    const int nh   = blockIdx.y;
    const int row0 = qt * 64 + warp * 16;

    const __half* kbp = g_kh + (size_t)nh * TT * DD;
    const __half* vtp = g_vt + (size_t)nh * DD * TT;

    const uint32_t sbase = (uint32_t)__cvta_generic_to_shared(smh);

    // Q fragments: fp16 big/small split of fp32 q (4 k-chunks of 16)
    uint32_t qfb[4][4], qfs[4][4];
    {
        const float* qp = g_q + ((size_t)nh * TT + row0) * DD;
#pragma unroll
        for (int dk = 0; dk < 4; ++dk) {
            h2split(qp[gid * DD + dk * 16 + 2 * tig],
                    qp[gid * DD + dk * 16 + 2 * tig + 1],       qfb[dk][0], qfs[dk][0]);
            h2split(qp[(gid + 8) * DD + dk * 16 + 2 * tig],
                    qp[(gid + 8) * DD + dk * 16 + 2 * tig + 1], qfb[dk][1], qfs[dk][1]);
            h2split(qp[gid * DD + dk * 16 + 2 * tig + 8],
                    qp[gid * DD + dk * 16 + 2 * tig + 9],       qfb[dk][2], qfs[dk][2]);
            h2split(qp[(gid + 8) * DD + dk * 16 + 2 * tig + 8],
                    qp[(gid + 8) * DD + dk * 16 + 2 * tig + 9], qfb[dk][3], qfs[dk][3]);
        }
    }

    float o[8][4];
#pragma unroll
    for (int nt = 0; nt < 8; ++nt)
#pragma unroll
        for (int j = 0; j < 4; ++j) o[nt][j] = 0.f;
    float m0 = -INFINITY, m1 = -INFINITY, l0 = 0.f, l1 = 0.f;

    const int ntiles = 2 * qt + 2;

    // K tile: 32 keys x 64 halves (128B rows) = 256 16B chunks; V: 64 d x 32 keys (64B) = 256
    auto prefetch = [&](int t) {
        const int buf = t & 1;
        const uint32_t kOff = OFF_KB + buf * KT * LDKH;
        const uint32_t vOff = OFF_VT + buf * DD * LDVH;
#pragma unroll
        for (int i = 0; i < 2; ++i) {
            int c = i * 128 + tid;                 // 0..255
            int key = c >> 3, ko = (c & 7) * 8;
            cp_async16(sbase + (kOff + key * LDKH + ko) * 2,
                       kbp + (size_t)(t * KT + key) * DD + ko);
            int d = c >> 2, vo = (c & 3) * 8;
            cp_async16(sbase + (vOff + d * LDVH + vo) * 2,
                       vtp + (size_t)d * TT + t * KT + vo);
        }
        cp_commit();
    };

    prefetch(0);

    uint32_t* PwB = (uint32_t*)(smh + OFF_PB) + warp * 16 * LDPW;
    uint32_t* PwS = (uint32_t*)(smh + OFF_PS) + warp * 16 * LDPW;

#pragma unroll 1
    for (int kt_i = 0; kt_i < ntiles; ++kt_i) {
        cp_wait<0>();
        __syncthreads();
        if (kt_i + 1 < ntiles) prefetch(kt_i + 1);

        const int buf = kt_i & 1;
        const __half* Kb = smh + OFF_KB + buf * KT * LDKH;
        const __half* Vt = smh + OFF_VT + buf * DD * LDVH;

        // ---- S = (q_big + q_small) @ K^T : fp16 k16, 2 mma per (nt,dk) ----
        float cs[4][4];
#pragma unroll
        for (int nt = 0; nt < 4; ++nt) {
#pragma unroll
            for (int j = 0; j < 4; ++j) cs[nt][j] = 0.f;
#pragma unroll
            for (int dk = 0; dk < 4; ++dk) {
                const __half* kr = Kb + (nt * 8 + gid) * LDKH + dk * 16 + 2 * tig;
                uint32_t b0 = *(const uint32_t*)kr;
                uint32_t b1 = *(const uint32_t*)(kr + 8);
                mma_f16(cs[nt], qfb[dk], b0, b1);
                mma_f16(cs[nt], qfs[dk], b0, b1);
            }
        }

        if (kt_i >= 2 * qt) {
            const int rl0 = row0 + gid;
            const int rl1 = rl0 + 8;
#pragma unroll
            for (int nt = 0; nt < 4; ++nt) {
                int j = kt_i * KT + nt * 8 + 2 * tig;
                if (j     > rl0) cs[nt][0] = -INFINITY;
                if (j + 1 > rl0) cs[nt][1] = -INFINITY;
                if (j     > rl1) cs[nt][2] = -INFINITY;
                if (j + 1 > rl1) cs[nt][3] = -INFINITY;
            }
        }

        // ---- online softmax (exp2 domain, fp32) ----
        float mx0 = -INFINITY, mx1 = -INFINITY;
#pragma unroll
        for (int nt = 0; nt < 4; ++nt) {
            mx0 = fmaxf(mx0, fmaxf(cs[nt][0], cs[nt][1]));
            mx1 = fmaxf(mx1, fmaxf(cs[nt][2], cs[nt][3]));
        }
        mx0 = fmaxf(mx0, __shfl_xor_sync(0xffffffffu, mx0, 1));
        mx0 = fmaxf(mx0, __shfl_xor_sync(0xffffffffu, mx0, 2));
        mx1 = fmaxf(mx1, __shfl_xor_sync(0xffffffffu, mx1, 1));
        mx1 = fmaxf(mx1, __shfl_xor_sync(0xffffffffu, mx1, 2));

        const float mn0 = fmaxf(m0, mx0);
        const float mn1 = fmaxf(m1, mx1);
        const float cor0 = ex2(m0 - mn0);
        const float cor1 = ex2(m1 - mn1);
        l0 *= cor0; l1 *= cor1;
#pragma unroll
        for (int nt = 0; nt < 8; ++nt) {
            o[nt][0] *= cor0; o[nt][1] *= cor0;
            o[nt][2] *= cor1; o[nt][3] *= cor1;
        }

        float rs0 = 0.f, rs1 = 0.f;
#pragma unroll
        for (int nt = 0; nt < 4; ++nt) {
            float p0 = ex2(cs[nt][0] - mn0);
            float p1 = ex2(cs[nt][1] - mn0);
            float p2 = ex2(cs[nt][2] - mn1);
            float p3 = ex2(cs[nt][3] - mn1);
            rs0 += p0 + p1; rs1 += p2 + p3;
            uint32_t b01, s01, b23, s23;
            h2split(p0, p1, b01, s01);
            h2split(p2, p3, b23, s23);
            const int w = nt * 4 + tig;
            PwB[gid * LDPW + w]       = b01;
            PwS[gid * LDPW + w]       = s01;
            PwB[(gid + 8) * LDPW + w] = b23;
            PwS[(gid + 8) * LDPW + w] = s23;
        }
        rs0 += __shfl_xor_sync(0xffffffffu, rs0, 1);
        rs0 += __shfl_xor_sync(0xffffffffu, rs0, 2);
        rs1 += __shfl_xor_sync(0xffffffffu, rs1, 1);
        rs1 += __shfl_xor_sync(0xffffffffu, rs1, 2);
        l0 += rs0; l1 += rs1;
        m0 = mn0; m1 = mn1;

        __syncwarp();

        // ---- O += (P_big + P_small) @ V : fp16 k16 ----
#pragma unroll
        for (int kk = 0; kk < 2; ++kk) {
            uint32_t ab[4], as_[4];
            ab[0]  = PwB[gid * LDPW + kk * 8 + tig];
            ab[1]  = PwB[(gid + 8) * LDPW + kk * 8 + tig];
            ab[2]  = PwB[gid * LDPW + kk * 8 + tig + 4];
            ab[3]  = PwB[(gid + 8) * LDPW + kk * 8 + tig + 4];
            as_[0] = PwS[gid * LDPW + kk * 8 + tig];
            as_[1] = PwS[(gid + 8) * LDPW + kk * 8 + tig];
            as_[2] = PwS[gid * LDPW + kk * 8 + tig + 4];
            as_[3] = PwS[(gid + 8) * LDPW + kk * 8 + tig + 4];
#pragma unroll
            for (int nt = 0; nt < 8; ++nt) {
                const __half* vr = Vt + (nt * 8 + gid) * LDVH + kk * 16 + 2 * tig;
                uint32_t b0 = *(const uint32_t*)vr;
                uint32_t b1 = *(const uint32_t*)(vr + 8);
                mma_f16(o[nt], ab,  b0, b1);
                mma_f16(o[nt], as_, b0, b1);
            }
        }
    }

    const float i0 = 1.f / l0;
    const float i1 = 1.f / l1;
    const int n = nh >> 3, hh = nh & 7;
    const int rg0 = row0 + gid;
#pragma unroll
    for (int nt = 0; nt < 8; ++nt) {
        int col = hh * DD + nt * 8 + 2 * tig;
        *(float2*)(g_att + (size_t)(n * TT + rg0) * DMOD + col) =
            make_float2(o[nt][0] * i0, o[nt][1] * i0);
        *(float2*)(g_att + (size_t)(n * TT + rg0 + 8) * DMOD + col) =
            make_float2(o[nt][2] * i1, o[nt][3] * i1);
    }
}

// ---------------- fused residual add + LayerNorm -------------------------------
template<bool WRITE_H16>
__global__ __launch_bounds__(256)
void add_ln_kernel(const float* __restrict__ a, const float* __restrict__ b,
                   const float* __restrict__ gamma, const float* __restrict__ beta,
                   float* __restrict__ out)
{
    int row = blockIdx.x;
    int tid = threadIdx.x;
    const float* ar = a + (size_t)row * DMOD;
    const float* br = b + (size_t)row * DMOD;

    float x0 = ar[tid]       + br[tid];
    float x1 = ar[tid + 256] + br[tid + 256];

    float sum = x0 + x1;
    float sq  = x0 * x0 + x1 * x1;
#pragma unroll
    for (int off = 16; off; off >>= 1) {
        sum += __shfl_xor_sync(0xffffffffu, sum, off);
        sq  += __shfl_xor_sync(0xffffffffu, sq,  off);
    }
    __shared__ float s1[8], s2[8];
    int wid = tid >> 5, lane = tid & 31;
    if (lane == 0) { s1[wid] = sum; s2[wid] = sq; }
    __syncthreads();
    float S = 0.f, Q = 0.f;
#pragma unroll
    for (int i = 0; i < 8; ++i) { S += s1[i]; Q += s2[i]; }

    float mean = S * (1.f / DMOD);
    float var  = Q * (1.f / DMOD) - mean * mean;
    float rstd = 1.f / sqrtf(var + 1e-3f);

    float y0 = gamma[tid]       * (x0 - mean) * rstd + beta[tid];
    float y1 = gamma[tid + 256] * (x1 - mean) * rstd + beta[tid + 256];
    out[(size_t)row * DMOD + tid]       = y0;
    out[(size_t)row * DMOD + tid + 256] = y1;
    if (WRITE_H16) {
        g_hh[(size_t)row * DMOD + tid]       = __float2half(y0);
        g_hh[(size_t)row * DMOD + tid + 256] = __float2half(y1);
    }
}

// ---------------- launch ------------------------------------------------------
extern "C" void kernel_launch(void* const* d_in, const int* in_sizes, int n_in,
                              void* d_out, int out_size)
{
    const int*   x     = (const int*)  d_in[0];
    const float* emb   = (const float*)d_in[1];
    const float* Wqkv  = (const float*)d_in[2];
    const float* bqkv  = (const float*)d_in[3];
    const float* Wff   = (const float*)d_in[4];
    const float* bff   = (const float*)d_in[5];
    const float* Wo    = (const float*)d_in[6];
    const float* bo    = (const float*)d_in[7];
    const float* g1    = (const float*)d_in[8];
    const float* beta1 = (const float*)d_in[9];
    const float* g2    = (const float*)d_in[10];
    const float* beta2 = (const float*)d_in[11];
    float* out = (float*)d_out;

    float *h, *qkv, *att, *ff2;
    __half *hh, *ff1, *wqkv, *wff, *wo;
    cudaGetSymbolAddress((void**)&h,    g_h);
    cudaGetSymbolAddress((void**)&hh,   g_hh);
    cudaGetSymbolAddress((void**)&qkv,  g_qkv);
    cudaGetSymbolAddress((void**)&att,  g_att);
    cudaGetSymbolAddress((void**)&ff1,  g_ff1);
    cudaGetSymbolAddress((void**)&ff2,  g_ff2);
    cudaGetSymbolAddress((void**)&wqkv, g_wqkv);
    cudaGetSymbolAddress((void**)&wff,  g_wff);
    cudaGetSymbolAddress((void**)&wo,   g_wo);

    cudaFuncSetAttribute(attn_mma_kernel,
                         cudaFuncAttributeMaxDynamicSharedMemorySize, ATTN_SMEM_BYTES);

    transpose_w_kernel<<<dim3(1536 / 32, DMOD / 32, NLAY), dim3(32, 8)>>>(
        Wqkv, wqkv, DMOD, 3 * DMOD);
    transpose_w_kernel<<<dim3(DFFV / 32, DMOD / 32, NLAY), dim3(32, 8)>>>(
        Wff, wff, DMOD, DFFV);
    transpose_w_kernel<<<dim3(DMOD / 32, DFFV / 32, NLAY), dim3(32, 8)>>>(
        Wo, wo, DFFV, DMOD);

    embed_kernel<<<ROWS, 128>>>(x, emb);

    for (int l = 0; l < NLAY; ++l) {
        gemm_f16<0><<<dim3(1536 / 128, ROWS / 128), 256>>>(
            hh, wqkv + (size_t)l * DMOD * 3 * DMOD, bqkv + (size_t)l * 3 * DMOD,
            qkv, ROWS, 3 * DMOD, DMOD);

        split_qkv_kernel<<<ROWS, 384>>>();
        vt_kernel<<<dim3(TT / 64, NH), dim3(32, 8)>>>();

        attn_mma_kernel<<<dim3(TT / 64, NH), 128, ATTN_SMEM_BYTES>>>();

        add_ln_kernel<true><<<ROWS, 256>>>(h, att,
            g1 + (size_t)l * DMOD, beta1 + (size_t)l * DMOD, h);

        gemm_f16<1><<<dim3(DFFV / 128, ROWS / 128), 256>>>(
            hh, wff + (size_t)l * DMOD * DFFV, bff + (size_t)l * DFFV,
            ff1, ROWS, DFFV, DMOD);

        gemm_f16<0><<<dim3(DMOD / 128, ROWS / 128), 256>>>(
            ff1, wo + (size_t)l * DFFV * DMOD, bo + (size_t)l * DMOD,
            ff2, ROWS, DMOD, DFFV);

        if (l == NLAY - 1)
            add_ln_kernel<false><<<ROWS, 256>>>(h, ff2,
                g2 + (size_t)l * DMOD, beta2 + (size_t)l * DMOD, out);
        else
            add_ln_kernel<true><<<ROWS, 256>>>(h, ff2,
                g2 + (size_t)l * DMOD, beta2 + (size_t)l * DMOD, h);
    }
}

// round 16
// speedup vs baseline: 2.6657x; 1.0151x over previous
#include <cuda_runtime.h>
#include <cuda_fp16.h>
#include <math.h>
#include <stdint.h>

#define NB   4
#define TT   1024
#define HH   8
#define DD   64
#define DMOD 512
#define DFFV 1024
#define NLAY 6
#define ROWS (NB * TT)   // 4096
#define NH   (NB * HH)   // 32

#define QSCALE (0.125f * 1.4426950408889634f)

// ---------------- scratch (static device globals; no allocation) -------------
__device__ float  g_h   [ROWS * DMOD];
__device__ __half g_hh  [ROWS * DMOD];
__device__ float  g_qkv [ROWS * 3 * DMOD];
__device__ float  g_att [ROWS * DMOD];
__device__ __half g_ff1 [ROWS * DFFV];
__device__ float  g_ff2 [ROWS * DMOD];
__device__ float  g_q   [NH * TT * DD];
__device__ __half g_kh  [NH * TT * DD];
__device__ __half g_vh  [NH * TT * DD];
__device__ __half g_vt  [NH * DD * TT];
__device__ __half g_wqkv[NLAY * DMOD * 3 * DMOD];
__device__ __half g_wff [NLAY * DMOD * DFFV];
__device__ __half g_wo  [NLAY * DFFV * DMOD];

// ---------------- common PTX helpers -------------------------------------------
__device__ __forceinline__ void mma_f16(float* c, const uint32_t* a, uint32_t b0, uint32_t b1)
{
    asm volatile(
        "mma.sync.aligned.m16n8k16.row.col.f32.f16.f16.f32 "
        "{%0,%1,%2,%3}, {%4,%5,%6,%7}, {%8,%9}, {%0,%1,%2,%3};"
        : "+f"(c[0]), "+f"(c[1]), "+f"(c[2]), "+f"(c[3])
        : "r"(a[0]), "r"(a[1]), "r"(a[2]), "r"(a[3]), "r"(b0), "r"(b1));
}
__device__ __forceinline__ void ldsm_x4(uint32_t& x, uint32_t& y, uint32_t& z, uint32_t& w,
                                        uint32_t addr)
{
    asm volatile("ldmatrix.sync.aligned.m8n8.x4.shared.b16 {%0,%1,%2,%3}, [%4];"
                 : "=r"(x), "=r"(y), "=r"(z), "=r"(w) : "r"(addr));
}
__device__ __forceinline__ void cp_async16(uint32_t saddr, const void* gaddr)
{
    asm volatile("cp.async.cg.shared.global [%0], [%1], 16;" :: "r"(saddr), "l"(gaddr));
}
__device__ __forceinline__ void cp_commit() { asm volatile("cp.async.commit_group;"); }
template<int N> __device__ __forceinline__ void cp_wait() {
    asm volatile("cp.async.wait_group %0;" :: "n"(N));
}
__device__ __forceinline__ float ex2(float x)
{
    float r;
    asm("ex2.approx.ftz.f32 %0, %1;" : "=f"(r) : "f"(x));
    return r;
}
__device__ __forceinline__ uint32_t packh2(__half lo, __half hi)
{
    return (uint32_t)__half_as_ushort(lo) | ((uint32_t)__half_as_ushort(hi) << 16);
}
__device__ __forceinline__ void h2split(float f0, float f1, uint32_t& big, uint32_t& small)
{
    __half b0 = __float2half_rn(f0), b1 = __float2half_rn(f1);
    __half s0 = __float2half_rn(f0 - __half2float(b0));
    __half s1 = __float2half_rn(f1 - __half2float(b1));
    big   = packh2(b0, b1);
    small = packh2(s0, s1);
}

// ---------------- weight transpose + fp16 convert prepass ----------------------
__global__ __launch_bounds__(256)
void transpose_w_kernel(const float* __restrict__ src, __half* __restrict__ dst,
                        int K, int N)
{
    __shared__ __half tile[32][33];
    const size_t lo = (size_t)blockIdx.z * K * N;
    const int k0 = blockIdx.y * 32, n0 = blockIdx.x * 32;
#pragma unroll
    for (int i = threadIdx.y; i < 32; i += 8)
        tile[i][threadIdx.x] = __float2half(src[lo + (size_t)(k0 + i) * N + n0 + threadIdx.x]);
    __syncthreads();
#pragma unroll
    for (int i = threadIdx.y; i < 32; i += 8)
        dst[lo + (size_t)(n0 + i) * K + k0 + threadIdx.x] = tile[threadIdx.x][i];
}

// ---------------- per-layer V transpose: [nh][t][d] -> [nh][d][t] ---------------
__global__ __launch_bounds__(256)
void vt_kernel()
{
    __shared__ __half tile[64][65];
    const int nh = blockIdx.y;
    const int t0 = blockIdx.x * 64;
    const __half* src = g_vh + (size_t)nh * TT * DD;
    __half*       dst = g_vt + (size_t)nh * DD * TT;
#pragma unroll
    for (int i = threadIdx.y; i < 64; i += 8) {
        tile[i][threadIdx.x]      = src[(size_t)(t0 + i) * DD + threadIdx.x];
        tile[i][threadIdx.x + 32] = src[(size_t)(t0 + i) * DD + threadIdx.x + 32];
    }
    __syncthreads();
#pragma unroll
    for (int i = threadIdx.y; i < 64; i += 8) {
        dst[(size_t)i * TT + t0 + threadIdx.x]      = tile[threadIdx.x][i];
        dst[(size_t)i * TT + t0 + threadIdx.x + 32] = tile[threadIdx.x + 32][i];
    }
}

// ---------------- embedding + positional encoding (all-fp32, MUFU) -------------
__global__ void embed_kernel(const int* __restrict__ x, const float* __restrict__ emb)
{
    int row = blockIdx.x;
    int t   = row & (TT - 1);
    int tok = x[row];
    const float* e = emb + (size_t)tok * DMOD;
    float tf = (float)t;
    for (int i = threadIdx.x; i < DMOD; i += blockDim.x) {
        float expo = -2.0f * (float)(i >> 1) * (1.0f / (float)DMOD);
        float rate = powf(10000.0f, expo);
        float ang  = tf * rate;
        float s, c;
        sincosf(ang, &s, &c);
        float p   = (i & 1) ? c : s;
        float val = e[i] * 22.62741699796952f + p;  // sqrt(512)
        g_h [(size_t)row * DMOD + i] = val;
        g_hh[(size_t)row * DMOD + i] = __float2half(val);
    }
}

// ---------------- FP16 GEMM — m16n8k16 + ldmatrix, 3-stage cp.async -------------
#define LDAH 40
#define STG  3
#define BUFB (128 * LDAH * 2)   // bytes per stage per array

template<int MODE>
__global__ __launch_bounds__(256)
void gemm_f16(const __half* __restrict__ A, const __half* __restrict__ B,
              const float* __restrict__ bias, void* __restrict__ Cv,
              int M, int N, int K)
{
    __shared__ __half As[STG][128 * LDAH];
    __shared__ __half Bs[STG][128 * LDAH];

    const int tid  = threadIdx.x;
    const int bm   = blockIdx.y * 128;
    const int bn   = blockIdx.x * 128;

    const int r0 = tid >> 1;
    const int o0 = (tid & 1) * 16;

    const uint32_t sA = (uint32_t)__cvta_generic_to_shared(&As[0][0]);
    const uint32_t sB = (uint32_t)__cvta_generic_to_shared(&Bs[0][0]);

    const int warp = tid >> 5, lane = tid & 31;
    const int gid  = lane >> 2, tig = lane & 3;
    const int wm   = (warp & 3) * 32;
    const int wn   = (warp >> 2) * 64;

    // ldmatrix per-thread byte offsets (within a stage buffer)
    uint32_t aoff[2];
#pragma unroll
    for (int mt = 0; mt < 2; ++mt)
        aoff[mt] = ((uint32_t)(wm + mt * 16 + (lane & 15)) * LDAH + (lane >> 4) * 8) * 2;
    uint32_t boff[4];
    {
        const int g8 = lane >> 3, l7 = lane & 7;
#pragma unroll
        for (int j = 0; j < 4; ++j)
            boff[j] = ((uint32_t)(wn + (2 * j + (g8 >> 1)) * 8 + l7) * LDAH + (g8 & 1) * 8) * 2;
    }

    float c[2][8][4];
#pragma unroll
    for (int mt = 0; mt < 2; ++mt)
#pragma unroll
        for (int nt = 0; nt < 8; ++nt)
#pragma unroll
            for (int j = 0; j < 4; ++j) c[mt][nt][j] = 0.f;

    const int nIter = K >> 5;

    auto issue = [&](int t) {
        const int buf = t % STG;
        const __half* Ap = A + (size_t)(bm + r0) * K + t * 32 + o0;
        const __half* Bp = B + (size_t)(bn + r0) * K + t * 32 + o0;
        uint32_t sa = sA + buf * BUFB + (r0 * LDAH + o0) * 2;
        uint32_t sb = sB + buf * BUFB + (r0 * LDAH + o0) * 2;
        cp_async16(sa,      Ap);
        cp_async16(sa + 16, Ap + 8);
        cp_async16(sb,      Bp);
        cp_async16(sb + 16, Bp + 8);
        cp_commit();
    };

    issue(0);
    if (nIter > 1) issue(1);

    for (int it = 0; it < nIter; ++it) {
        if (it + 1 < nIter) cp_wait<1>(); else cp_wait<0>();
        __syncthreads();
        if (it + 2 < nIter) issue(it + 2);

        const uint32_t bufA = sA + (uint32_t)(it % STG) * BUFB;
        const uint32_t bufB = sB + (uint32_t)(it % STG) * BUFB;
#pragma unroll
        for (int ks = 0; ks < 2; ++ks) {
            const uint32_t kb = ks * 32;     // 16 halves = 32 bytes
            uint32_t a[2][4], b[8][2];
            ldsm_x4(a[0][0], a[0][1], a[0][2], a[0][3], bufA + aoff[0] + kb);
            ldsm_x4(a[1][0], a[1][1], a[1][2], a[1][3], bufA + aoff[1] + kb);
#pragma unroll
            for (int j = 0; j < 4; ++j)
                ldsm_x4(b[2 * j][0], b[2 * j][1], b[2 * j + 1][0], b[2 * j + 1][1],
                        bufB + boff[j] + kb);
#pragma unroll
            for (int mt = 0; mt < 2; ++mt)
#pragma unroll
                for (int nt = 0; nt < 8; ++nt)
                    mma_f16(c[mt][nt], a[mt], b[nt][0], b[nt][1]);
        }
    }

#pragma unroll
    for (int mt = 0; mt < 2; ++mt) {
        const int row0 = bm + wm + mt * 16 + gid;
#pragma unroll
        for (int nt = 0; nt < 8; ++nt) {
            const int coln = bn + wn + nt * 8 + 2 * tig;
            const float2 bv = *(const float2*)(bias + coln);
            float2 v0, v1;
            v0.x = c[mt][nt][0] + bv.x; v0.y = c[mt][nt][1] + bv.y;
            v1.x = c[mt][nt][2] + bv.x; v1.y = c[mt][nt][3] + bv.y;
            if (MODE == 1) {
                __half* C = (__half*)Cv;
                __half2 h0 = __floats2half2_rn(fmaxf(v0.x, 0.f), fmaxf(v0.y, 0.f));
                __half2 h1 = __floats2half2_rn(fmaxf(v1.x, 0.f), fmaxf(v1.y, 0.f));
                *(__half2*)(C + (size_t)row0 * N + coln)       = h0;
                *(__half2*)(C + (size_t)(row0 + 8) * N + coln) = h1;
            } else {
                float* C = (float*)Cv;
                *(float2*)(C + (size_t)row0 * N + coln)       = v0;
                *(float2*)(C + (size_t)(row0 + 8) * N + coln) = v1;
            }
        }
    }
}

// ---------------- split qkv: q fp32 (scaled), K/V fp16 -------------------------
__global__ __launch_bounds__(384)
void split_qkv_kernel()
{
    int row = blockIdx.x;
    int n   = row >> 10;
    int t   = row & (TT - 1);
    int c0  = threadIdx.x * 4;
    float4 v = *(const float4*)(g_qkv + (size_t)row * 1536 + c0);
    float vals[4] = {v.x, v.y, v.z, v.w};
#pragma unroll
    for (int u = 0; u < 4; ++u) {
        int c = c0 + u;
        int h = c / 192;
        int r = c - h * 192;
        int d = r / 3;
        int j = r - d * 3;
        size_t dst = ((size_t)(n * HH + h) * TT + t) * DD + d;
        if (j == 0)      g_q [dst] = vals[u] * QSCALE;
        else if (j == 1) g_kh[dst] = __float2half(vals[u]);
        else             g_vh[dst] = __float2half(vals[u]);
    }
}

// ---------------- FlashAttention-2, fp16 mma, compensated Q & P (R15) ----------
#define KT    32
#define LDKH  72
#define LDVH  40
#define LDPW  20
#define OFF_KB 0
#define OFF_VT (2 * KT * LDKH)
#define OFF_PB (OFF_VT + 2 * DD * LDVH)
#define OFF_PS (OFF_PB + 4 * 16 * 2 * LDPW)
#define ATTN_SMEM_HALVES (OFF_PS + 4 * 16 * 2 * LDPW)
#define ATTN_SMEM_BYTES  (ATTN_SMEM_HALVES * 2)        // 29696

__global__ __launch_bounds__(128)
void attn_mma_kernel()
{
    extern __shared__ __half smh[];

    const int tid  = threadIdx.x;
    const int warp = tid >> 5, lane = tid & 31;
    const int gid  = lane >> 2, tig = lane & 3;
    const int qt   = gridDim.x - 1 - blockIdx.x;
    const int nh   = blockIdx.y;
    const int row0 = qt * 64 + warp * 16;

    const __half* kbp = g_kh + (size_t)nh * TT * DD;
    const __half* vtp = g_vt + (size_t)nh * DD * TT;

    const uint32_t sbase = (uint32_t)__cvta_generic_to_shared(smh);

    uint32_t qfb[4][4], qfs[4][4];
    {
        const float* qp = g_q + ((size_t)nh * TT + row0) * DD;
#pragma unroll
        for (int dk = 0; dk < 4; ++dk) {
            h2split(qp[gid * DD + dk * 16 + 2 * tig],
                    qp[gid * DD + dk * 16 + 2 * tig + 1],       qfb[dk][0], qfs[dk][0]);
            h2split(qp[(gid + 8) * DD + dk * 16 + 2 * tig],
                    qp[(gid + 8) * DD + dk * 16 + 2 * tig + 1], qfb[dk][1], qfs[dk][1]);
            h2split(qp[gid * DD + dk * 16 + 2 * tig + 8],
                    qp[gid * DD + dk * 16 + 2 * tig + 9],       qfb[dk][2], qfs[dk][2]);
            h2split(qp[(gid + 8) * DD + dk * 16 + 2 * tig + 8],
                    qp[(gid + 8) * DD + dk * 16 + 2 * tig + 9], qfb[dk][3], qfs[dk][3]);
        }
    }

    float o[8][4];
#pragma unroll
    for (int nt = 0; nt < 8; ++nt)
#pragma unroll
        for (int j = 0; j < 4; ++j) o[nt][j] = 0.f;
    float m0 = -INFINITY, m1 = -INFINITY, l0 = 0.f, l1 = 0.f;

    const int ntiles = 2 * qt + 2;

    auto prefetch = [&](int t) {
        const int buf = t & 1;
        const uint32_t kOff = OFF_KB + buf * KT * LDKH;
        const uint32_t vOff = OFF_VT + buf * DD * LDVH;
#pragma unroll
        for (int i = 0; i < 2; ++i) {
            int c = i * 128 + tid;
            int key = c >> 3, ko = (c & 7) * 8;
            cp_async16(sbase + (kOff + key * LDKH + ko) * 2,
                       kbp + (size_t)(t * KT + key) * DD + ko);
            int d = c >> 2, vo = (c & 3) * 8;
            cp_async16(sbase + (vOff + d * LDVH + vo) * 2,
                       vtp + (size_t)d * TT + t * KT + vo);
        }
        cp_commit();
    };

    prefetch(0);

    uint32_t* PwB = (uint32_t*)(smh + OFF_PB) + warp * 16 * LDPW;
    uint32_t* PwS = (uint32_t*)(smh + OFF_PS) + warp * 16 * LDPW;

#pragma unroll 1
    for (int kt_i = 0; kt_i < ntiles; ++kt_i) {
        cp_wait<0>();
        __syncthreads();
        if (kt_i + 1 < ntiles) prefetch(kt_i + 1);

        const int buf = kt_i & 1;
        const __half* Kb = smh + OFF_KB + buf * KT * LDKH;
        const __half* Vt = smh + OFF_VT + buf * DD * LDVH;

        float cs[4][4];
#pragma unroll
        for (int nt = 0; nt < 4; ++nt) {
#pragma unroll
            for (int j = 0; j < 4; ++j) cs[nt][j] = 0.f;
#pragma unroll
            for (int dk = 0; dk < 4; ++dk) {
                const __half* kr = Kb + (nt * 8 + gid) * LDKH + dk * 16 + 2 * tig;
                uint32_t b0 = *(const uint32_t*)kr;
                uint32_t b1 = *(const uint32_t*)(kr + 8);
                mma_f16(cs[nt], qfb[dk], b0, b1);
                mma_f16(cs[nt], qfs[dk], b0, b1);
            }
        }

        if (kt_i >= 2 * qt) {
            const int rl0 = row0 + gid;
            const int rl1 = rl0 + 8;
#pragma unroll
            for (int nt = 0; nt < 4; ++nt) {
                int j = kt_i * KT + nt * 8 + 2 * tig;
                if (j     > rl0) cs[nt][0] = -INFINITY;
                if (j + 1 > rl0) cs[nt][1] = -INFINITY;
                if (j     > rl1) cs[nt][2] = -INFINITY;
                if (j + 1 > rl1) cs[nt][3] = -INFINITY;
            }
        }

        float mx0 = -INFINITY, mx1 = -INFINITY;
#pragma unroll
        for (int nt = 0; nt < 4; ++nt) {
            mx0 = fmaxf(mx0, fmaxf(cs[nt][0], cs[nt][1]));
            mx1 = fmaxf(mx1, fmaxf(cs[nt][2], cs[nt][3]));
        }
        mx0 = fmaxf(mx0, __shfl_xor_sync(0xffffffffu, mx0, 1));
        mx0 = fmaxf(mx0, __shfl_xor_sync(0xffffffffu, mx0, 2));
        mx1 = fmaxf(mx1, __shfl_xor_sync(0xffffffffu, mx1, 1));
        mx1 = fmaxf(mx1, __shfl_xor_sync(0xffffffffu, mx1, 2));

        const float mn0 = fmaxf(m0, mx0);
        const float mn1 = fmaxf(m1, mx1);
        const float cor0 = ex2(m0 - mn0);
        const float cor1 = ex2(m1 - mn1);
        l0 *= cor0; l1 *= cor1;
#pragma unroll
        for (int nt = 0; nt < 8; ++nt) {
            o[nt][0] *= cor0; o[nt][1] *= cor0;
            o[nt][2] *= cor1; o[nt][3] *= cor1;
        }

        float rs0 = 0.f, rs1 = 0.f;
#pragma unroll
        for (int nt = 0; nt < 4; ++nt) {
            float p0 = ex2(cs[nt][0] - mn0);
            float p1 = ex2(cs[nt][1] - mn0);
            float p2 = ex2(cs[nt][2] - mn1);
            float p3 = ex2(cs[nt][3] - mn1);
            rs0 += p0 + p1; rs1 += p2 + p3;
            uint32_t b01, s01, b23, s23;
            h2split(p0, p1, b01, s01);
            h2split(p2, p3, b23, s23);
            const int w = nt * 4 + tig;
            PwB[gid * LDPW + w]       = b01;
            PwS[gid * LDPW + w]       = s01;
            PwB[(gid + 8) * LDPW + w] = b23;
            PwS[(gid + 8) * LDPW + w] = s23;
        }
        rs0 += __shfl_xor_sync(0xffffffffu, rs0, 1);
        rs0 += __shfl_xor_sync(0xffffffffu, rs0, 2);
        rs1 += __shfl_xor_sync(0xffffffffu, rs1, 1);
        rs1 += __shfl_xor_sync(0xffffffffu, rs1, 2);
        l0 += rs0; l1 += rs1;
        m0 = mn0; m1 = mn1;

        __syncwarp();

#pragma unroll
        for (int kk = 0; kk < 2; ++kk) {
            uint32_t ab[4], as_[4];
            ab[0]  = PwB[gid * LDPW + kk * 8 + tig];
            ab[1]  = PwB[(gid + 8) * LDPW + kk * 8 + tig];
            ab[2]  = PwB[gid * LDPW + kk * 8 + tig + 4];
            ab[3]  = PwB[(gid + 8) * LDPW + kk * 8 + tig + 4];
            as_[0] = PwS[gid * LDPW + kk * 8 + tig];
            as_[1] = PwS[(gid + 8) * LDPW + kk * 8 + tig];
            as_[2] = PwS[gid * LDPW + kk * 8 + tig + 4];
            as_[3] = PwS[(gid + 8) * LDPW + kk * 8 + tig + 4];
#pragma unroll
            for (int nt = 0; nt < 8; ++nt) {
                const __half* vr = Vt + (nt * 8 + gid) * LDVH + kk * 16 + 2 * tig;
                uint32_t b0 = *(const uint32_t*)vr;
                uint32_t b1 = *(const uint32_t*)(vr + 8);
                mma_f16(o[nt], ab,  b0, b1);
                mma_f16(o[nt], as_, b0, b1);
            }
        }
    }

    const float i0 = 1.f / l0;
    const float i1 = 1.f / l1;
    const int n = nh >> 3, hh = nh & 7;
    const int rg0 = row0 + gid;
#pragma unroll
    for (int nt = 0; nt < 8; ++nt) {
        int col = hh * DD + nt * 8 + 2 * tig;
        *(float2*)(g_att + (size_t)(n * TT + rg0) * DMOD + col) =
            make_float2(o[nt][0] * i0, o[nt][1] * i0);
        *(float2*)(g_att + (size_t)(n * TT + rg0 + 8) * DMOD + col) =
            make_float2(o[nt][2] * i1, o[nt][3] * i1);
    }
}

// ---------------- fused residual add + LayerNorm -------------------------------
template<bool WRITE_H16>
__global__ __launch_bounds__(256)
void add_ln_kernel(const float* __restrict__ a, const float* __restrict__ b,
                   const float* __restrict__ gamma, const float* __restrict__ beta,
                   float* __restrict__ out)
{
    int row = blockIdx.x;
    int tid = threadIdx.x;
    const float* ar = a + (size_t)row * DMOD;
    const float* br = b + (size_t)row * DMOD;

    float x0 = ar[tid]       + br[tid];
    float x1 = ar[tid + 256] + br[tid + 256];

    float sum = x0 + x1;
    float sq  = x0 * x0 + x1 * x1;
#pragma unroll
    for (int off = 16; off; off >>= 1) {
        sum += __shfl_xor_sync(0xffffffffu, sum, off);
        sq  += __shfl_xor_sync(0xffffffffu, sq,  off);
    }
    __shared__ float s1[8], s2[8];
    int wid = tid >> 5, lane = tid & 31;
    if (lane == 0) { s1[wid] = sum; s2[wid] = sq; }
    __syncthreads();
    float S = 0.f, Q = 0.f;
#pragma unroll
    for (int i = 0; i < 8; ++i) { S += s1[i]; Q += s2[i]; }

    float mean = S * (1.f / DMOD);
    float var  = Q * (1.f / DMOD) - mean * mean;
    float rstd = 1.f / sqrtf(var + 1e-3f);

    float y0 = gamma[tid]       * (x0 - mean) * rstd + beta[tid];
    float y1 = gamma[tid + 256] * (x1 - mean) * rstd + beta[tid + 256];
    out[(size_t)row * DMOD + tid]       = y0;
    out[(size_t)row * DMOD + tid + 256] = y1;
    if (WRITE_H16) {
        g_hh[(size_t)row * DMOD + tid]       = __float2half(y0);
        g_hh[(size_t)row * DMOD + tid + 256] = __float2half(y1);
    }
}

// ---------------- launch ------------------------------------------------------
extern "C" void kernel_launch(void* const* d_in, const int* in_sizes, int n_in,
                              void* d_out, int out_size)
{
    const int*   x     = (const int*)  d_in[0];
    const float* emb   = (const float*)d_in[1];
    const float* Wqkv  = (const float*)d_in[2];
    const float* bqkv  = (const float*)d_in[3];
    const float* Wff   = (const float*)d_in[4];
    const float* bff   = (const float*)d_in[5];
    const float* Wo    = (const float*)d_in[6];
    const float* bo    = (const float*)d_in[7];
    const float* g1    = (const float*)d_in[8];
    const float* beta1 = (const float*)d_in[9];
    const float* g2    = (const float*)d_in[10];
    const float* beta2 = (const float*)d_in[11];
    float* out = (float*)d_out;

    float *h, *qkv, *att, *ff2;
    __half *hh, *ff1, *wqkv, *wff, *wo;
    cudaGetSymbolAddress((void**)&h,    g_h);
    cudaGetSymbolAddress((void**)&hh,   g_hh);
    cudaGetSymbolAddress((void**)&qkv,  g_qkv);
    cudaGetSymbolAddress((void**)&att,  g_att);
    cudaGetSymbolAddress((void**)&ff1,  g_ff1);
    cudaGetSymbolAddress((void**)&ff2,  g_ff2);
    cudaGetSymbolAddress((void**)&wqkv, g_wqkv);
    cudaGetSymbolAddress((void**)&wff,  g_wff);
    cudaGetSymbolAddress((void**)&wo,   g_wo);

    cudaFuncSetAttribute(attn_mma_kernel,
                         cudaFuncAttributeMaxDynamicSharedMemorySize, ATTN_SMEM_BYTES);

    transpose_w_kernel<<<dim3(1536 / 32, DMOD / 32, NLAY), dim3(32, 8)>>>(
        Wqkv, wqkv, DMOD, 3 * DMOD);
    transpose_w_kernel<<<dim3(DFFV / 32, DMOD / 32, NLAY), dim3(32, 8)>>>(
        Wff, wff, DMOD, DFFV);
    transpose_w_kernel<<<dim3(DMOD / 32, DFFV / 32, NLAY), dim3(32, 8)>>>(
        Wo, wo, DFFV, DMOD);

    embed_kernel<<<ROWS, 128>>>(x, emb);

    for (int l = 0; l < NLAY; ++l) {
        gemm_f16<0><<<dim3(1536 / 128, ROWS / 128), 256>>>(
            hh, wqkv + (size_t)l * DMOD * 3 * DMOD, bqkv + (size_t)l * 3 * DMOD,
            qkv, ROWS, 3 * DMOD, DMOD);

        split_qkv_kernel<<<ROWS, 384>>>();
        vt_kernel<<<dim3(TT / 64, NH), dim3(32, 8)>>>();

        attn_mma_kernel<<<dim3(TT / 64, NH), 128, ATTN_SMEM_BYTES>>>();

        add_ln_kernel<true><<<ROWS, 256>>>(h, att,
            g1 + (size_t)l * DMOD, beta1 + (size_t)l * DMOD, h);

        gemm_f16<1><<<dim3(DFFV / 128, ROWS / 128), 256>>>(
            hh, wff + (size_t)l * DMOD * DFFV, bff + (size_t)l * DFFV,
            ff1, ROWS, DFFV, DMOD);

        gemm_f16<0><<<dim3(DMOD / 128, ROWS / 128), 256>>>(
            ff1, wo + (size_t)l * DFFV * DMOD, bo + (size_t)l * DMOD,
            ff2, ROWS, DMOD, DFFV);

        if (l == NLAY - 1)
            add_ln_kernel<false><<<ROWS, 256>>>(h, ff2,
                g2 + (size_t)l * DMOD, beta2 + (size_t)l * DMOD, out);
        else
            add_ln_kernel<true><<<ROWS, 256>>>(h, ff2,
                g2 + (size_t)l * DMOD, beta2 + (size_t)l * DMOD, h);
    }
}

// round 17
// speedup vs baseline: 2.9002x; 1.0880x over previous
#include <cuda_runtime.h>
#include <cuda_fp16.h>
#include <math.h>
#include <stdint.h>

#define NB   4
#define TT   1024
#define HH   8
#define DD   64
#define DMOD 512
#define DFFV 1024
#define NLAY 6
#define ROWS (NB * TT)   // 4096
#define NH   (NB * HH)   // 32

#define QSCALE (0.125f * 1.4426950408889634f)

// ---------------- scratch (static device globals; no allocation) -------------
__device__ float  g_h   [ROWS * DMOD];
__device__ __half g_hh  [ROWS * DMOD];
__device__ float  g_qkv [ROWS * 3 * DMOD];
__device__ float  g_att [ROWS * DMOD];
__device__ __half g_ff1 [ROWS * DFFV];
__device__ float  g_ff2 [ROWS * DMOD];
__device__ float  g_q   [NH * TT * DD];
__device__ __half g_kh  [NH * TT * DD];
__device__ __half g_vh  [NH * TT * DD];
__device__ __half g_vt  [NH * DD * TT];
__device__ __half g_wqkv[NLAY * DMOD * 3 * DMOD];
__device__ __half g_wff [NLAY * DMOD * DFFV];
__device__ __half g_wo  [NLAY * DFFV * DMOD];

// ---------------- common PTX helpers -------------------------------------------
__device__ __forceinline__ void mma_f16(float* c, const uint32_t* a, uint32_t b0, uint32_t b1)
{
    asm volatile(
        "mma.sync.aligned.m16n8k16.row.col.f32.f16.f16.f32 "
        "{%0,%1,%2,%3}, {%4,%5,%6,%7}, {%8,%9}, {%0,%1,%2,%3};"
        : "+f"(c[0]), "+f"(c[1]), "+f"(c[2]), "+f"(c[3])
        : "r"(a[0]), "r"(a[1]), "r"(a[2]), "r"(a[3]), "r"(b0), "r"(b1));
}
__device__ __forceinline__ void ldsm_x4(uint32_t& x, uint32_t& y, uint32_t& z, uint32_t& w,
                                        uint32_t addr)
{
    asm volatile("ldmatrix.sync.aligned.m8n8.x4.shared.b16 {%0,%1,%2,%3}, [%4];"
                 : "=r"(x), "=r"(y), "=r"(z), "=r"(w) : "r"(addr));
}
__device__ __forceinline__ void cp_async16(uint32_t saddr, const void* gaddr)
{
    asm volatile("cp.async.cg.shared.global [%0], [%1], 16;" :: "r"(saddr), "l"(gaddr));
}
__device__ __forceinline__ void cp_commit() { asm volatile("cp.async.commit_group;"); }
template<int N> __device__ __forceinline__ void cp_wait() {
    asm volatile("cp.async.wait_group %0;" :: "n"(N));
}
__device__ __forceinline__ float ex2(float x)
{
    float r;
    asm("ex2.approx.ftz.f32 %0, %1;" : "=f"(r) : "f"(x));
    return r;
}
__device__ __forceinline__ uint32_t packh2(__half lo, __half hi)
{
    return (uint32_t)__half_as_ushort(lo) | ((uint32_t)__half_as_ushort(hi) << 16);
}
__device__ __forceinline__ void h2split(float f0, float f1, uint32_t& big, uint32_t& small)
{
    __half b0 = __float2half_rn(f0), b1 = __float2half_rn(f1);
    __half s0 = __float2half_rn(f0 - __half2float(b0));
    __half s1 = __float2half_rn(f1 - __half2float(b1));
    big   = packh2(b0, b1);
    small = packh2(s0, s1);
}

// ---------------- weight transpose + fp16 convert prepass ----------------------
__global__ __launch_bounds__(256)
void transpose_w_kernel(const float* __restrict__ src, __half* __restrict__ dst,
                        int K, int N)
{
    __shared__ __half tile[32][33];
    const size_t lo = (size_t)blockIdx.z * K * N;
    const int k0 = blockIdx.y * 32, n0 = blockIdx.x * 32;
#pragma unroll
    for (int i = threadIdx.y; i < 32; i += 8)
        tile[i][threadIdx.x] = __float2half(src[lo + (size_t)(k0 + i) * N + n0 + threadIdx.x]);
    __syncthreads();
#pragma unroll
    for (int i = threadIdx.y; i < 32; i += 8)
        dst[lo + (size_t)(n0 + i) * K + k0 + threadIdx.x] = tile[threadIdx.x][i];
}

// ---------------- per-layer V transpose: [nh][t][d] -> [nh][d][t] ---------------
__global__ __launch_bounds__(256)
void vt_kernel()
{
    __shared__ __half tile[64][65];
    const int nh = blockIdx.y;
    const int t0 = blockIdx.x * 64;
    const __half* src = g_vh + (size_t)nh * TT * DD;
    __half*       dst = g_vt + (size_t)nh * DD * TT;
#pragma unroll
    for (int i = threadIdx.y; i < 64; i += 8) {
        tile[i][threadIdx.x]      = src[(size_t)(t0 + i) * DD + threadIdx.x];
        tile[i][threadIdx.x + 32] = src[(size_t)(t0 + i) * DD + threadIdx.x + 32];
    }
    __syncthreads();
#pragma unroll
    for (int i = threadIdx.y; i < 64; i += 8) {
        dst[(size_t)i * TT + t0 + threadIdx.x]      = tile[threadIdx.x][i];
        dst[(size_t)i * TT + t0 + threadIdx.x + 32] = tile[threadIdx.x + 32][i];
    }
}

// ---------------- embedding + positional encoding (all-fp32, MUFU) -------------
__global__ void embed_kernel(const int* __restrict__ x, const float* __restrict__ emb)
{
    int row = blockIdx.x;
    int t   = row & (TT - 1);
    int tok = x[row];
    const float* e = emb + (size_t)tok * DMOD;
    float tf = (float)t;
    for (int i = threadIdx.x; i < DMOD; i += blockDim.x) {
        float expo = -2.0f * (float)(i >> 1) * (1.0f / (float)DMOD);
        float rate = powf(10000.0f, expo);
        float ang  = tf * rate;
        float s, c;
        sincosf(ang, &s, &c);
        float p   = (i & 1) ? c : s;
        float val = e[i] * 22.62741699796952f + p;  // sqrt(512)
        g_h [(size_t)row * DMOD + i] = val;
        g_hh[(size_t)row * DMOD + i] = __float2half(val);
    }
}

// ---------------- FP16 GEMM — m16n8k16 + ldmatrix, 3-stage cp.async (R16) ------
#define LDAH 40
#define STG  3
#define BUFB (128 * LDAH * 2)

template<int MODE>
__global__ __launch_bounds__(256)
void gemm_f16(const __half* __restrict__ A, const __half* __restrict__ B,
              const float* __restrict__ bias, void* __restrict__ Cv,
              int M, int N, int K)
{
    __shared__ __half As[STG][128 * LDAH];
    __shared__ __half Bs[STG][128 * LDAH];

    const int tid  = threadIdx.x;
    const int bm   = blockIdx.y * 128;
    const int bn   = blockIdx.x * 128;

    const int r0 = tid >> 1;
    const int o0 = (tid & 1) * 16;

    const uint32_t sA = (uint32_t)__cvta_generic_to_shared(&As[0][0]);
    const uint32_t sB = (uint32_t)__cvta_generic_to_shared(&Bs[0][0]);

    const int warp = tid >> 5, lane = tid & 31;
    const int gid  = lane >> 2, tig = lane & 3;
    const int wm   = (warp & 3) * 32;
    const int wn   = (warp >> 2) * 64;

    uint32_t aoff[2];
#pragma unroll
    for (int mt = 0; mt < 2; ++mt)
        aoff[mt] = ((uint32_t)(wm + mt * 16 + (lane & 15)) * LDAH + (lane >> 4) * 8) * 2;
    uint32_t boff[4];
    {
        const int g8 = lane >> 3, l7 = lane & 7;
#pragma unroll
        for (int j = 0; j < 4; ++j)
            boff[j] = ((uint32_t)(wn + (2 * j + (g8 >> 1)) * 8 + l7) * LDAH + (g8 & 1) * 8) * 2;
    }

    float c[2][8][4];
#pragma unroll
    for (int mt = 0; mt < 2; ++mt)
#pragma unroll
        for (int nt = 0; nt < 8; ++nt)
#pragma unroll
            for (int j = 0; j < 4; ++j) c[mt][nt][j] = 0.f;

    const int nIter = K >> 5;

    auto issue = [&](int t) {
        const int buf = t % STG;
        const __half* Ap = A + (size_t)(bm + r0) * K + t * 32 + o0;
        const __half* Bp = B + (size_t)(bn + r0) * K + t * 32 + o0;
        uint32_t sa = sA + buf * BUFB + (r0 * LDAH + o0) * 2;
        uint32_t sb = sB + buf * BUFB + (r0 * LDAH + o0) * 2;
        cp_async16(sa,      Ap);
        cp_async16(sa + 16, Ap + 8);
        cp_async16(sb,      Bp);
        cp_async16(sb + 16, Bp + 8);
        cp_commit();
    };

    issue(0);
    if (nIter > 1) issue(1);

    for (int it = 0; it < nIter; ++it) {
        if (it + 1 < nIter) cp_wait<1>(); else cp_wait<0>();
        __syncthreads();
        if (it + 2 < nIter) issue(it + 2);

        const uint32_t bufA = sA + (uint32_t)(it % STG) * BUFB;
        const uint32_t bufB = sB + (uint32_t)(it % STG) * BUFB;
#pragma unroll
        for (int ks = 0; ks < 2; ++ks) {
            const uint32_t kb = ks * 32;
            uint32_t a[2][4], b[8][2];
            ldsm_x4(a[0][0], a[0][1], a[0][2], a[0][3], bufA + aoff[0] + kb);
            ldsm_x4(a[1][0], a[1][1], a[1][2], a[1][3], bufA + aoff[1] + kb);
#pragma unroll
            for (int j = 0; j < 4; ++j)
                ldsm_x4(b[2 * j][0], b[2 * j][1], b[2 * j + 1][0], b[2 * j + 1][1],
                        bufB + boff[j] + kb);
#pragma unroll
            for (int mt = 0; mt < 2; ++mt)
#pragma unroll
                for (int nt = 0; nt < 8; ++nt)
                    mma_f16(c[mt][nt], a[mt], b[nt][0], b[nt][1]);
        }
    }

#pragma unroll
    for (int mt = 0; mt < 2; ++mt) {
        const int row0 = bm + wm + mt * 16 + gid;
#pragma unroll
        for (int nt = 0; nt < 8; ++nt) {
            const int coln = bn + wn + nt * 8 + 2 * tig;
            const float2 bv = *(const float2*)(bias + coln);
            float2 v0, v1;
            v0.x = c[mt][nt][0] + bv.x; v0.y = c[mt][nt][1] + bv.y;
            v1.x = c[mt][nt][2] + bv.x; v1.y = c[mt][nt][3] + bv.y;
            if (MODE == 1) {
                __half* C = (__half*)Cv;
                __half2 h0 = __floats2half2_rn(fmaxf(v0.x, 0.f), fmaxf(v0.y, 0.f));
                __half2 h1 = __floats2half2_rn(fmaxf(v1.x, 0.f), fmaxf(v1.y, 0.f));
                *(__half2*)(C + (size_t)row0 * N + coln)       = h0;
                *(__half2*)(C + (size_t)(row0 + 8) * N + coln) = h1;
            } else {
                float* C = (float*)Cv;
                *(float2*)(C + (size_t)row0 * N + coln)       = v0;
                *(float2*)(C + (size_t)(row0 + 8) * N + coln) = v1;
            }
        }
    }
}

// ---------------- split qkv: q fp32 (scaled), K/V fp16 -------------------------
__global__ __launch_bounds__(384)
void split_qkv_kernel()
{
    int row = blockIdx.x;
    int n   = row >> 10;
    int t   = row & (TT - 1);
    int c0  = threadIdx.x * 4;
    float4 v = *(const float4*)(g_qkv + (size_t)row * 1536 + c0);
    float vals[4] = {v.x, v.y, v.z, v.w};
#pragma unroll
    for (int u = 0; u < 4; ++u) {
        int c = c0 + u;
        int h = c / 192;
        int r = c - h * 192;
        int d = r / 3;
        int j = r - d * 3;
        size_t dst = ((size_t)(n * HH + h) * TT + t) * DD + d;
        if (j == 0)      g_q [dst] = vals[u] * QSCALE;
        else if (j == 1) g_kh[dst] = __float2half(vals[u]);
        else             g_vh[dst] = __float2half(vals[u]);
    }
}

// ---------------- FlashAttention-2, fp16 mma, 64-key tiles ---------------------
// smem (halves): K 2x64x72, Vt 2x64x72, Pb/Ps 4 warps x 16 rows x 36 words
#define KT    64
#define LDKH  72
#define LDVH  72
#define LDPW  36
#define OFF_KB 0
#define OFF_VT (2 * KT * LDKH)                     // 9216
#define OFF_PB (OFF_VT + 2 * DD * LDVH)            // 18432
#define OFF_PS (OFF_PB + 4 * 16 * 2 * LDPW)        // 23040
#define ATTN_SMEM_HALVES (OFF_PS + 4 * 16 * 2 * LDPW)  // 27648
#define ATTN_SMEM_BYTES  (ATTN_SMEM_HALVES * 2)        // 55296

__global__ __launch_bounds__(128)
void attn_mma_kernel()
{
    extern __shared__ __half smh[];

    const int tid  = threadIdx.x;
    const int warp = tid >> 5, lane = tid & 31;
    const int gid  = lane >> 2, tig = lane & 3;
    const int qt   = gridDim.x - 1 - blockIdx.x;   // heavy q-tiles first
    const int nh   = blockIdx.y;
    const int row0 = qt * 64 + warp * 16;

    const __half* kbp = g_kh + (size_t)nh * TT * DD;
    const __half* vtp = g_vt + (size_t)nh * DD * TT;

    const uint32_t sbase = (uint32_t)__cvta_generic_to_shared(smh);

    uint32_t qfb[4][4], qfs[4][4];
    {
        const float* qp = g_q + ((size_t)nh * TT + row0) * DD;
#pragma unroll
        for (int dk = 0; dk < 4; ++dk) {
            h2split(qp[gid * DD + dk * 16 + 2 * tig],
                    qp[gid * DD + dk * 16 + 2 * tig + 1],       qfb[dk][0], qfs[dk][0]);
            h2split(qp[(gid + 8) * DD + dk * 16 + 2 * tig],
                    qp[(gid + 8) * DD + dk * 16 + 2 * tig + 1], qfb[dk][1], qfs[dk][1]);
            h2split(qp[gid * DD + dk * 16 + 2 * tig + 8],
                    qp[gid * DD + dk * 16 + 2 * tig + 9],       qfb[dk][2], qfs[dk][2]);
            h2split(qp[(gid + 8) * DD + dk * 16 + 2 * tig + 8],
                    qp[(gid + 8) * DD + dk * 16 + 2 * tig + 9], qfb[dk][3], qfs[dk][3]);
        }
    }

    float o[8][4];
#pragma unroll
    for (int nt = 0; nt < 8; ++nt)
#pragma unroll
        for (int j = 0; j < 4; ++j) o[nt][j] = 0.f;
    float m0 = -INFINITY, m1 = -INFINITY, l0 = 0.f, l1 = 0.f;

    const int ntiles = qt + 1;                     // 64-key tiles

    // K: 64 keys x 64 halves; Vt: 64 d x 64 keys -> 512 chunks each, 4/thread each
    auto prefetch = [&](int t) {
        const int buf = t & 1;
        const uint32_t kOff = OFF_KB + buf * KT * LDKH;
        const uint32_t vOff = OFF_VT + buf * DD * LDVH;
#pragma unroll
        for (int i = 0; i < 4; ++i) {
            int c = i * 128 + tid;                 // 0..511
            int key = c >> 3, ko = (c & 7) * 8;
            cp_async16(sbase + (kOff + key * LDKH + ko) * 2,
                       kbp + (size_t)(t * KT + key) * DD + ko);
            int d = c >> 3, vo = (c & 7) * 8;
            cp_async16(sbase + (vOff + d * LDVH + vo) * 2,
                       vtp + (size_t)d * TT + t * KT + vo);
        }
        cp_commit();
    };

    prefetch(0);

    uint32_t* PwB = (uint32_t*)(smh + OFF_PB) + warp * 16 * LDPW;
    uint32_t* PwS = (uint32_t*)(smh + OFF_PS) + warp * 16 * LDPW;

#pragma unroll 1
    for (int kt_i = 0; kt_i < ntiles; ++kt_i) {
        cp_wait<0>();
        __syncthreads();
        if (kt_i + 1 < ntiles) prefetch(kt_i + 1);

        const int buf = kt_i & 1;
        const __half* Kb = smh + OFF_KB + buf * KT * LDKH;
        const __half* Vt = smh + OFF_VT + buf * DD * LDVH;

        // ---- S = (q_big + q_small) @ K^T : 16x64 per warp ----
        float cs[8][4];
#pragma unroll
        for (int nt = 0; nt < 8; ++nt) {
#pragma unroll
            for (int j = 0; j < 4; ++j) cs[nt][j] = 0.f;
#pragma unroll
            for (int dk = 0; dk < 4; ++dk) {
                const __half* kr = Kb + (nt * 8 + gid) * LDKH + dk * 16 + 2 * tig;
                uint32_t b0 = *(const uint32_t*)kr;
                uint32_t b1 = *(const uint32_t*)(kr + 8);
                mma_f16(cs[nt], qfb[dk], b0, b1);
                mma_f16(cs[nt], qfs[dk], b0, b1);
            }
        }

        // ---- causal mask (only the diagonal tile) ----
        if (kt_i == qt) {
            const int rl0 = row0 + gid;
            const int rl1 = rl0 + 8;
#pragma unroll
            for (int nt = 0; nt < 8; ++nt) {
                int j = kt_i * KT + nt * 8 + 2 * tig;
                if (j     > rl0) cs[nt][0] = -INFINITY;
                if (j + 1 > rl0) cs[nt][1] = -INFINITY;
                if (j     > rl1) cs[nt][2] = -INFINITY;
                if (j + 1 > rl1) cs[nt][3] = -INFINITY;
            }
        }

        // ---- online softmax (exp2 domain, fp32) ----
        float mx0 = -INFINITY, mx1 = -INFINITY;
#pragma unroll
        for (int nt = 0; nt < 8; ++nt) {
            mx0 = fmaxf(mx0, fmaxf(cs[nt][0], cs[nt][1]));
            mx1 = fmaxf(mx1, fmaxf(cs[nt][2], cs[nt][3]));
        }
        mx0 = fmaxf(mx0, __shfl_xor_sync(0xffffffffu, mx0, 1));
        mx0 = fmaxf(mx0, __shfl_xor_sync(0xffffffffu, mx0, 2));
        mx1 = fmaxf(mx1, __shfl_xor_sync(0xffffffffu, mx1, 1));
        mx1 = fmaxf(mx1, __shfl_xor_sync(0xffffffffu, mx1, 2));

        const float mn0 = fmaxf(m0, mx0);
        const float mn1 = fmaxf(m1, mx1);
        const float cor0 = ex2(m0 - mn0);
        const float cor1 = ex2(m1 - mn1);
        l0 *= cor0; l1 *= cor1;
#pragma unroll
        for (int nt = 0; nt < 8; ++nt) {
            o[nt][0] *= cor0; o[nt][1] *= cor0;
            o[nt][2] *= cor1; o[nt][3] *= cor1;
        }

        float rs0 = 0.f, rs1 = 0.f;
#pragma unroll
        for (int nt = 0; nt < 8; ++nt) {
            float p0 = ex2(cs[nt][0] - mn0);
            float p1 = ex2(cs[nt][1] - mn0);
            float p2 = ex2(cs[nt][2] - mn1);
            float p3 = ex2(cs[nt][3] - mn1);
            rs0 += p0 + p1; rs1 += p2 + p3;
            uint32_t b01, s01, b23, s23;
            h2split(p0, p1, b01, s01);
            h2split(p2, p3, b23, s23);
            const int w = nt * 4 + tig;
            PwB[gid * LDPW + w]       = b01;
            PwS[gid * LDPW + w]       = s01;
            PwB[(gid + 8) * LDPW + w] = b23;
            PwS[(gid + 8) * LDPW + w] = s23;
        }
        rs0 += __shfl_xor_sync(0xffffffffu, rs0, 1);
        rs0 += __shfl_xor_sync(0xffffffffu, rs0, 2);
        rs1 += __shfl_xor_sync(0xffffffffu, rs1, 1);
        rs1 += __shfl_xor_sync(0xffffffffu, rs1, 2);
        l0 += rs0; l1 += rs1;
        m0 = mn0; m1 = mn1;

        __syncwarp();

        // ---- O += (P_big + P_small) @ V : 64 keys = 4 k16 chunks ----
#pragma unroll
        for (int kk = 0; kk < 4; ++kk) {
            uint32_t ab[4], as_[4];
            ab[0]  = PwB[gid * LDPW + kk * 8 + tig];
            ab[1]  = PwB[(gid + 8) * LDPW + kk * 8 + tig];
            ab[2]  = PwB[gid * LDPW + kk * 8 + tig + 4];
            ab[3]  = PwB[(gid + 8) * LDPW + kk * 8 + tig + 4];
            as_[0] = PwS[gid * LDPW + kk * 8 + tig];
            as_[1] = PwS[(gid + 8) * LDPW + kk * 8 + tig];
            as_[2] = PwS[gid * LDPW + kk * 8 + tig + 4];
            as_[3] = PwS[(gid + 8) * LDPW + kk * 8 + tig + 4];
#pragma unroll
            for (int nt = 0; nt < 8; ++nt) {
                const __half* vr = Vt + (nt * 8 + gid) * LDVH + kk * 16 + 2 * tig;
                uint32_t b0 = *(const uint32_t*)vr;
                uint32_t b1 = *(const uint32_t*)(vr + 8);
                mma_f16(o[nt], ab,  b0, b1);
                mma_f16(o[nt], as_, b0, b1);
            }
        }
    }

    const float i0 = 1.f / l0;
    const float i1 = 1.f / l1;
    const int n = nh >> 3, hh = nh & 7;
    const int rg0 = row0 + gid;
#pragma unroll
    for (int nt = 0; nt < 8; ++nt) {
        int col = hh * DD + nt * 8 + 2 * tig;
        *(float2*)(g_att + (size_t)(n * TT + rg0) * DMOD + col) =
            make_float2(o[nt][0] * i0, o[nt][1] * i0);
        *(float2*)(g_att + (size_t)(n * TT + rg0 + 8) * DMOD + col) =
            make_float2(o[nt][2] * i1, o[nt][3] * i1);
    }
}

// ---------------- fused residual add + LayerNorm -------------------------------
template<bool WRITE_H16>
__global__ __launch_bounds__(256)
void add_ln_kernel(const float* __restrict__ a, const float* __restrict__ b,
                   const float* __restrict__ gamma, const float* __restrict__ beta,
                   float* __restrict__ out)
{
    int row = blockIdx.x;
    int tid = threadIdx.x;
    const float* ar = a + (size_t)row * DMOD;
    const float* br = b + (size_t)row * DMOD;

    float x0 = ar[tid]       + br[tid];
    float x1 = ar[tid + 256] + br[tid + 256];

    float sum = x0 + x1;
    float sq  = x0 * x0 + x1 * x1;
#pragma unroll
    for (int off = 16; off; off >>= 1) {
        sum += __shfl_xor_sync(0xffffffffu, sum, off);
        sq  += __shfl_xor_sync(0xffffffffu, sq,  off);
    }
    __shared__ float s1[8], s2[8];
    int wid = tid >> 5, lane = tid & 31;
    if (lane == 0) { s1[wid] = sum; s2[wid] = sq; }
    __syncthreads();
    float S = 0.f, Q = 0.f;
#pragma unroll
    for (int i = 0; i < 8; ++i) { S += s1[i]; Q += s2[i]; }

    float mean = S * (1.f / DMOD);
    float var  = Q * (1.f / DMOD) - mean * mean;
    float rstd = 1.f / sqrtf(var + 1e-3f);

    float y0 = gamma[tid]       * (x0 - mean) * rstd + beta[tid];
    float y1 = gamma[tid + 256] * (x1 - mean) * rstd + beta[tid + 256];
    out[(size_t)row * DMOD + tid]       = y0;
    out[(size_t)row * DMOD + tid + 256] = y1;
    if (WRITE_H16) {
        g_hh[(size_t)row * DMOD + tid]       = __float2half(y0);
        g_hh[(size_t)row * DMOD + tid + 256] = __float2half(y1);
    }
}

// ---------------- launch ------------------------------------------------------
extern "C" void kernel_launch(void* const* d_in, const int* in_sizes, int n_in,
                              void* d_out, int out_size)
{
    const int*   x     = (const int*)  d_in[0];
    const float* emb   = (const float*)d_in[1];
    const float* Wqkv  = (const float*)d_in[2];
    const float* bqkv  = (const float*)d_in[3];
    const float* Wff   = (const float*)d_in[4];
    const float* bff   = (const float*)d_in[5];
    const float* Wo    = (const float*)d_in[6];
    const float* bo    = (const float*)d_in[7];
    const float* g1    = (const float*)d_in[8];
    const float* beta1 = (const float*)d_in[9];
    const float* g2    = (const float*)d_in[10];
    const float* beta2 = (const float*)d_in[11];
    float* out = (float*)d_out;

    float *h, *qkv, *att, *ff2;
    __half *hh, *ff1, *wqkv, *wff, *wo;
    cudaGetSymbolAddress((void**)&h,    g_h);
    cudaGetSymbolAddress((void**)&hh,   g_hh);
    cudaGetSymbolAddress((void**)&qkv,  g_qkv);
    cudaGetSymbolAddress((void**)&att,  g_att);
    cudaGetSymbolAddress((void**)&ff1,  g_ff1);
    cudaGetSymbolAddress((void**)&ff2,  g_ff2);
    cudaGetSymbolAddress((void**)&wqkv, g_wqkv);
    cudaGetSymbolAddress((void**)&wff,  g_wff);
    cudaGetSymbolAddress((void**)&wo,   g_wo);

    cudaFuncSetAttribute(attn_mma_kernel,
                         cudaFuncAttributeMaxDynamicSharedMemorySize, ATTN_SMEM_BYTES);

    transpose_w_kernel<<<dim3(1536 / 32, DMOD / 32, NLAY), dim3(32, 8)>>>(
        Wqkv, wqkv, DMOD, 3 * DMOD);
    transpose_w_kernel<<<dim3(DFFV / 32, DMOD / 32, NLAY), dim3(32, 8)>>>(
        Wff, wff, DMOD, DFFV);
    transpose_w_kernel<<<dim3(DMOD / 32, DFFV / 32, NLAY), dim3(32, 8)>>>(
        Wo, wo, DFFV, DMOD);

    embed_kernel<<<ROWS, 128>>>(x, emb);

    for (int l = 0; l < NLAY; ++l) {
        gemm_f16<0><<<dim3(1536 / 128, ROWS / 128), 256>>>(
            hh, wqkv + (size_t)l * DMOD * 3 * DMOD, bqkv + (size_t)l * 3 * DMOD,
            qkv, ROWS, 3 * DMOD, DMOD);

        split_qkv_kernel<<<ROWS, 384>>>();
        vt_kernel<<<dim3(TT / 64, NH), dim3(32, 8)>>>();

        attn_mma_kernel<<<dim3(TT / 64, NH), 128, ATTN_SMEM_BYTES>>>();

        add_ln_kernel<true><<<ROWS, 256>>>(h, att,
            g1 + (size_t)l * DMOD, beta1 + (size_t)l * DMOD, h);

        gemm_f16<1><<<dim3(DFFV / 128, ROWS / 128), 256>>>(
            hh, wff + (size_t)l * DMOD * DFFV, bff + (size_t)l * DFFV,
            ff1, ROWS, DFFV, DMOD);

        gemm_f16<0><<<dim3(DMOD / 128, ROWS / 128), 256>>>(
            ff1, wo + (size_t)l * DFFV * DMOD, bo + (size_t)l * DMOD,
            ff2, ROWS, DMOD, DFFV);

        if (l == NLAY - 1)
            add_ln_kernel<false><<<ROWS, 256>>>(h, ff2,
                g2 + (size_t)l * DMOD, beta2 + (size_t)l * DMOD, out);
        else
            add_ln_kernel<true><<<ROWS, 256>>>(h, ff2,
                g2 + (size_t)l * DMOD, beta2 + (size_t)l * DMOD, h);
    }
}